// round 1
// baseline (speedup 1.0000x reference)
#include <cuda_runtime.h>

#define DM 0.9394130628134758f   /* exp(-1/16) */
#define DS 0.7788007830714049f   /* exp(-1/4)  */
#define TH 0.3f

#define N_L0 (16*64*64*64)
#define N_L1 (16*128*64*64)
#define N_P1 (16*128*32*32)
#define N_L2 (16*128*32*32)
#define N_P2 (16*32768)
#define N_L3 (16*512)
#define N_L4 (16*11)
#define N_PART (16*16*512)

__device__ float g_vm0[N_L0], g_vs0[N_L0], g_s0[N_L0];
__device__ float g_vm1[N_L1], g_vs1[N_L1], g_s1[N_L1];
__device__ float g_p1[N_P1];
__device__ float g_vm2[N_L2], g_vs2[N_L2], g_s2[N_L2];
__device__ float g_p2[N_P2];
__device__ float g_vm3[N_L3], g_vs3[N_L3], g_s3[N_L3];
__device__ float g_vm4[N_L4], g_vs4[N_L4], g_s4[N_L4];
__device__ float g_part[N_PART];
__device__ float g_out[N_L4];

__device__ __forceinline__ float srm_g(float I, float* vm, float* vs, float* sp, int idx) {
    float so = sp[idx];
    float k = 1.0f - so;               // exactly 0 or 1
    float vmn = DM * vm[idx] * k + I;
    float vsn = DS * vs[idx] * k + I;
    float sn = ((vmn - vsn) > TH) ? 1.0f : 0.0f;
    vm[idx] = vmn; vs[idx] = vsn; sp[idx] = sn;
    return sn;
}

__global__ void zero_all() {
    int stride = gridDim.x * blockDim.x;
    int i0 = blockIdx.x * blockDim.x + threadIdx.x;
    for (int i = i0; i < N_L0; i += stride) { g_vm0[i] = 0.f; g_vs0[i] = 0.f; g_s0[i] = 0.f; }
    for (int i = i0; i < N_L1; i += stride) { g_vm1[i] = 0.f; g_vs1[i] = 0.f; g_s1[i] = 0.f; }
    for (int i = i0; i < N_L2; i += stride) { g_vm2[i] = 0.f; g_vs2[i] = 0.f; g_s2[i] = 0.f; }
    for (int i = i0; i < N_L3; i += stride) { g_vm3[i] = 0.f; g_vs3[i] = 0.f; g_s3[i] = 0.f; }
    for (int i = i0; i < N_L4; i += stride) { g_vm4[i] = 0.f; g_vs4[i] = 0.f; g_s4[i] = 0.f; g_out[i] = 0.f; }
}

// conv0: 2->64 channels on 64x64, fused input clip + SRM. One thread per output.
__global__ void conv0_srm(const float* __restrict__ x, const float* __restrict__ W0, int t) {
    __shared__ float ws[1152];
    for (int i = threadIdx.x; i < 1152; i += 256) ws[i] = W0[i];
    __syncthreads();
    int gid = blockIdx.x * 256 + threadIdx.x;
    int w = gid & 63, h = (gid >> 6) & 63, co = (gid >> 12) & 63, b = gid >> 18;
    const float* xb = x + ((size_t)(b * 16 + t)) * 2 * 4096;
    float acc = 0.f;
#pragma unroll
    for (int ci = 0; ci < 2; ci++) {
        const float* xp = xb + ci * 4096;
        const float* wp = ws + (co * 2 + ci) * 9;
#pragma unroll
        for (int dh = 0; dh < 3; dh++) {
            int y = h + dh - 1;
            if ((unsigned)y < 64u) {
#pragma unroll
                for (int dw = 0; dw < 3; dw++) {
                    int xx = w + dw - 1;
                    if ((unsigned)xx < 64u) {
                        float v = __ldg(xp + y * 64 + xx);
                        v = fminf(fmaxf(v, 0.f), 1.f);
                        acc += v * wp[dh * 3 + dw];
                    }
                }
            }
        }
    }
    srm_g(acc, g_vm0, g_vs0, g_s0, gid);
}

// Tiled 3x3 conv (pad 1) + SRM + fused 2x2 maxpool.
// CTA: 16x16 spatial tile x 32 output channels, one batch image.
// 256 threads = 64 spatial (2x2 px each) x 4 co-groups (8 co each) -> 32 regs of acc.
// ci staged in chunks of 32. FFMA:LDS = 288:88 per ci -> FFMA-bound.
template<int CIN, int COUT, int HW>
__global__ void __launch_bounds__(256, 2)
conv_srm_pool(const float* __restrict__ in, const float* __restrict__ Wt,
              float* __restrict__ vm, float* __restrict__ vs, float* __restrict__ sp,
              float* __restrict__ pout)
{
    extern __shared__ float smem[];
    float* ins = smem;              // [32][18][19] padded rows
    float* ws  = smem + 32 * 342;   // [32 co][32 ci][9]
    const int NT = HW / 16;
    int tid = threadIdx.x;
    int b = blockIdx.z;
    int cog = blockIdx.y * 32;
    int tX = blockIdx.x % NT, tY = blockIdx.x / NT;
    int x0 = tX * 16, y0 = tY * 16;
    int co_t = tid >> 6;            // 0..3 (constant within a warp -> weight LDS broadcast)
    int spt = tid & 63;
    int ty = spt >> 3, tx = spt & 7;

    float acc[8][2][2];
#pragma unroll
    for (int j = 0; j < 8; j++)
#pragma unroll
        for (int a = 0; a < 2; a++)
#pragma unroll
            for (int c = 0; c < 2; c++) acc[j][a][c] = 0.f;

    for (int cc = 0; cc < CIN; cc += 32) {
        __syncthreads();
#pragma unroll 1
        for (int i = tid; i < 32 * 324; i += 256) {
            int ci = i / 324; int r = i - ci * 324;
            int y = r / 18;   int xq = r - y * 18;
            int gy = y0 + y - 1, gx = x0 + xq - 1;
            float v = 0.f;
            if ((unsigned)gy < (unsigned)HW && (unsigned)gx < (unsigned)HW)
                v = in[((size_t)(b * CIN + cc + ci) * HW + gy) * HW + gx];
            ins[ci * 342 + y * 19 + xq] = v;
        }
#pragma unroll 1
        for (int i = tid; i < 32 * 288; i += 256) {
            int co = i / 288; int r = i - co * 288;   // r = ci*9 + k
            ws[i] = Wt[((size_t)(cog + co) * CIN + cc) * 9 + r];
        }
        __syncthreads();

#pragma unroll 1
        for (int ci = 0; ci < 32; ci++) {
            float iv[4][4];
            const float* ip = ins + ci * 342 + (2 * ty) * 19 + 2 * tx;
#pragma unroll
            for (int yy = 0; yy < 4; yy++)
#pragma unroll
                for (int xx = 0; xx < 4; xx++)
                    iv[yy][xx] = ip[yy * 19 + xx];
            const float* wb = ws + (co_t * 8) * 288 + ci * 9;
#pragma unroll
            for (int j = 0; j < 8; j++) {
                const float* wp = wb + j * 288;
                float w00 = wp[0], w01 = wp[1], w02 = wp[2];
                float w10 = wp[3], w11 = wp[4], w12 = wp[5];
                float w20 = wp[6], w21 = wp[7], w22 = wp[8];
#pragma unroll
                for (int ry = 0; ry < 2; ry++)
#pragma unroll
                    for (int rx = 0; rx < 2; rx++) {
                        float s = acc[j][ry][rx];
                        s += iv[ry + 0][rx + 0] * w00; s += iv[ry + 0][rx + 1] * w01; s += iv[ry + 0][rx + 2] * w02;
                        s += iv[ry + 1][rx + 0] * w10; s += iv[ry + 1][rx + 1] * w11; s += iv[ry + 1][rx + 2] * w12;
                        s += iv[ry + 2][rx + 0] * w20; s += iv[ry + 2][rx + 1] * w21; s += iv[ry + 2][rx + 2] * w22;
                        acc[j][ry][rx] = s;
                    }
            }
        }
    }

    // Epilogue: SRM per output element + fused 2x2 maxpool (spikes are >=0 -> max init 0).
    const int HWo = HW / 2;
#pragma unroll
    for (int j = 0; j < 8; j++) {
        int co = cog + co_t * 8 + j;
        float mx = 0.f;
#pragma unroll
        for (int ry = 0; ry < 2; ry++)
#pragma unroll
            for (int rx = 0; rx < 2; rx++) {
                int oy = y0 + 2 * ty + ry, ox = x0 + 2 * tx + rx;
                int idx = ((b * COUT + co) * HW + oy) * HW + ox;
                float sn = srm_g(acc[j][ry][rx], vm, vs, sp, idx);
                mx = fmaxf(mx, sn);
            }
        pout[((size_t)(b * COUT + co) * HWo + (y0 / 2 + ty)) * HWo + (x0 / 2 + tx)] = mx;
    }
}

// fc3 split-K partial GEMM: C[16,512] = p2[16,32768] @ W3[512,32768]^T.
// grid = (16 k-splits, 64 j-groups); p2 chunk (16 x 2048) staged in smem; warp per j.
__global__ void __launch_bounds__(256) fc3_partial(const float* __restrict__ W3) {
    extern __shared__ float p2s[];   // [16][2048]
    int ks = blockIdx.x, jg = blockIdx.y;
    int k0 = ks * 2048;
    int tid = threadIdx.x;
    for (int i = tid; i < 16 * 2048; i += 256) {
        int b = i >> 11, k = i & 2047;
        p2s[i] = g_p2[b * 32768 + k0 + k];
    }
    __syncthreads();
    int wj = tid >> 5, lane = tid & 31;
    int j = jg * 8 + wj;
    const float4* wr = reinterpret_cast<const float4*>(W3 + (size_t)j * 32768 + k0);
    const float4* ps = reinterpret_cast<const float4*>(p2s);
    float acc[16];
#pragma unroll
    for (int b = 0; b < 16; b++) acc[b] = 0.f;
#pragma unroll 1
    for (int kk = lane; kk < 512; kk += 32) {
        float4 w4 = __ldg(wr + kk);
#pragma unroll
        for (int b = 0; b < 16; b++) {
            float4 p = ps[b * 512 + kk];
            acc[b] += w4.x * p.x; acc[b] += w4.y * p.y;
            acc[b] += w4.z * p.z; acc[b] += w4.w * p.w;
        }
    }
#pragma unroll
    for (int b = 0; b < 16; b++) {
        float v = acc[b];
        v += __shfl_down_sync(0xffffffffu, v, 16);
        v += __shfl_down_sync(0xffffffffu, v, 8);
        v += __shfl_down_sync(0xffffffffu, v, 4);
        v += __shfl_down_sync(0xffffffffu, v, 2);
        v += __shfl_down_sync(0xffffffffu, v, 1);
        if (lane == 0) g_part[(ks * 16 + b) * 512 + j] = v;
    }
}

__global__ void fc3_srm() {
    int i = blockIdx.x * 256 + threadIdx.x;   // 8192 = [b][j]
    float I = 0.f;
#pragma unroll
    for (int ks = 0; ks < 16; ks++) I += g_part[ks * 8192 + i];
    srm_g(I, g_vm3, g_vs3, g_s3, i);
}

// fc4 (512->11) + SRM + output accumulation. Single block.
__global__ void fc4_srm(const float* __restrict__ W4) {
    __shared__ float s3s[8192];
    int tid = threadIdx.x;
    for (int i = tid; i < 8192; i += 256) s3s[i] = g_s3[i];
    __syncthreads();
    if (tid < 176) {
        int b = tid / 11, j = tid % 11;
        const float4* wr = reinterpret_cast<const float4*>(W4 + j * 512);
        const float4* sr = reinterpret_cast<const float4*>(s3s + b * 512);
        float acc = 0.f;
#pragma unroll 4
        for (int k = 0; k < 128; k++) {
            float4 w = __ldg(wr + k), s = sr[k];
            acc += w.x * s.x; acc += w.y * s.y; acc += w.z * s.z; acc += w.w * s.w;
        }
        float sn = srm_g(acc, g_vm4, g_vs4, g_s4, tid);
        g_out[tid] += sn;
    }
}

__global__ void finalize_k(float* __restrict__ out) {
    int i = threadIdx.x;
    if (i < 176) out[i] = g_out[i] * 0.0625f;   // / num_steps (exact)
}

extern "C" void kernel_launch(void* const* d_in, const int* in_sizes, int n_in,
                              void* d_out, int out_size) {
    (void)in_sizes; (void)n_in; (void)out_size;
    const float* x  = (const float*)d_in[0];
    const float* W0 = (const float*)d_in[1];
    const float* W1 = (const float*)d_in[2];
    const float* W2 = (const float*)d_in[3];
    const float* W3 = (const float*)d_in[4];
    const float* W4 = (const float*)d_in[5];
    float* out = (float*)d_out;

    const int SMEM_CONV = (32 * 342 + 32 * 288) * 4;   // 80640 B
    cudaFuncSetAttribute(conv_srm_pool<64, 128, 64>,
                         cudaFuncAttributeMaxDynamicSharedMemorySize, SMEM_CONV);
    cudaFuncSetAttribute(conv_srm_pool<128, 128, 32>,
                         cudaFuncAttributeMaxDynamicSharedMemorySize, SMEM_CONV);
    cudaFuncSetAttribute(fc3_partial,
                         cudaFuncAttributeMaxDynamicSharedMemorySize, 131072);

    float *s0, *vm1, *vs1, *s1, *p1, *vm2, *vs2, *s2, *p2;
    cudaGetSymbolAddress((void**)&s0,  g_s0);
    cudaGetSymbolAddress((void**)&vm1, g_vm1);
    cudaGetSymbolAddress((void**)&vs1, g_vs1);
    cudaGetSymbolAddress((void**)&s1,  g_s1);
    cudaGetSymbolAddress((void**)&p1,  g_p1);
    cudaGetSymbolAddress((void**)&vm2, g_vm2);
    cudaGetSymbolAddress((void**)&vs2, g_vs2);
    cudaGetSymbolAddress((void**)&s2,  g_s2);
    cudaGetSymbolAddress((void**)&p2,  g_p2);

    zero_all<<<2048, 256>>>();
    for (int t = 0; t < 16; t++) {
        conv0_srm<<<N_L0 / 256, 256>>>(x, W0, t);
        conv_srm_pool<64, 128, 64><<<dim3(16, 4, 16), 256, SMEM_CONV>>>(s0, W1, vm1, vs1, s1, p1);
        conv_srm_pool<128, 128, 32><<<dim3(4, 4, 16), 256, SMEM_CONV>>>(p1, W2, vm2, vs2, s2, p2);
        fc3_partial<<<dim3(16, 64), 256, 131072>>>(W3);
        fc3_srm<<<32, 256>>>();
        fc4_srm<<<1, 256>>>(W4);
    }
    finalize_k<<<1, 256>>>(out);
}

// round 2
// speedup vs baseline: 1.0073x; 1.0073x over previous
#include <cuda_runtime.h>

#define DM 0.9394130628134758f   /* exp(-1/16) */
#define DS 0.7788007830714049f   /* exp(-1/4)  */
#define TH 0.3f

#define N_L0 (16*64*64*64)
#define N_L1 (16*128*64*64)
#define N_P1 (16*128*32*32)
#define N_L2 (16*128*32*32)
#define N_P2 (16*32768)
#define N_L3 (16*512)
#define N_L4 (16*11)
#define N_PART (16*16*512)

__device__ float g_vm0[N_L0], g_vs0[N_L0], g_s0[N_L0];
__device__ float g_vm1[N_L1], g_vs1[N_L1], g_s1[N_L1];
__device__ float g_p1[N_P1];
__device__ float g_vm2[N_L2], g_vs2[N_L2], g_s2[N_L2];
__device__ float g_p2[N_P2];
__device__ float g_vm3[N_L3], g_vs3[N_L3], g_s3[N_L3];
__device__ float g_vm4[N_L4], g_vs4[N_L4], g_s4[N_L4];
__device__ float g_part[N_PART];
__device__ float g_out[N_L4];

__device__ __forceinline__ float srm_g(float I, float* vm, float* vs, float* sp, int idx) {
    float so = sp[idx];
    float k = 1.0f - so;               // exactly 0 or 1
    float vmn = DM * vm[idx] * k + I;
    float vsn = DS * vs[idx] * k + I;
    float sn = ((vmn - vsn) > TH) ? 1.0f : 0.0f;
    vm[idx] = vmn; vs[idx] = vsn; sp[idx] = sn;
    return sn;
}

__global__ void zero_all() {
    int stride = gridDim.x * blockDim.x;
    int i0 = blockIdx.x * blockDim.x + threadIdx.x;
    for (int i = i0; i < N_L0; i += stride) { g_vm0[i] = 0.f; g_vs0[i] = 0.f; g_s0[i] = 0.f; }
    for (int i = i0; i < N_L1; i += stride) { g_vm1[i] = 0.f; g_vs1[i] = 0.f; g_s1[i] = 0.f; }
    for (int i = i0; i < N_L2; i += stride) { g_vm2[i] = 0.f; g_vs2[i] = 0.f; g_s2[i] = 0.f; }
    for (int i = i0; i < N_L3; i += stride) { g_vm3[i] = 0.f; g_vs3[i] = 0.f; g_s3[i] = 0.f; }
    for (int i = i0; i < N_L4; i += stride) { g_vm4[i] = 0.f; g_vs4[i] = 0.f; g_s4[i] = 0.f; g_out[i] = 0.f; }
}

// conv0: 2->64 channels on 64x64, fused input clip + SRM. One thread per output.
__global__ void conv0_srm(const float* __restrict__ x, const float* __restrict__ W0, int t) {
    __shared__ float ws[1152];
    for (int i = threadIdx.x; i < 1152; i += 256) ws[i] = W0[i];
    __syncthreads();
    int gid = blockIdx.x * 256 + threadIdx.x;
    int w = gid & 63, h = (gid >> 6) & 63, co = (gid >> 12) & 63, b = gid >> 18;
    const float* xb = x + ((size_t)(b * 16 + t)) * 2 * 4096;
    float acc = 0.f;
#pragma unroll
    for (int ci = 0; ci < 2; ci++) {
        const float* xp = xb + ci * 4096;
        const float* wp = ws + (co * 2 + ci) * 9;
#pragma unroll
        for (int dh = 0; dh < 3; dh++) {
            int y = h + dh - 1;
            if ((unsigned)y < 64u) {
#pragma unroll
                for (int dw = 0; dw < 3; dw++) {
                    int xx = w + dw - 1;
                    if ((unsigned)xx < 64u) {
                        float v = __ldg(xp + y * 64 + xx);
                        v = fminf(fmaxf(v, 0.f), 1.f);
                        acc += v * wp[dh * 3 + dw];
                    }
                }
            }
        }
    }
    srm_g(acc, g_vm0, g_vs0, g_s0, gid);
}

// Tiled 3x3 conv (pad 1) + SRM + fused 2x2 maxpool.
// CTA: 16x16 spatial tile x 32 output channels, one batch image.
// 256 threads = 64 spatial (2x2 px each) x 4 co-groups (8 co each) -> 32 regs of acc.
// ci staged in chunks of 32. FFMA:LDS = 288:88 per ci -> FFMA-bound.
template<int CIN, int COUT, int HW>
__global__ void __launch_bounds__(256, 2)
conv_srm_pool(const float* __restrict__ in, const float* __restrict__ Wt,
              float* __restrict__ vm, float* __restrict__ vs, float* __restrict__ sp,
              float* __restrict__ pout)
{
    extern __shared__ float smem[];
    float* ins = smem;              // [32][18][19] padded rows
    float* ws  = smem + 32 * 342;   // [32 co][32 ci][9]
    const int NT = HW / 16;
    int tid = threadIdx.x;
    int b = blockIdx.z;
    int cog = blockIdx.y * 32;
    int tX = blockIdx.x % NT, tY = blockIdx.x / NT;
    int x0 = tX * 16, y0 = tY * 16;
    int co_t = tid >> 6;            // 0..3 (constant within a warp -> weight LDS broadcast)
    int spt = tid & 63;
    int ty = spt >> 3, tx = spt & 7;

    float acc[8][2][2];
#pragma unroll
    for (int j = 0; j < 8; j++)
#pragma unroll
        for (int a = 0; a < 2; a++)
#pragma unroll
            for (int c = 0; c < 2; c++) acc[j][a][c] = 0.f;

    for (int cc = 0; cc < CIN; cc += 32) {
        __syncthreads();
#pragma unroll 1
        for (int i = tid; i < 32 * 324; i += 256) {
            int ci = i / 324; int r = i - ci * 324;
            int y = r / 18;   int xq = r - y * 18;
            int gy = y0 + y - 1, gx = x0 + xq - 1;
            float v = 0.f;
            if ((unsigned)gy < (unsigned)HW && (unsigned)gx < (unsigned)HW)
                v = in[((size_t)(b * CIN + cc + ci) * HW + gy) * HW + gx];
            ins[ci * 342 + y * 19 + xq] = v;
        }
#pragma unroll 1
        for (int i = tid; i < 32 * 288; i += 256) {
            int co = i / 288; int r = i - co * 288;   // r = ci*9 + k
            ws[i] = Wt[((size_t)(cog + co) * CIN + cc) * 9 + r];
        }
        __syncthreads();

#pragma unroll 1
        for (int ci = 0; ci < 32; ci++) {
            float iv[4][4];
            const float* ip = ins + ci * 342 + (2 * ty) * 19 + 2 * tx;
#pragma unroll
            for (int yy = 0; yy < 4; yy++)
#pragma unroll
                for (int xx = 0; xx < 4; xx++)
                    iv[yy][xx] = ip[yy * 19 + xx];
            const float* wb = ws + (co_t * 8) * 288 + ci * 9;
#pragma unroll
            for (int j = 0; j < 8; j++) {
                const float* wp = wb + j * 288;
                float w00 = wp[0], w01 = wp[1], w02 = wp[2];
                float w10 = wp[3], w11 = wp[4], w12 = wp[5];
                float w20 = wp[6], w21 = wp[7], w22 = wp[8];
#pragma unroll
                for (int ry = 0; ry < 2; ry++)
#pragma unroll
                    for (int rx = 0; rx < 2; rx++) {
                        float s = acc[j][ry][rx];
                        s += iv[ry + 0][rx + 0] * w00; s += iv[ry + 0][rx + 1] * w01; s += iv[ry + 0][rx + 2] * w02;
                        s += iv[ry + 1][rx + 0] * w10; s += iv[ry + 1][rx + 1] * w11; s += iv[ry + 1][rx + 2] * w12;
                        s += iv[ry + 2][rx + 0] * w20; s += iv[ry + 2][rx + 1] * w21; s += iv[ry + 2][rx + 2] * w22;
                        acc[j][ry][rx] = s;
                    }
            }
        }
    }

    // Epilogue: SRM per output element + fused 2x2 maxpool (spikes are >=0 -> max init 0).
    const int HWo = HW / 2;
#pragma unroll
    for (int j = 0; j < 8; j++) {
        int co = cog + co_t * 8 + j;
        float mx = 0.f;
#pragma unroll
        for (int ry = 0; ry < 2; ry++)
#pragma unroll
            for (int rx = 0; rx < 2; rx++) {
                int oy = y0 + 2 * ty + ry, ox = x0 + 2 * tx + rx;
                int idx = ((b * COUT + co) * HW + oy) * HW + ox;
                float sn = srm_g(acc[j][ry][rx], vm, vs, sp, idx);
                mx = fmaxf(mx, sn);
            }
        pout[((size_t)(b * COUT + co) * HWo + (y0 / 2 + ty)) * HWo + (x0 / 2 + tx)] = mx;
    }
}

// fc3 split-K partial GEMM: C[16,512] = p2[16,32768] @ W3[512,32768]^T.
// grid = (16 k-splits, 64 j-groups); p2 chunk (16 x 2048) staged in smem; warp per j.
__global__ void __launch_bounds__(256) fc3_partial(const float* __restrict__ W3) {
    extern __shared__ float p2s[];   // [16][2048]
    int ks = blockIdx.x, jg = blockIdx.y;
    int k0 = ks * 2048;
    int tid = threadIdx.x;
    for (int i = tid; i < 16 * 2048; i += 256) {
        int b = i >> 11, k = i & 2047;
        p2s[i] = g_p2[b * 32768 + k0 + k];
    }
    __syncthreads();
    int wj = tid >> 5, lane = tid & 31;
    int j = jg * 8 + wj;
    const float4* wr = reinterpret_cast<const float4*>(W3 + (size_t)j * 32768 + k0);
    const float4* ps = reinterpret_cast<const float4*>(p2s);
    float acc[16];
#pragma unroll
    for (int b = 0; b < 16; b++) acc[b] = 0.f;
#pragma unroll 1
    for (int kk = lane; kk < 512; kk += 32) {
        float4 w4 = __ldg(wr + kk);
#pragma unroll
        for (int b = 0; b < 16; b++) {
            float4 p = ps[b * 512 + kk];
            acc[b] += w4.x * p.x; acc[b] += w4.y * p.y;
            acc[b] += w4.z * p.z; acc[b] += w4.w * p.w;
        }
    }
#pragma unroll
    for (int b = 0; b < 16; b++) {
        float v = acc[b];
        v += __shfl_down_sync(0xffffffffu, v, 16);
        v += __shfl_down_sync(0xffffffffu, v, 8);
        v += __shfl_down_sync(0xffffffffu, v, 4);
        v += __shfl_down_sync(0xffffffffu, v, 2);
        v += __shfl_down_sync(0xffffffffu, v, 1);
        if (lane == 0) g_part[(ks * 16 + b) * 512 + j] = v;
    }
}

__global__ void fc3_srm() {
    int i = blockIdx.x * 256 + threadIdx.x;   // 8192 = [b][j]
    float I = 0.f;
#pragma unroll
    for (int ks = 0; ks < 16; ks++) I += g_part[ks * 8192 + i];
    srm_g(I, g_vm3, g_vs3, g_s3, i);
}

// fc4 (512->11) + SRM + output accumulation. Single block.
__global__ void fc4_srm(const float* __restrict__ W4) {
    __shared__ float s3s[8192];
    int tid = threadIdx.x;
    for (int i = tid; i < 8192; i += 256) s3s[i] = g_s3[i];
    __syncthreads();
    if (tid < 176) {
        int b = tid / 11, j = tid % 11;
        const float4* wr = reinterpret_cast<const float4*>(W4 + j * 512);
        const float4* sr = reinterpret_cast<const float4*>(s3s + b * 512);
        float acc = 0.f;
#pragma unroll 4
        for (int k = 0; k < 128; k++) {
            float4 w = __ldg(wr + k), s = sr[k];
            acc += w.x * s.x; acc += w.y * s.y; acc += w.z * s.z; acc += w.w * s.w;
        }
        float sn = srm_g(acc, g_vm4, g_vs4, g_s4, tid);
        g_out[tid] += sn;
    }
}

__global__ void finalize_k(float* __restrict__ out) {
    int i = threadIdx.x;
    if (i < 176) out[i] = g_out[i] * 0.0625f;   // / num_steps (exact)
}

extern "C" void kernel_launch(void* const* d_in, const int* in_sizes, int n_in,
                              void* d_out, int out_size) {
    (void)in_sizes; (void)n_in; (void)out_size;
    const float* x  = (const float*)d_in[0];
    const float* W0 = (const float*)d_in[1];
    const float* W1 = (const float*)d_in[2];
    const float* W2 = (const float*)d_in[3];
    const float* W3 = (const float*)d_in[4];
    const float* W4 = (const float*)d_in[5];
    float* out = (float*)d_out;

    const int SMEM_CONV = (32 * 342 + 32 * 288) * 4;   // 80640 B
    cudaFuncSetAttribute(conv_srm_pool<64, 128, 64>,
                         cudaFuncAttributeMaxDynamicSharedMemorySize, SMEM_CONV);
    cudaFuncSetAttribute(conv_srm_pool<128, 128, 32>,
                         cudaFuncAttributeMaxDynamicSharedMemorySize, SMEM_CONV);
    cudaFuncSetAttribute(fc3_partial,
                         cudaFuncAttributeMaxDynamicSharedMemorySize, 131072);

    float *s0, *vm1, *vs1, *s1, *p1, *vm2, *vs2, *s2, *p2;
    cudaGetSymbolAddress((void**)&s0,  g_s0);
    cudaGetSymbolAddress((void**)&vm1, g_vm1);
    cudaGetSymbolAddress((void**)&vs1, g_vs1);
    cudaGetSymbolAddress((void**)&s1,  g_s1);
    cudaGetSymbolAddress((void**)&p1,  g_p1);
    cudaGetSymbolAddress((void**)&vm2, g_vm2);
    cudaGetSymbolAddress((void**)&vs2, g_vs2);
    cudaGetSymbolAddress((void**)&s2,  g_s2);
    cudaGetSymbolAddress((void**)&p2,  g_p2);

    zero_all<<<2048, 256>>>();
    for (int t = 0; t < 16; t++) {
        conv0_srm<<<N_L0 / 256, 256>>>(x, W0, t);
        conv_srm_pool<64, 128, 64><<<dim3(16, 4, 16), 256, SMEM_CONV>>>(s0, W1, vm1, vs1, s1, p1);
        conv_srm_pool<128, 128, 32><<<dim3(4, 4, 16), 256, SMEM_CONV>>>(p1, W2, vm2, vs2, s2, p2);
        fc3_partial<<<dim3(16, 64), 256, 131072>>>(W3);
        fc3_srm<<<32, 256>>>();
        fc4_srm<<<1, 256>>>(W4);
    }
    finalize_k<<<1, 256>>>(out);
}

// round 3
// speedup vs baseline: 1.0801x; 1.0723x over previous
#include <cuda_runtime.h>

#define DM 0.9394130628134758f   /* exp(-1/16) */
#define DS 0.7788007830714049f   /* exp(-1/4)  */
#define TH 0.3f

#define N_L0 (16*64*64*64)
#define N_L1 (16*128*64*64)
#define N_P1 (16*128*32*32)
#define N_L2 (16*128*32*32)
#define N_P2 (16*32768)
#define N_L3 (16*512)
#define N_L4 (16*11)
#define N_PART (16*16*512)

__device__ float g_vm0[N_L0], g_vs0[N_L0], g_s0[N_L0];
__device__ float g_vm1[N_L1], g_vs1[N_L1], g_s1[N_L1];
__device__ float g_p1[N_P1];
__device__ float g_vm2[N_L2], g_vs2[N_L2], g_s2[N_L2];
__device__ float g_p2[N_P2];
__device__ float g_vm3[N_L3], g_vs3[N_L3], g_s3[N_L3];
__device__ float g_vm4[N_L4], g_vs4[N_L4], g_s4[N_L4];
__device__ float g_part[N_PART];
__device__ float g_out[N_L4];

__device__ __forceinline__ float srm_g(float I, float* vm, float* vs, float* sp, int idx) {
    float so = sp[idx];
    float k = 1.0f - so;               // exactly 0 or 1
    float vmn = DM * vm[idx] * k + I;
    float vsn = DS * vs[idx] * k + I;
    float sn = ((vmn - vsn) > TH) ? 1.0f : 0.0f;
    vm[idx] = vmn; vs[idx] = vsn; sp[idx] = sn;
    return sn;
}

__global__ void zero_all() {
    int stride = gridDim.x * blockDim.x;
    int i0 = blockIdx.x * blockDim.x + threadIdx.x;
    for (int i = i0; i < N_L0; i += stride) { g_vm0[i] = 0.f; g_vs0[i] = 0.f; g_s0[i] = 0.f; }
    for (int i = i0; i < N_L1; i += stride) { g_vm1[i] = 0.f; g_vs1[i] = 0.f; g_s1[i] = 0.f; }
    for (int i = i0; i < N_L2; i += stride) { g_vm2[i] = 0.f; g_vs2[i] = 0.f; g_s2[i] = 0.f; }
    for (int i = i0; i < N_L3; i += stride) { g_vm3[i] = 0.f; g_vs3[i] = 0.f; g_s3[i] = 0.f; }
    for (int i = i0; i < N_L4; i += stride) { g_vm4[i] = 0.f; g_vs4[i] = 0.f; g_s4[i] = 0.f; g_out[i] = 0.f; }
}

// ---------------------------------------------------------------------------
// conv0: 2->64 on 64x64, tiled. CTA = one b, one 16x16 tile, all 64 co.
// 256 thr = 64 spatial (2x2 px) x 4 co-groups (16 co each).
__global__ void __launch_bounds__(256, 2)
conv0_srm(const float* __restrict__ x, const float* __restrict__ W0, int t) {
    __shared__ float ins[2 * 360];        // [2ci][18 rows][20 cols(pad)]
    __shared__ float ws[64 * 2 * 12];     // [64co][2ci][12(pad of 9)]
    int tid = threadIdx.x;
    int b = blockIdx.y;
    int tX = blockIdx.x & 3, tY = blockIdx.x >> 2;
    int x0 = tX * 16, y0 = tY * 16;

    // stage input (with clip) — 2x18x18 valid elements
    const float* xb = x + ((size_t)(b * 16 + t)) * 2 * 4096;
    for (int i = tid; i < 2 * 324; i += 256) {
        int ci = i / 324; int r = i - ci * 324;
        int y = r / 18;   int xq = r - y * 18;
        int gy = y0 + y - 1, gx = x0 + xq - 1;
        float v = 0.f;
        if ((unsigned)gy < 64u && (unsigned)gx < 64u) {
            v = __ldg(xb + ci * 4096 + gy * 64 + gx);
            v = fminf(fmaxf(v, 0.f), 1.f);
        }
        ins[ci * 360 + y * 20 + xq] = v;
    }
    // stage weights padded to 12
    for (int i = tid; i < 64 * 2 * 9; i += 256) {
        int co = i / 18; int r = i - co * 18;
        int ci = r / 9;  int k = r - ci * 9;
        ws[(co * 2 + ci) * 12 + k] = __ldg(W0 + i);
    }
    __syncthreads();

    int co_t = tid >> 6;              // 0..3, 16 co each
    int spt = tid & 63;
    int ty = spt >> 3, tx = spt & 7;

    float acc[16][2][2];
#pragma unroll
    for (int j = 0; j < 16; j++)
#pragma unroll
        for (int a = 0; a < 2; a++)
#pragma unroll
            for (int c = 0; c < 2; c++) acc[j][a][c] = 0.f;

#pragma unroll
    for (int ci = 0; ci < 2; ci++) {
        float iv[4][4];
        const float* ip = ins + ci * 360 + (2 * ty) * 20 + 2 * tx;
#pragma unroll
        for (int yy = 0; yy < 4; yy++) {
            float2 a2 = *reinterpret_cast<const float2*>(ip + yy * 20);
            float2 b2 = *reinterpret_cast<const float2*>(ip + yy * 20 + 2);
            iv[yy][0] = a2.x; iv[yy][1] = a2.y; iv[yy][2] = b2.x; iv[yy][3] = b2.y;
        }
#pragma unroll
        for (int j = 0; j < 16; j++) {
            const float* wb = ws + ((co_t * 16 + j) * 2 + ci) * 12;
            float4 wA = *reinterpret_cast<const float4*>(wb);
            float4 wB = *reinterpret_cast<const float4*>(wb + 4);
            float  w8 = wb[8];
#pragma unroll
            for (int ry = 0; ry < 2; ry++)
#pragma unroll
                for (int rx = 0; rx < 2; rx++) {
                    float s = acc[j][ry][rx];
                    s += iv[ry + 0][rx + 0] * wA.x; s += iv[ry + 0][rx + 1] * wA.y; s += iv[ry + 0][rx + 2] * wA.z;
                    s += iv[ry + 1][rx + 0] * wA.w; s += iv[ry + 1][rx + 1] * wB.x; s += iv[ry + 1][rx + 2] * wB.y;
                    s += iv[ry + 2][rx + 0] * wB.z; s += iv[ry + 2][rx + 1] * wB.w; s += iv[ry + 2][rx + 2] * w8;
                    acc[j][ry][rx] = s;
                }
        }
    }

#pragma unroll
    for (int j = 0; j < 16; j++) {
        int co = co_t * 16 + j;
#pragma unroll
        for (int ry = 0; ry < 2; ry++)
#pragma unroll
            for (int rx = 0; rx < 2; rx++) {
                int oy = y0 + 2 * ty + ry, ox = x0 + 2 * tx + rx;
                int idx = ((b * 64 + co) * 64 + oy) * 64 + ox;
                srm_g(acc[j][ry][rx], g_vm0, g_vs0, g_s0, idx);
            }
    }
}

// ---------------------------------------------------------------------------
// Tiled 3x3 conv (pad 1) + SRM + fused 2x2 maxpool.
// CTA: 16x16 spatial x 32 co, one b. ci staged in chunks of 16 (47.6KB smem
// -> 3 CTAs/SM). Vectorized LDS: weights padded to 12 (3x LDS.128/j),
// iv rows as 2x LDS.64. Per ci: 8+24 LDS vs 288 FFMA.
template<int CIN, int COUT, int HW>
__global__ void __launch_bounds__(256, 3)
conv_srm_pool(const float* __restrict__ in, const float* __restrict__ Wt,
              float* __restrict__ vm, float* __restrict__ vs, float* __restrict__ sp,
              float* __restrict__ pout)
{
    __shared__ float ins[16 * 360];       // [16ci][18][20 pad]
    __shared__ float ws[32 * 16 * 12];    // [32co][16ci][12 pad]
    const int NT = HW / 16;
    int tid = threadIdx.x;
    int b = blockIdx.z;
    int cog = blockIdx.y * 32;
    int tX = blockIdx.x % NT, tY = blockIdx.x / NT;
    int x0 = tX * 16, y0 = tY * 16;
    int co_t = tid >> 6;            // 0..3 (constant within warp -> broadcast weight LDS)
    int spt = tid & 63;
    int ty = spt >> 3, tx = spt & 7;

    float acc[8][2][2];
#pragma unroll
    for (int j = 0; j < 8; j++)
#pragma unroll
        for (int a = 0; a < 2; a++)
#pragma unroll
            for (int c = 0; c < 2; c++) acc[j][a][c] = 0.f;

    for (int cc = 0; cc < CIN; cc += 16) {
        __syncthreads();
#pragma unroll 1
        for (int i = tid; i < 16 * 324; i += 256) {
            int ci = i / 324; int r = i - ci * 324;
            int y = r / 18;   int xq = r - y * 18;
            int gy = y0 + y - 1, gx = x0 + xq - 1;
            float v = 0.f;
            if ((unsigned)gy < (unsigned)HW && (unsigned)gx < (unsigned)HW)
                v = in[((size_t)(b * CIN + cc + ci) * HW + gy) * HW + gx];
            ins[ci * 360 + y * 20 + xq] = v;
        }
#pragma unroll 1
        for (int i = tid; i < 32 * 16 * 9; i += 256) {
            int co = i / 144; int r = i - co * 144;
            int ci = r / 9;   int k = r - ci * 9;
            ws[(co * 16 + ci) * 12 + k] =
                __ldg(Wt + ((size_t)(cog + co) * CIN + cc + ci) * 9 + k);
        }
        __syncthreads();

#pragma unroll 1
        for (int ci = 0; ci < 16; ci++) {
            float iv[4][4];
            const float* ip = ins + ci * 360 + (2 * ty) * 20 + 2 * tx;
#pragma unroll
            for (int yy = 0; yy < 4; yy++) {
                float2 a2 = *reinterpret_cast<const float2*>(ip + yy * 20);
                float2 b2 = *reinterpret_cast<const float2*>(ip + yy * 20 + 2);
                iv[yy][0] = a2.x; iv[yy][1] = a2.y; iv[yy][2] = b2.x; iv[yy][3] = b2.y;
            }
            const float* wbase = ws + (co_t * 8 * 16 + ci) * 12;
#pragma unroll
            for (int j = 0; j < 8; j++) {
                const float* wb = wbase + j * 192;   // 16ci*12 per co
                float4 wA = *reinterpret_cast<const float4*>(wb);
                float4 wB = *reinterpret_cast<const float4*>(wb + 4);
                float  w8 = wb[8];
#pragma unroll
                for (int ry = 0; ry < 2; ry++)
#pragma unroll
                    for (int rx = 0; rx < 2; rx++) {
                        float s = acc[j][ry][rx];
                        s += iv[ry + 0][rx + 0] * wA.x; s += iv[ry + 0][rx + 1] * wA.y; s += iv[ry + 0][rx + 2] * wA.z;
                        s += iv[ry + 1][rx + 0] * wA.w; s += iv[ry + 1][rx + 1] * wB.x; s += iv[ry + 1][rx + 2] * wB.y;
                        s += iv[ry + 2][rx + 0] * wB.z; s += iv[ry + 2][rx + 1] * wB.w; s += iv[ry + 2][rx + 2] * w8;
                        acc[j][ry][rx] = s;
                    }
            }
        }
    }

    // Epilogue: SRM per output + fused 2x2 maxpool (spikes >= 0 -> init 0).
    const int HWo = HW / 2;
#pragma unroll
    for (int j = 0; j < 8; j++) {
        int co = cog + co_t * 8 + j;
        float mx = 0.f;
#pragma unroll
        for (int ry = 0; ry < 2; ry++)
#pragma unroll
            for (int rx = 0; rx < 2; rx++) {
                int oy = y0 + 2 * ty + ry, ox = x0 + 2 * tx + rx;
                int idx = ((b * COUT + co) * HW + oy) * HW + ox;
                float sn = srm_g(acc[j][ry][rx], vm, vs, sp, idx);
                mx = fmaxf(mx, sn);
            }
        pout[((size_t)(b * COUT + co) * HWo + (y0 / 2 + ty)) * HWo + (x0 / 2 + tx)] = mx;
    }
}

// ---------------------------------------------------------------------------
// fc3 split-K partial GEMM: C[16,512] = p2[16,32768] @ W3[512,32768]^T.
__global__ void __launch_bounds__(256) fc3_partial(const float* __restrict__ W3) {
    extern __shared__ float p2s[];   // [16][2048]
    int ks = blockIdx.x, jg = blockIdx.y;
    int k0 = ks * 2048;
    int tid = threadIdx.x;
    for (int i = tid; i < 16 * 2048; i += 256) {
        int b = i >> 11, k = i & 2047;
        p2s[i] = g_p2[b * 32768 + k0 + k];
    }
    __syncthreads();
    int wj = tid >> 5, lane = tid & 31;
    int j = jg * 8 + wj;
    const float4* wr = reinterpret_cast<const float4*>(W3 + (size_t)j * 32768 + k0);
    const float4* ps = reinterpret_cast<const float4*>(p2s);
    float acc[16];
#pragma unroll
    for (int b = 0; b < 16; b++) acc[b] = 0.f;
#pragma unroll 1
    for (int kk = lane; kk < 512; kk += 32) {
        float4 w4 = __ldg(wr + kk);
#pragma unroll
        for (int b = 0; b < 16; b++) {
            float4 p = ps[b * 512 + kk];
            acc[b] += w4.x * p.x; acc[b] += w4.y * p.y;
            acc[b] += w4.z * p.z; acc[b] += w4.w * p.w;
        }
    }
#pragma unroll
    for (int b = 0; b < 16; b++) {
        float v = acc[b];
        v += __shfl_down_sync(0xffffffffu, v, 16);
        v += __shfl_down_sync(0xffffffffu, v, 8);
        v += __shfl_down_sync(0xffffffffu, v, 4);
        v += __shfl_down_sync(0xffffffffu, v, 2);
        v += __shfl_down_sync(0xffffffffu, v, 1);
        if (lane == 0) g_part[(ks * 16 + b) * 512 + j] = v;
    }
}

__global__ void fc3_srm() {
    int i = blockIdx.x * 256 + threadIdx.x;   // 8192 = [b][j]
    float I = 0.f;
#pragma unroll
    for (int ks = 0; ks < 16; ks++) I += g_part[ks * 8192 + i];
    srm_g(I, g_vm3, g_vs3, g_s3, i);
}

// fc4 (512->11) + SRM + output accumulation. Single block.
__global__ void fc4_srm(const float* __restrict__ W4) {
    __shared__ float s3s[8192];
    int tid = threadIdx.x;
    for (int i = tid; i < 8192; i += 256) s3s[i] = g_s3[i];
    __syncthreads();
    if (tid < 176) {
        int b = tid / 11, j = tid % 11;
        const float4* wr = reinterpret_cast<const float4*>(W4 + j * 512);
        const float4* sr = reinterpret_cast<const float4*>(s3s + b * 512);
        float acc = 0.f;
#pragma unroll 4
        for (int k = 0; k < 128; k++) {
            float4 w = __ldg(wr + k), s = sr[k];
            acc += w.x * s.x; acc += w.y * s.y; acc += w.z * s.z; acc += w.w * s.w;
        }
        float sn = srm_g(acc, g_vm4, g_vs4, g_s4, tid);
        g_out[tid] += sn;
    }
}

__global__ void finalize_k(float* __restrict__ out) {
    int i = threadIdx.x;
    if (i < 176) out[i] = g_out[i] * 0.0625f;   // / num_steps (exact)
}

extern "C" void kernel_launch(void* const* d_in, const int* in_sizes, int n_in,
                              void* d_out, int out_size) {
    (void)in_sizes; (void)n_in; (void)out_size;
    const float* x  = (const float*)d_in[0];
    const float* W0 = (const float*)d_in[1];
    const float* W1 = (const float*)d_in[2];
    const float* W2 = (const float*)d_in[3];
    const float* W3 = (const float*)d_in[4];
    const float* W4 = (const float*)d_in[5];
    float* out = (float*)d_out;

    cudaFuncSetAttribute(fc3_partial,
                         cudaFuncAttributeMaxDynamicSharedMemorySize, 131072);

    float *s0, *vm1, *vs1, *s1, *p1, *vm2, *vs2, *s2, *p2;
    cudaGetSymbolAddress((void**)&s0,  g_s0);
    cudaGetSymbolAddress((void**)&vm1, g_vm1);
    cudaGetSymbolAddress((void**)&vs1, g_vs1);
    cudaGetSymbolAddress((void**)&s1,  g_s1);
    cudaGetSymbolAddress((void**)&p1,  g_p1);
    cudaGetSymbolAddress((void**)&vm2, g_vm2);
    cudaGetSymbolAddress((void**)&vs2, g_vs2);
    cudaGetSymbolAddress((void**)&s2,  g_s2);
    cudaGetSymbolAddress((void**)&p2,  g_p2);

    zero_all<<<2048, 256>>>();
    for (int t = 0; t < 16; t++) {
        conv0_srm<<<dim3(16, 16), 256>>>(x, W0, t);
        conv_srm_pool<64, 128, 64><<<dim3(16, 4, 16), 256>>>(s0, W1, vm1, vs1, s1, p1);
        conv_srm_pool<128, 128, 32><<<dim3(4, 4, 16), 256>>>(p1, W2, vm2, vs2, s2, p2);
        fc3_partial<<<dim3(16, 64), 256, 131072>>>(W3);
        fc3_srm<<<32, 256>>>();
        fc4_srm<<<1, 256>>>(W4);
    }
    finalize_k<<<1, 256>>>(out);
}

// round 4
// speedup vs baseline: 2.1013x; 1.9454x over previous
#include <cuda_runtime.h>
#include <cuda_bf16.h>

#define DM 0.9394130628134758f   /* exp(-1/16) */
#define DS 0.7788007830714049f   /* exp(-1/4)  */
#define TH 0.3f

#define N_L0 (16*64*64*64)
#define N_L1 (16*64*64*128)      /* conv1 state, NHWC */
#define N_L2 (16*32*32*128)      /* conv2 state, NHWC */
#define N_P2 (16*32768)
#define N_L3 (16*512)
#define N_L4 (16*11)
#define N_PART (16*16*512)

#define SZ_S0B (16*4356*64)      /* s0 spikes, guarded NHWC bf16 (66x66) */
#define SZ_P1B (16*1156*128)     /* p1 pooled spikes, guarded NHWC bf16 (34x34) */
#define NW1PK (9*3*4*16*32)      /* conv1 packed B: tap,split,kc,nt,lane */
#define NW2PK (9*3*8*16*32)

__device__ float g_vm0[N_L0], g_vs0[N_L0], g_s0[N_L0];
__device__ float g_vm1[N_L1], g_vs1[N_L1], g_sp1[N_L1];
__device__ float g_vm2[N_L2], g_vs2[N_L2], g_sp2[N_L2];
__device__ float g_p2[N_P2];
__device__ float g_vm3[N_L3], g_vs3[N_L3], g_s3[N_L3];
__device__ float g_vm4[N_L4], g_vs4[N_L4], g_s4[N_L4];
__device__ float g_part[N_PART];
__device__ float g_out[N_L4];
__device__ __nv_bfloat16 g_s0b[SZ_S0B];
__device__ __nv_bfloat16 g_p1b[SZ_P1B];
__device__ uint2 g_w1pk[NW1PK];
__device__ uint2 g_w2pk[NW2PK];

__device__ __forceinline__ float srm_g(float I, float* vm, float* vs, float* sp, size_t idx) {
    float so = sp[idx];
    float k = 1.0f - so;
    float vmn = DM * vm[idx] * k + I;
    float vsn = DS * vs[idx] * k + I;
    float sn = ((vmn - vsn) > TH) ? 1.0f : 0.0f;
    vm[idx] = vmn; vs[idx] = vsn; sp[idx] = sn;
    return sn;
}

// Paired SRM for two adjacent channels (co even). Vectorized float2 state access.
__device__ __forceinline__ void srm2(float I0, float I1,
                                     float* vm, float* vs, float* sp, size_t idx,
                                     float& s0, float& s1) {
    float2 vmv = *(float2*)(vm + idx);
    float2 vsv = *(float2*)(vs + idx);
    float2 spv = *(float2*)(sp + idx);
    float k0 = 1.f - spv.x, k1 = 1.f - spv.y;
    float a0 = DM * vmv.x * k0 + I0, a1 = DM * vmv.y * k1 + I1;
    float b0 = DS * vsv.x * k0 + I0, b1 = DS * vsv.y * k1 + I1;
    s0 = ((a0 - b0) > TH) ? 1.f : 0.f;
    s1 = ((a1 - b1) > TH) ? 1.f : 0.f;
    *(float2*)(vm + idx) = make_float2(a0, a1);
    *(float2*)(vs + idx) = make_float2(b0, b1);
    *(float2*)(sp + idx) = make_float2(s0, s1);
}

__global__ void zero_all() {
    int stride = gridDim.x * blockDim.x;
    int i0 = blockIdx.x * blockDim.x + threadIdx.x;
    for (int i = i0; i < N_L0; i += stride) { g_vm0[i] = 0.f; g_vs0[i] = 0.f; g_s0[i] = 0.f; }
    for (int i = i0; i < N_L1; i += stride) { g_vm1[i] = 0.f; g_vs1[i] = 0.f; g_sp1[i] = 0.f; }
    for (int i = i0; i < N_L2; i += stride) { g_vm2[i] = 0.f; g_vs2[i] = 0.f; g_sp2[i] = 0.f; }
    for (int i = i0; i < N_L3; i += stride) { g_vm3[i] = 0.f; g_vs3[i] = 0.f; g_s3[i] = 0.f; }
    for (int i = i0; i < N_L4; i += stride) { g_vm4[i] = 0.f; g_vs4[i] = 0.f; g_s4[i] = 0.f; g_out[i] = 0.f; }
    unsigned* s0b = (unsigned*)g_s0b;
    for (int i = i0; i < SZ_S0B / 2; i += stride) s0b[i] = 0u;
    unsigned* p1b = (unsigned*)g_p1b;
    for (int i = i0; i < SZ_P1B / 2; i += stride) p1b[i] = 0u;
}

// ---------------------------------------------------------------------------
// Weight prepack: W[co][ci][3][3] fp32 -> mma B-fragments, bf16 3-way split.
// Layout: idx = (((tap*3+split)*KC + kc)*16 + nt)*32 + lane, value = uint2
//   n = nt*8 + lane>>2 ; k0 = kc*16 + (lane&3)*2 ; .x = {w[k0],w[k0+1]}, .y = {k0+8,k0+9}
__device__ __forceinline__ unsigned pick_split_pack(float wa, float wb, int split) {
    __nv_bfloat16 ha = __float2bfloat16(wa);
    float ra = wa - __bfloat162float(ha);
    __nv_bfloat16 ma = __float2bfloat16(ra);
    __nv_bfloat16 la = __float2bfloat16(ra - __bfloat162float(ma));
    __nv_bfloat16 hb = __float2bfloat16(wb);
    float rb = wb - __bfloat162float(hb);
    __nv_bfloat16 mb = __float2bfloat16(rb);
    __nv_bfloat16 lb = __float2bfloat16(rb - __bfloat162float(mb));
    __nv_bfloat16 va = (split == 0) ? ha : (split == 1) ? ma : la;
    __nv_bfloat16 vb = (split == 0) ? hb : (split == 1) ? mb : lb;
    unsigned ua = (unsigned)__bfloat16_as_ushort(va);
    unsigned ub = (unsigned)__bfloat16_as_ushort(vb);
    return ua | (ub << 16);
}

__global__ void pack_w(const float* __restrict__ W, uint2* __restrict__ Bpk, int CIN, int total) {
    int idx = blockIdx.x * 256 + threadIdx.x;
    if (idx >= total) return;
    int KC = CIN / 16;
    int lane = idx & 31;
    int nt = (idx >> 5) & 15;
    int rest = idx >> 9;
    int kc = rest % KC; rest /= KC;
    int split = rest % 3; int tap = rest / 3;
    int ky = tap / 3, kx = tap % 3;
    int n = nt * 8 + (lane >> 2);
    int k0 = kc * 16 + (lane & 3) * 2;
    float w0 = W[((size_t)(n * CIN + k0 + 0) * 3 + ky) * 3 + kx];
    float w1 = W[((size_t)(n * CIN + k0 + 1) * 3 + ky) * 3 + kx];
    float w8 = W[((size_t)(n * CIN + k0 + 8) * 3 + ky) * 3 + kx];
    float w9 = W[((size_t)(n * CIN + k0 + 9) * 3 + ky) * 3 + kx];
    uint2 v;
    v.x = pick_split_pack(w0, w1, split);
    v.y = pick_split_pack(w8, w9, split);
    Bpk[idx] = v;
}

// ---------------------------------------------------------------------------
// conv0: 2->64 on 64x64 (scalar; tiny). Writes spikes to guarded NHWC bf16 buf.
__global__ void __launch_bounds__(256, 2)
conv0_srm(const float* __restrict__ x, const float* __restrict__ W0, int t) {
    __shared__ float ins[2 * 360];
    __shared__ float ws[64 * 2 * 12];
    int tid = threadIdx.x;
    int b = blockIdx.y;
    int tX = blockIdx.x & 3, tY = blockIdx.x >> 2;
    int x0 = tX * 16, y0 = tY * 16;

    const float* xb = x + ((size_t)(b * 16 + t)) * 2 * 4096;
    for (int i = tid; i < 2 * 324; i += 256) {
        int ci = i / 324; int r = i - ci * 324;
        int y = r / 18;   int xq = r - y * 18;
        int gy = y0 + y - 1, gx = x0 + xq - 1;
        float v = 0.f;
        if ((unsigned)gy < 64u && (unsigned)gx < 64u) {
            v = __ldg(xb + ci * 4096 + gy * 64 + gx);
            v = fminf(fmaxf(v, 0.f), 1.f);
        }
        ins[ci * 360 + y * 20 + xq] = v;
    }
    for (int i = tid; i < 64 * 2 * 9; i += 256) {
        int co = i / 18; int r = i - co * 18;
        int ci = r / 9;  int k = r - ci * 9;
        ws[(co * 2 + ci) * 12 + k] = __ldg(W0 + i);
    }
    __syncthreads();

    int co_t = tid >> 6;
    int spt = tid & 63;
    int ty = spt >> 3, tx = spt & 7;

    float acc[16][2][2];
#pragma unroll
    for (int j = 0; j < 16; j++)
#pragma unroll
        for (int a = 0; a < 2; a++)
#pragma unroll
            for (int c = 0; c < 2; c++) acc[j][a][c] = 0.f;

#pragma unroll
    for (int ci = 0; ci < 2; ci++) {
        float iv[4][4];
        const float* ip = ins + ci * 360 + (2 * ty) * 20 + 2 * tx;
#pragma unroll
        for (int yy = 0; yy < 4; yy++) {
            float2 a2 = *reinterpret_cast<const float2*>(ip + yy * 20);
            float2 b2 = *reinterpret_cast<const float2*>(ip + yy * 20 + 2);
            iv[yy][0] = a2.x; iv[yy][1] = a2.y; iv[yy][2] = b2.x; iv[yy][3] = b2.y;
        }
#pragma unroll
        for (int j = 0; j < 16; j++) {
            const float* wb = ws + ((co_t * 16 + j) * 2 + ci) * 12;
            float4 wA = *reinterpret_cast<const float4*>(wb);
            float4 wB = *reinterpret_cast<const float4*>(wb + 4);
            float  w8 = wb[8];
#pragma unroll
            for (int ry = 0; ry < 2; ry++)
#pragma unroll
                for (int rx = 0; rx < 2; rx++) {
                    float s = acc[j][ry][rx];
                    s += iv[ry + 0][rx + 0] * wA.x; s += iv[ry + 0][rx + 1] * wA.y; s += iv[ry + 0][rx + 2] * wA.z;
                    s += iv[ry + 1][rx + 0] * wA.w; s += iv[ry + 1][rx + 1] * wB.x; s += iv[ry + 1][rx + 2] * wB.y;
                    s += iv[ry + 2][rx + 0] * wB.z; s += iv[ry + 2][rx + 1] * wB.w; s += iv[ry + 2][rx + 2] * w8;
                    acc[j][ry][rx] = s;
                }
        }
    }

#pragma unroll
    for (int ry = 0; ry < 2; ry++)
#pragma unroll
        for (int rx = 0; rx < 2; rx++) {
            int oy = y0 + 2 * ty + ry, ox = x0 + 2 * tx + rx;
            size_t qb = ((size_t)b * 4356 + (oy + 1) * 66 + (ox + 1)) * 64 + co_t * 16;
#pragma unroll
            for (int j = 0; j < 16; j += 2) {
                int co = co_t * 16 + j;
                size_t i0 = ((size_t)(b * 64 + co) * 64 + oy) * 64 + ox;
                size_t i1 = ((size_t)(b * 64 + co + 1) * 64 + oy) * 64 + ox;
                float s0 = srm_g(acc[j][ry][rx],     g_vm0, g_vs0, g_s0, i0);
                float s1 = srm_g(acc[j + 1][ry][rx], g_vm0, g_vs0, g_s0, i1);
                *reinterpret_cast<__nv_bfloat162*>(g_s0b + qb + j) = __floats2bfloat162_rn(s0, s1);
            }
        }
}

// ---------------------------------------------------------------------------
// mma.sync bf16 helper
__device__ __forceinline__ void mma16816(float* c, const unsigned* a, unsigned b0, unsigned b1) {
    asm volatile(
        "mma.sync.aligned.m16n8k16.row.col.f32.bf16.bf16.f32 "
        "{%0,%1,%2,%3}, {%4,%5,%6,%7}, {%8,%9}, {%0,%1,%2,%3};\n"
        : "+f"(c[0]), "+f"(c[1]), "+f"(c[2]), "+f"(c[3])
        : "r"(a[0]), "r"(a[1]), "r"(a[2]), "r"(a[3]), "r"(b0), "r"(b1));
}

// ---------------------------------------------------------------------------
// Implicit-GEMM conv (3x3, pad 1) on tensor cores, SRM + 2x2 maxpool fused.
// A = binary spikes NHWC bf16 guard-padded buffer; B = prepacked 3-split weights.
// CTA: M=128 pixels (YROWS full rows) x N=128 co, one b. 8 warps = 2(M) x 4(N).
template<int HW, int CIN, int YROWS, int SHIFT, bool IS_CONV2>
__global__ void __launch_bounds__(256, 2)
conv_mma(const __nv_bfloat16* __restrict__ Abuf,
         const uint2* __restrict__ Bpk,
         float* __restrict__ vm, float* __restrict__ vs, float* __restrict__ sp,
         __nv_bfloat16* __restrict__ poolb,   // conv1: p1b
         float* __restrict__ p2out)           // conv2: g_p2
{
    const int WB = HW + 2, QTOT = WB * WB, KC = CIN / 16;
    const int PITCHE = CIN + 8;               // bf16 units; pitch%32 words == 4 -> no LDS conflicts
    const int SLABROWS = (YROWS + 2) * WB;
    const int CPR = CIN / 8;                  // uint4 chunks per row
    extern __shared__ __align__(16) unsigned char dsm[];
    __nv_bfloat16* As = (__nv_bfloat16*)dsm;

    int tid = threadIdx.x, lane = tid & 31, wid = tid >> 5;
    int warp_m = wid >> 2, warp_n = wid & 3;
    int b = blockIdx.y;
    int y0 = blockIdx.x * YROWS;
    int q0 = y0 * WB;

    // stage A slab (rows q0 .. q0+SLABROWS)
    for (int i = tid; i < SLABROWS * CPR; i += 256) {
        int rrow = i / CPR, cw = i - rrow * CPR;
        uint4 v = __ldg((const uint4*)(Abuf + ((size_t)b * QTOT + q0 + rrow) * CIN) + cw);
        *(uint4*)(As + rrow * PITCHE + cw * 8) = v;
    }
    __syncthreads();

    // per-lane m-tile mapping: conv1 interleaves so pool y-pairs stay in-warp
    int mtg[4];
    int mbase[4][2];
#pragma unroll
    for (int l = 0; l < 4; l++) {
        int g = (YROWS == 2) ? (warp_m * 2 + (l & 1) + ((l & 2) << 1)) : (warp_m * 4 + l);
        mtg[l] = g;
#pragma unroll
        for (int o = 0; o < 2; o++) {
            int m = g * 16 + (lane >> 2) + o * 8;
            mbase[l][o] = (m >> SHIFT) * WB + (m & (HW - 1));
        }
    }
    int kcol = (lane & 3) * 4;

    float acc[4][4][4];
#pragma unroll
    for (int l = 0; l < 4; l++)
#pragma unroll
        for (int j = 0; j < 4; j++)
#pragma unroll
            for (int c = 0; c < 4; c++) acc[l][j][c] = 0.f;

#pragma unroll 1
    for (int tap = 0; tap < 9; tap++) {
        int ky = tap / 3, kx = tap - ky * 3;
        int ra[4][2];
#pragma unroll
        for (int l = 0; l < 4; l++)
#pragma unroll
            for (int o = 0; o < 2; o++)
                ra[l][o] = (mbase[l][o] + ky * WB + kx) * (PITCHE * 2);
#pragma unroll 1
        for (int kc = 0; kc < KC; kc++) {
            unsigned a[4][4];
            int kb = kc * 32 + kcol;
#pragma unroll
            for (int l = 0; l < 4; l++) {
                a[l][0] = *(const unsigned*)((const char*)As + ra[l][0] + kb);
                a[l][1] = *(const unsigned*)((const char*)As + ra[l][1] + kb);
                a[l][2] = *(const unsigned*)((const char*)As + ra[l][0] + kb + 16);
                a[l][3] = *(const unsigned*)((const char*)As + ra[l][1] + kb + 16);
            }
            const uint2* bbase = Bpk + (((size_t)(tap * 3) * KC + kc) * 16 + warp_n * 4) * 32 + lane;
#pragma unroll
            for (int s = 0; s < 3; s++) {
                uint2 bb[4];
#pragma unroll
                for (int j = 0; j < 4; j++) bb[j] = __ldg(bbase + (size_t)s * KC * 512 + j * 32);
#pragma unroll
                for (int l = 0; l < 4; l++)
#pragma unroll
                    for (int j = 0; j < 4; j++)
                        mma16816(acc[l][j], a[l], bb[j].x, bb[j].y);
            }
        }
    }

    // Epilogue: SRM per neuron + 2x2 maxpool.
    // y-pairs = mtiles (l, l+2); x-pairs = lane^4; even-r lanes own pooled output.
    const int HWo = HW / 2;
    (void)HWo;
#pragma unroll
    for (int lp = 0; lp < 2; lp++) {
#pragma unroll
        for (int o = 0; o < 2; o++) {
            int mA = mtg[lp] * 16 + (lane >> 2) + o * 8;
            int mB = mtg[lp + 2] * 16 + (lane >> 2) + o * 8;
            int yA = y0 + (mA >> SHIFT), xA = mA & (HW - 1);
            int yB = y0 + (mB >> SHIFT);
#pragma unroll
            for (int j = 0; j < 4; j++) {
                int co = warp_n * 32 + j * 8 + (lane & 3) * 2;
                size_t iA = ((size_t)(b * HW * HW) + yA * HW + xA) * 128 + co;
                size_t iB = ((size_t)(b * HW * HW) + yB * HW + xA) * 128 + co;
                float sA0, sA1, sB0, sB1;
                srm2(acc[lp][j][o * 2 + 0],     acc[lp][j][o * 2 + 1],     vm, vs, sp, iA, sA0, sA1);
                srm2(acc[lp + 2][j][o * 2 + 0], acc[lp + 2][j][o * 2 + 1], vm, vs, sp, iB, sB0, sB1);
                // x-pool via shfl, then y-pool in-register
                float xA0 = fmaxf(sA0, __shfl_xor_sync(0xffffffffu, sA0, 4));
                float xA1 = fmaxf(sA1, __shfl_xor_sync(0xffffffffu, sA1, 4));
                float xB0 = fmaxf(sB0, __shfl_xor_sync(0xffffffffu, sB0, 4));
                float xB1 = fmaxf(sB1, __shfl_xor_sync(0xffffffffu, sB1, 4));
                float p0 = fmaxf(xA0, xB0);
                float p1 = fmaxf(xA1, xB1);
                if ((lane & 4) == 0) {
                    int yp = yA >> 1, xp = xA >> 1;   // yA is even member of pair
                    if (IS_CONV2) {
                        p2out[(size_t)b * 32768 + co * 256 + yp * 16 + xp] = p0;
                        p2out[(size_t)b * 32768 + (co + 1) * 256 + yp * 16 + xp] = p1;
                    } else {
                        size_t qi = ((size_t)b * 1156 + (yp + 1) * 34 + (xp + 1)) * 128 + co;
                        *reinterpret_cast<__nv_bfloat162*>(poolb + qi) = __floats2bfloat162_rn(p0, p1);
                    }
                }
            }
        }
    }
}

// ---------------------------------------------------------------------------
// fc3 split-K partial GEMM: C[16,512] = p2[16,32768] @ W3[512,32768]^T.
__global__ void __launch_bounds__(256) fc3_partial(const float* __restrict__ W3) {
    extern __shared__ float p2s[];   // [16][2048]
    int ks = blockIdx.x, jg = blockIdx.y;
    int k0 = ks * 2048;
    int tid = threadIdx.x;
    for (int i = tid; i < 16 * 2048; i += 256) {
        int b = i >> 11, k = i & 2047;
        p2s[i] = g_p2[b * 32768 + k0 + k];
    }
    __syncthreads();
    int wj = tid >> 5, lane = tid & 31;
    int j = jg * 8 + wj;
    const float4* wr = reinterpret_cast<const float4*>(W3 + (size_t)j * 32768 + k0);
    const float4* ps = reinterpret_cast<const float4*>(p2s);
    float acc[16];
#pragma unroll
    for (int b = 0; b < 16; b++) acc[b] = 0.f;
#pragma unroll 1
    for (int kk = lane; kk < 512; kk += 32) {
        float4 w4 = __ldg(wr + kk);
#pragma unroll
        for (int b = 0; b < 16; b++) {
            float4 p = ps[b * 512 + kk];
            acc[b] += w4.x * p.x; acc[b] += w4.y * p.y;
            acc[b] += w4.z * p.z; acc[b] += w4.w * p.w;
        }
    }
#pragma unroll
    for (int b = 0; b < 16; b++) {
        float v = acc[b];
        v += __shfl_down_sync(0xffffffffu, v, 16);
        v += __shfl_down_sync(0xffffffffu, v, 8);
        v += __shfl_down_sync(0xffffffffu, v, 4);
        v += __shfl_down_sync(0xffffffffu, v, 2);
        v += __shfl_down_sync(0xffffffffu, v, 1);
        if (lane == 0) g_part[(ks * 16 + b) * 512 + j] = v;
    }
}

__global__ void fc3_srm() {
    int i = blockIdx.x * 256 + threadIdx.x;
    float I = 0.f;
#pragma unroll
    for (int ks = 0; ks < 16; ks++) I += g_part[ks * 8192 + i];
    srm_g(I, g_vm3, g_vs3, g_s3, i);
}

__global__ void fc4_srm(const float* __restrict__ W4) {
    __shared__ float s3s[8192];
    int tid = threadIdx.x;
    for (int i = tid; i < 8192; i += 256) s3s[i] = g_s3[i];
    __syncthreads();
    if (tid < 176) {
        int b = tid / 11, j = tid % 11;
        const float4* wr = reinterpret_cast<const float4*>(W4 + j * 512);
        const float4* sr = reinterpret_cast<const float4*>(s3s + b * 512);
        float acc = 0.f;
#pragma unroll 4
        for (int k = 0; k < 128; k++) {
            float4 w = __ldg(wr + k), s = sr[k];
            acc += w.x * s.x; acc += w.y * s.y; acc += w.z * s.z; acc += w.w * s.w;
        }
        float sn = srm_g(acc, g_vm4, g_vs4, g_s4, tid);
        g_out[tid] += sn;
    }
}

__global__ void finalize_k(float* __restrict__ out) {
    int i = threadIdx.x;
    if (i < 176) out[i] = g_out[i] * 0.0625f;
}

extern "C" void kernel_launch(void* const* d_in, const int* in_sizes, int n_in,
                              void* d_out, int out_size) {
    (void)in_sizes; (void)n_in; (void)out_size;
    const float* x  = (const float*)d_in[0];
    const float* W0 = (const float*)d_in[1];
    const float* W1 = (const float*)d_in[2];
    const float* W2 = (const float*)d_in[3];
    const float* W3 = (const float*)d_in[4];
    const float* W4 = (const float*)d_in[5];
    float* out = (float*)d_out;

    const int SMEM1 = 264 * 144;   // 38016 B
    const int SMEM2 = 204 * 272;   // 55488 B
    cudaFuncSetAttribute((const void*)conv_mma<64, 64, 2, 6, false>,
                         cudaFuncAttributeMaxDynamicSharedMemorySize, SMEM1);
    cudaFuncSetAttribute((const void*)conv_mma<32, 128, 4, 5, true>,
                         cudaFuncAttributeMaxDynamicSharedMemorySize, SMEM2);
    cudaFuncSetAttribute((const void*)fc3_partial,
                         cudaFuncAttributeMaxDynamicSharedMemorySize, 131072);

    __nv_bfloat16 *s0b, *p1b;
    uint2 *w1pk, *w2pk;
    float *vm1, *vs1, *sp1, *vm2, *vs2, *sp2, *p2;
    cudaGetSymbolAddress((void**)&s0b, g_s0b);
    cudaGetSymbolAddress((void**)&p1b, g_p1b);
    cudaGetSymbolAddress((void**)&w1pk, g_w1pk);
    cudaGetSymbolAddress((void**)&w2pk, g_w2pk);
    cudaGetSymbolAddress((void**)&vm1, g_vm1);
    cudaGetSymbolAddress((void**)&vs1, g_vs1);
    cudaGetSymbolAddress((void**)&sp1, g_sp1);
    cudaGetSymbolAddress((void**)&vm2, g_vm2);
    cudaGetSymbolAddress((void**)&vs2, g_vs2);
    cudaGetSymbolAddress((void**)&sp2, g_sp2);
    cudaGetSymbolAddress((void**)&p2,  g_p2);

    zero_all<<<2048, 256>>>();
    pack_w<<<(NW1PK + 255) / 256, 256>>>(W1, w1pk, 64, NW1PK);
    pack_w<<<(NW2PK + 255) / 256, 256>>>(W2, w2pk, 128, NW2PK);
    for (int t = 0; t < 16; t++) {
        conv0_srm<<<dim3(16, 16), 256>>>(x, W0, t);
        conv_mma<64, 64, 2, 6, false><<<dim3(32, 16), 256, SMEM1>>>(
            s0b, w1pk, vm1, vs1, sp1, p1b, nullptr);
        conv_mma<32, 128, 4, 5, true><<<dim3(8, 16), 256, SMEM2>>>(
            p1b, w2pk, vm2, vs2, sp2, nullptr, p2);
        fc3_partial<<<dim3(16, 64), 256, 131072>>>(W3);
        fc3_srm<<<32, 256>>>();
        fc4_srm<<<1, 256>>>(W4);
    }
    finalize_k<<<1, 256>>>(out);
}

// round 5
// speedup vs baseline: 2.1311x; 1.0142x over previous
#include <cuda_runtime.h>
#include <cuda_bf16.h>
#include <cstdint>

#define DM 0.9394130628134758f   /* exp(-1/16) */
#define DS 0.7788007830714049f   /* exp(-1/4)  */
#define TH 0.3f

#define N_L0 (16*64*64*64)       /* conv0 state, NHWC */
#define N_L1 (16*64*64*128)      /* conv1 state, NHWC */
#define N_L2 (16*32*32*128)      /* conv2 state, NHWC */
#define N_P2 (16*32768)
#define N_L3 (16*512)
#define N_L4 (16*11)
#define N_PART (16*16*512)

#define SZ_S0B (16*4356*64)      /* s0 spikes, guarded NHWC bf16 (66x66) */
#define SZ_P1B (16*1156*128)     /* p1 pooled spikes, guarded NHWC bf16 (34x34) */
#define NW1PK (9*3*4*16*32)
#define NW2PK (9*3*8*16*32)

__device__ float g_vm0[N_L0], g_vs0[N_L0];
__device__ float g_vm1[N_L1], g_vs1[N_L1], g_sp1[N_L1];
__device__ float g_vm2[N_L2], g_vs2[N_L2], g_sp2[N_L2];
__device__ float g_p2[N_P2];
__device__ float g_vm3[N_L3], g_vs3[N_L3], g_sp3[N_L3];
__device__ float g_vm4[N_L4], g_vs4[N_L4], g_s4[N_L4];
__device__ float g_part[N_PART];
__device__ float g_out[N_L4];
__device__ __nv_bfloat16 g_s0b[SZ_S0B];
__device__ __nv_bfloat16 g_p1b[SZ_P1B];
__device__ uint2 g_w1pk[NW1PK];
__device__ uint2 g_w2pk[NW2PK];

__device__ __forceinline__ float srm_g(float I, float* vm, float* vs, float* sp, size_t idx) {
    float so = sp[idx];
    float k = 1.0f - so;
    float vmn = DM * vm[idx] * k + I;
    float vsn = DS * vs[idx] * k + I;
    float sn = ((vmn - vsn) > TH) ? 1.0f : 0.0f;
    vm[idx] = vmn; vs[idx] = vsn; sp[idx] = sn;
    return sn;
}

__device__ __forceinline__ void srm2(float I0, float I1,
                                     float* vm, float* vs, float* sp, size_t idx,
                                     float& s0, float& s1) {
    float2 vmv = *(float2*)(vm + idx);
    float2 vsv = *(float2*)(vs + idx);
    float2 spv = *(float2*)(sp + idx);
    float k0 = 1.f - spv.x, k1 = 1.f - spv.y;
    float a0 = DM * vmv.x * k0 + I0, a1 = DM * vmv.y * k1 + I1;
    float b0 = DS * vsv.x * k0 + I0, b1 = DS * vsv.y * k1 + I1;
    s0 = ((a0 - b0) > TH) ? 1.f : 0.f;
    s1 = ((a1 - b1) > TH) ? 1.f : 0.f;
    *(float2*)(vm + idx) = make_float2(a0, a1);
    *(float2*)(vs + idx) = make_float2(b0, b1);
    *(float2*)(sp + idx) = make_float2(s0, s1);
}

__global__ void zero_all() {
    int stride = gridDim.x * blockDim.x;
    int i0 = blockIdx.x * blockDim.x + threadIdx.x;
    for (int i = i0; i < N_L0; i += stride) { g_vm0[i] = 0.f; g_vs0[i] = 0.f; }
    for (int i = i0; i < N_L1; i += stride) { g_vm1[i] = 0.f; g_vs1[i] = 0.f; g_sp1[i] = 0.f; }
    for (int i = i0; i < N_L2; i += stride) { g_vm2[i] = 0.f; g_vs2[i] = 0.f; g_sp2[i] = 0.f; }
    for (int i = i0; i < N_L3; i += stride) { g_vm3[i] = 0.f; g_vs3[i] = 0.f; g_sp3[i] = 0.f; }
    for (int i = i0; i < N_L4; i += stride) { g_vm4[i] = 0.f; g_vs4[i] = 0.f; g_s4[i] = 0.f; g_out[i] = 0.f; }
    unsigned* s0b = (unsigned*)g_s0b;
    for (int i = i0; i < SZ_S0B / 2; i += stride) s0b[i] = 0u;
    unsigned* p1b = (unsigned*)g_p1b;
    for (int i = i0; i < SZ_P1B / 2; i += stride) p1b[i] = 0u;
}

// ---------------------------------------------------------------------------
// Weight prepack: W[co][ci][3][3] fp32 -> mma B-fragments, bf16 3-way split.
__device__ __forceinline__ unsigned pick_split_pack(float wa, float wb, int split) {
    __nv_bfloat16 ha = __float2bfloat16(wa);
    float ra = wa - __bfloat162float(ha);
    __nv_bfloat16 ma = __float2bfloat16(ra);
    __nv_bfloat16 la = __float2bfloat16(ra - __bfloat162float(ma));
    __nv_bfloat16 hb = __float2bfloat16(wb);
    float rb = wb - __bfloat162float(hb);
    __nv_bfloat16 mb = __float2bfloat16(rb);
    __nv_bfloat16 lb = __float2bfloat16(rb - __bfloat162float(mb));
    __nv_bfloat16 va = (split == 0) ? ha : (split == 1) ? ma : la;
    __nv_bfloat16 vb = (split == 0) ? hb : (split == 1) ? mb : lb;
    unsigned ua = (unsigned)__bfloat16_as_ushort(va);
    unsigned ub = (unsigned)__bfloat16_as_ushort(vb);
    return ua | (ub << 16);
}

__global__ void pack_w(const float* __restrict__ W, uint2* __restrict__ Bpk, int CIN, int total) {
    int idx = blockIdx.x * 256 + threadIdx.x;
    if (idx >= total) return;
    int KC = CIN / 16;
    int lane = idx & 31;
    int nt = (idx >> 5) & 15;
    int rest = idx >> 9;
    int kc = rest % KC; rest /= KC;
    int split = rest % 3; int tap = rest / 3;
    int ky = tap / 3, kx = tap % 3;
    int n = nt * 8 + (lane >> 2);
    int k0 = kc * 16 + (lane & 3) * 2;
    float w0 = W[((size_t)(n * CIN + k0 + 0) * 3 + ky) * 3 + kx];
    float w1 = W[((size_t)(n * CIN + k0 + 1) * 3 + ky) * 3 + kx];
    float w8 = W[((size_t)(n * CIN + k0 + 8) * 3 + ky) * 3 + kx];
    float w9 = W[((size_t)(n * CIN + k0 + 9) * 3 + ky) * 3 + kx];
    uint2 v;
    v.x = pick_split_pack(w0, w1, split);
    v.y = pick_split_pack(w8, w9, split);
    Bpk[idx] = v;
}

// ---------------------------------------------------------------------------
// conv0: 2->64 on 64x64. grid (16 tiles, 4 co-groups, 16 b), 1 px x 16 co per thread.
// NHWC fp32 vm/vs state; previous spike read from g_s0b (exact 0/1 in bf16).
__global__ void __launch_bounds__(256)
conv0_srm(const float* __restrict__ x, const float* __restrict__ W0, int t) {
    __shared__ float ins[2 * 360];        // [2ci][18 rows][20 cols pad]
    __shared__ float ws[16 * 2 * 12];     // [16co][2ci][12 pad]
    int tid = threadIdx.x;
    int b = blockIdx.z;
    int cog = blockIdx.y;                 // 16-co group
    int tX = blockIdx.x & 3, tY = blockIdx.x >> 2;
    int x0 = tX * 16, y0 = tY * 16;

    const float* xb = x + ((size_t)(b * 16 + t)) * 2 * 4096;
    for (int i = tid; i < 2 * 324; i += 256) {
        int ci = i / 324; int r = i - ci * 324;
        int y = r / 18;   int xq = r - y * 18;
        int gy = y0 + y - 1, gx = x0 + xq - 1;
        float v = 0.f;
        if ((unsigned)gy < 64u && (unsigned)gx < 64u) {
            v = __ldg(xb + ci * 4096 + gy * 64 + gx);
            v = fminf(fmaxf(v, 0.f), 1.f);
        }
        ins[ci * 360 + y * 20 + xq] = v;
    }
    for (int i = tid; i < 16 * 18; i += 256) {
        int col = i / 18; int r = i - col * 18;
        int ci = r / 9;   int k = r - ci * 9;
        ws[(col * 2 + ci) * 12 + k] = __ldg(W0 + ((size_t)(cog * 16 + col) * 2 + ci) * 9 + k);
    }
    __syncthreads();

    int ty = tid >> 4, tx = tid & 15;
    float acc[16];
#pragma unroll
    for (int j = 0; j < 16; j++) acc[j] = 0.f;

#pragma unroll
    for (int ci = 0; ci < 2; ci++) {
        const float* ip = ins + ci * 360 + ty * 20 + tx;
        float iv[3][3];
#pragma unroll
        for (int yy = 0; yy < 3; yy++)
#pragma unroll
            for (int xx = 0; xx < 3; xx++) iv[yy][xx] = ip[yy * 20 + xx];
#pragma unroll
        for (int j = 0; j < 16; j++) {
            const float* wb = ws + (j * 2 + ci) * 12;
            float4 wA = *reinterpret_cast<const float4*>(wb);
            float4 wB = *reinterpret_cast<const float4*>(wb + 4);
            float  w8 = wb[8];
            float s = acc[j];
            s += iv[0][0] * wA.x; s += iv[0][1] * wA.y; s += iv[0][2] * wA.z;
            s += iv[1][0] * wA.w; s += iv[1][1] * wB.x; s += iv[1][2] * wB.y;
            s += iv[2][0] * wB.z; s += iv[2][1] * wB.w; s += iv[2][2] * w8;
            acc[j] = s;
        }
    }

    int oy = y0 + ty, ox = x0 + tx;
    size_t sidx = ((size_t)b * 4096 + oy * 64 + ox) * 64 + cog * 16;
    size_t qb = ((size_t)b * 4356 + (oy + 1) * 66 + (ox + 1)) * 64 + cog * 16;
#pragma unroll
    for (int q = 0; q < 4; q++) {
        float4 vmv = *(float4*)(g_vm0 + sidx + q * 4);
        float4 vsv = *(float4*)(g_vs0 + sidx + q * 4);
        __nv_bfloat162 pA = *(__nv_bfloat162*)(g_s0b + qb + q * 4);
        __nv_bfloat162 pB = *(__nv_bfloat162*)(g_s0b + qb + q * 4 + 2);
        float k0 = 1.f - __low2float(pA),  k1 = 1.f - __high2float(pA);
        float k2 = 1.f - __low2float(pB),  k3 = 1.f - __high2float(pB);
        float I0 = acc[q * 4 + 0], I1 = acc[q * 4 + 1], I2 = acc[q * 4 + 2], I3 = acc[q * 4 + 3];
        float a0 = DM * vmv.x * k0 + I0, a1 = DM * vmv.y * k1 + I1;
        float a2 = DM * vmv.z * k2 + I2, a3 = DM * vmv.w * k3 + I3;
        float c0 = DS * vsv.x * k0 + I0, c1 = DS * vsv.y * k1 + I1;
        float c2 = DS * vsv.z * k2 + I2, c3 = DS * vsv.w * k3 + I3;
        float s0 = ((a0 - c0) > TH) ? 1.f : 0.f;
        float s1 = ((a1 - c1) > TH) ? 1.f : 0.f;
        float s2 = ((a2 - c2) > TH) ? 1.f : 0.f;
        float s3 = ((a3 - c3) > TH) ? 1.f : 0.f;
        *(float4*)(g_vm0 + sidx + q * 4) = make_float4(a0, a1, a2, a3);
        *(float4*)(g_vs0 + sidx + q * 4) = make_float4(c0, c1, c2, c3);
        *(__nv_bfloat162*)(g_s0b + qb + q * 4)     = __floats2bfloat162_rn(s0, s1);
        *(__nv_bfloat162*)(g_s0b + qb + q * 4 + 2) = __floats2bfloat162_rn(s2, s3);
    }
}

// ---------------------------------------------------------------------------
__device__ __forceinline__ void mma16816(float* c, const unsigned* a, unsigned b0, unsigned b1) {
    asm volatile(
        "mma.sync.aligned.m16n8k16.row.col.f32.bf16.bf16.f32 "
        "{%0,%1,%2,%3}, {%4,%5,%6,%7}, {%8,%9}, {%0,%1,%2,%3};\n"
        : "+f"(c[0]), "+f"(c[1]), "+f"(c[2]), "+f"(c[3])
        : "r"(a[0]), "r"(a[1]), "r"(a[2]), "r"(a[3]), "r"(b0), "r"(b1));
}

__device__ __forceinline__ void ldsm4(unsigned& r0, unsigned& r1, unsigned& r2, unsigned& r3,
                                      uint32_t addr) {
    asm volatile("ldmatrix.sync.aligned.m8n8.x4.shared.b16 {%0,%1,%2,%3}, [%4];\n"
                 : "=r"(r0), "=r"(r1), "=r"(r2), "=r"(r3) : "r"(addr));
}

// ---------------------------------------------------------------------------
// Implicit-GEMM 3x3 conv on tensor cores + SRM + fused 2x2 maxpool.
// CTA: M=128 pixels x N=(32*JT) co. 8 warps = 2(M) x 4(N), JT j-tiles per warp.
template<int HW, int CIN, int YROWS, int SHIFT, int JT, bool IS_CONV2>
__global__ void __launch_bounds__(256, 2)
conv_mma(const __nv_bfloat16* __restrict__ Abuf,
         const uint2* __restrict__ Bpk,
         float* __restrict__ vm, float* __restrict__ vs, float* __restrict__ sp,
         __nv_bfloat16* __restrict__ poolb,
         float* __restrict__ p2out)
{
    const int WB = HW + 2, QTOT = WB * WB, KC = CIN / 16;
    const int PITCHE = CIN + 8;              // bf16 units; pitch%32 words == 4
    const int SLABROWS = (YROWS + 2) * WB;
    const int CPR = CIN / 8;
    extern __shared__ __align__(16) unsigned char dsm[];
    __nv_bfloat16* As = (__nv_bfloat16*)dsm;

    int tid = threadIdx.x, lane = tid & 31, wid = tid >> 5;
    int warp_m = wid >> 2, warp_n = wid & 3;
    int b = blockIdx.z;
    int cogBase = blockIdx.y * 32 * JT;
    int y0 = blockIdx.x * YROWS;
    int q0 = y0 * WB;

    for (int i = tid; i < SLABROWS * CPR; i += 256) {
        int rrow = i / CPR, cw = i - rrow * CPR;
        uint4 v = __ldg((const uint4*)(Abuf + ((size_t)b * QTOT + q0 + rrow) * CIN) + cw);
        *(uint4*)(As + rrow * PITCHE + cw * 8) = v;
    }
    __syncthreads();

    // mtile mapping: conv1 interleaves so pool y-pairs are mtiles (l, l+2)
    int mtg[4];
#pragma unroll
    for (int l = 0; l < 4; l++)
        mtg[l] = (YROWS == 2) ? (warp_m * 2 + (l & 1) + ((l & 2) << 1)) : (warp_m * 4 + l);

    // ldmatrix per-lane base addresses (lane&15 = row within mtile, lane>>4 = k half)
    uint32_t smem_u32 = (uint32_t)__cvta_generic_to_shared(As);
    uint32_t abase[4];
#pragma unroll
    for (int l = 0; l < 4; l++) {
        int m = mtg[l] * 16 + (lane & 15);
        int pr = (m >> SHIFT) * WB + (m & (HW - 1));
        abase[l] = smem_u32 + (uint32_t)(pr * PITCHE * 2) + ((lane >> 4) & 1) * 16;
    }

    float acc[4][JT][4];
#pragma unroll
    for (int l = 0; l < 4; l++)
#pragma unroll
        for (int j = 0; j < JT; j++)
#pragma unroll
            for (int c = 0; c < 4; c++) acc[l][j][c] = 0.f;

    int ntb = cogBase / 8 + warp_n * JT;

#pragma unroll 1
    for (int tap = 0; tap < 9; tap++) {
        int ky = tap / 3, kx = tap - ky * 3;
        uint32_t ta[4];
#pragma unroll
        for (int l = 0; l < 4; l++) ta[l] = abase[l] + (uint32_t)((ky * WB + kx) * PITCHE * 2);
#pragma unroll 1
        for (int kc = 0; kc < KC; kc++) {
            unsigned a[4][4];
#pragma unroll
            for (int l = 0; l < 4; l++)
                ldsm4(a[l][0], a[l][1], a[l][2], a[l][3], ta[l] + kc * 32);
            const uint2* bbase = Bpk + (((size_t)(tap * 3) * KC + kc) * 16 + ntb) * 32 + lane;
#pragma unroll
            for (int s = 0; s < 3; s++) {
                uint2 bb[JT];
#pragma unroll
                for (int j = 0; j < JT; j++) bb[j] = __ldg(bbase + (size_t)s * KC * 512 + j * 32);
#pragma unroll
                for (int l = 0; l < 4; l++)
#pragma unroll
                    for (int j = 0; j < JT; j++)
                        mma16816(acc[l][j], a[l], bb[j].x, bb[j].y);
            }
        }
    }

    // Epilogue: SRM + 2x2 maxpool (y-pairs = mtiles l,l+2; x-pairs = lane^4).
#pragma unroll
    for (int lp = 0; lp < 2; lp++) {
#pragma unroll
        for (int o = 0; o < 2; o++) {
            int mA = mtg[lp] * 16 + (lane >> 2) + o * 8;
            int mB = mtg[lp + 2] * 16 + (lane >> 2) + o * 8;
            int yA = y0 + (mA >> SHIFT), xA = mA & (HW - 1);
            int yB = y0 + (mB >> SHIFT);
#pragma unroll
            for (int j = 0; j < JT; j++) {
                int co = cogBase + warp_n * 8 * JT + j * 8 + (lane & 3) * 2;
                size_t iA = ((size_t)(b * HW * HW) + yA * HW + xA) * 128 + co;
                size_t iB = ((size_t)(b * HW * HW) + yB * HW + xA) * 128 + co;
                float sA0, sA1, sB0, sB1;
                srm2(acc[lp][j][o * 2 + 0],     acc[lp][j][o * 2 + 1],     vm, vs, sp, iA, sA0, sA1);
                srm2(acc[lp + 2][j][o * 2 + 0], acc[lp + 2][j][o * 2 + 1], vm, vs, sp, iB, sB0, sB1);
                float xA0 = fmaxf(sA0, __shfl_xor_sync(0xffffffffu, sA0, 4));
                float xA1 = fmaxf(sA1, __shfl_xor_sync(0xffffffffu, sA1, 4));
                float xB0 = fmaxf(sB0, __shfl_xor_sync(0xffffffffu, sB0, 4));
                float xB1 = fmaxf(sB1, __shfl_xor_sync(0xffffffffu, sB1, 4));
                float p0 = fmaxf(xA0, xB0);
                float p1 = fmaxf(xA1, xB1);
                if ((lane & 4) == 0) {
                    int yp = yA >> 1, xp = xA >> 1;
                    if (IS_CONV2) {
                        p2out[(size_t)b * 32768 + co * 256 + yp * 16 + xp] = p0;
                        p2out[(size_t)b * 32768 + (co + 1) * 256 + yp * 16 + xp] = p1;
                    } else {
                        size_t qi = ((size_t)b * 1156 + (yp + 1) * 34 + (xp + 1)) * 128 + co;
                        *reinterpret_cast<__nv_bfloat162*>(poolb + qi) = __floats2bfloat162_rn(p0, p1);
                    }
                }
            }
        }
    }
}

// ---------------------------------------------------------------------------
// fc3 split-K partial GEMM: grid (16 ks, 32 jg), 2 j per warp.
__global__ void __launch_bounds__(256) fc3_partial(const float* __restrict__ W3) {
    extern __shared__ float p2s[];   // [16][2048]
    int ks = blockIdx.x, jg = blockIdx.y;
    int k0 = ks * 2048;
    int tid = threadIdx.x;
    for (int i = tid; i < 16 * 2048; i += 256) {
        int b = i >> 11, k = i & 2047;
        p2s[i] = g_p2[b * 32768 + k0 + k];
    }
    __syncthreads();
    int wj = tid >> 5, lane = tid & 31;
    const float4* ps = reinterpret_cast<const float4*>(p2s);
#pragma unroll
    for (int jj = 0; jj < 2; jj++) {
        int j = jg * 16 + wj * 2 + jj;
        const float4* wr = reinterpret_cast<const float4*>(W3 + (size_t)j * 32768 + k0);
        float acc[16];
#pragma unroll
        for (int b = 0; b < 16; b++) acc[b] = 0.f;
#pragma unroll 1
        for (int kk = lane; kk < 512; kk += 32) {
            float4 w4 = __ldg(wr + kk);
#pragma unroll
            for (int b = 0; b < 16; b++) {
                float4 p = ps[b * 512 + kk];
                acc[b] += w4.x * p.x; acc[b] += w4.y * p.y;
                acc[b] += w4.z * p.z; acc[b] += w4.w * p.w;
            }
        }
#pragma unroll
        for (int b = 0; b < 16; b++) {
            float v = acc[b];
            v += __shfl_down_sync(0xffffffffu, v, 16);
            v += __shfl_down_sync(0xffffffffu, v, 8);
            v += __shfl_down_sync(0xffffffffu, v, 4);
            v += __shfl_down_sync(0xffffffffu, v, 2);
            v += __shfl_down_sync(0xffffffffu, v, 1);
            if (lane == 0) g_part[(ks * 16 + b) * 512 + j] = v;
        }
    }
}

// fc3 SRM + fc4 + SRM + output accumulation, one block of 1024 threads.
__global__ void __launch_bounds__(1024) fc34_srm(const float* __restrict__ W4) {
    __shared__ float s3s[8192];
    int tid = threadIdx.x;
#pragma unroll
    for (int e = 0; e < 8; e++) {
        int i = e * 1024 + tid;
        float I = 0.f;
#pragma unroll
        for (int ks = 0; ks < 16; ks++) I += g_part[ks * 8192 + i];
        s3s[i] = srm_g(I, g_vm3, g_vs3, g_sp3, i);
    }
    __syncthreads();
    if (tid < 176) {
        int b = tid / 11, j = tid % 11;
        const float4* wr = reinterpret_cast<const float4*>(W4 + j * 512);
        const float4* sr = reinterpret_cast<const float4*>(s3s + b * 512);
        float acc = 0.f;
#pragma unroll 4
        for (int k = 0; k < 128; k++) {
            float4 w = __ldg(wr + k), s = sr[k];
            acc += w.x * s.x; acc += w.y * s.y; acc += w.z * s.z; acc += w.w * s.w;
        }
        float sn = srm_g(acc, g_vm4, g_vs4, g_s4, tid);
        g_out[tid] += sn;
    }
}

__global__ void finalize_k(float* __restrict__ out) {
    int i = threadIdx.x;
    if (i < 176) out[i] = g_out[i] * 0.0625f;
}

extern "C" void kernel_launch(void* const* d_in, const int* in_sizes, int n_in,
                              void* d_out, int out_size) {
    (void)in_sizes; (void)n_in; (void)out_size;
    const float* x  = (const float*)d_in[0];
    const float* W0 = (const float*)d_in[1];
    const float* W1 = (const float*)d_in[2];
    const float* W2 = (const float*)d_in[3];
    const float* W3 = (const float*)d_in[4];
    const float* W4 = (const float*)d_in[5];
    float* out = (float*)d_out;

    const int SMEM1 = 264 * 144;   // 38016 B
    const int SMEM2 = 204 * 272;   // 55488 B
    cudaFuncSetAttribute((const void*)conv_mma<64, 64, 2, 6, 4, false>,
                         cudaFuncAttributeMaxDynamicSharedMemorySize, SMEM1);
    cudaFuncSetAttribute((const void*)conv_mma<32, 128, 4, 5, 2, true>,
                         cudaFuncAttributeMaxDynamicSharedMemorySize, SMEM2);
    cudaFuncSetAttribute((const void*)fc3_partial,
                         cudaFuncAttributeMaxDynamicSharedMemorySize, 131072);

    __nv_bfloat16 *s0b, *p1b;
    uint2 *w1pk, *w2pk;
    float *vm1, *vs1, *sp1, *vm2, *vs2, *sp2, *p2;
    cudaGetSymbolAddress((void**)&s0b, g_s0b);
    cudaGetSymbolAddress((void**)&p1b, g_p1b);
    cudaGetSymbolAddress((void**)&w1pk, g_w1pk);
    cudaGetSymbolAddress((void**)&w2pk, g_w2pk);
    cudaGetSymbolAddress((void**)&vm1, g_vm1);
    cudaGetSymbolAddress((void**)&vs1, g_vs1);
    cudaGetSymbolAddress((void**)&sp1, g_sp1);
    cudaGetSymbolAddress((void**)&vm2, g_vm2);
    cudaGetSymbolAddress((void**)&vs2, g_vs2);
    cudaGetSymbolAddress((void**)&sp2, g_sp2);
    cudaGetSymbolAddress((void**)&p2,  g_p2);

    zero_all<<<2048, 256>>>();
    pack_w<<<(NW1PK + 255) / 256, 256>>>(W1, w1pk, 64, NW1PK);
    pack_w<<<(NW2PK + 255) / 256, 256>>>(W2, w2pk, 128, NW2PK);
    for (int t = 0; t < 16; t++) {
        conv0_srm<<<dim3(16, 4, 16), 256>>>(x, W0, t);
        conv_mma<64, 64, 2, 6, 4, false><<<dim3(32, 1, 16), 256, SMEM1>>>(
            s0b, w1pk, vm1, vs1, sp1, p1b, nullptr);
        conv_mma<32, 128, 4, 5, 2, true><<<dim3(8, 2, 16), 256, SMEM2>>>(
            p1b, w2pk, vm2, vs2, sp2, nullptr, p2);
        fc3_partial<<<dim3(16, 32), 256, 131072>>>(W3);
        fc34_srm<<<1, 1024>>>(W4);
    }
    finalize_k<<<1, 256>>>(out);
}

// round 6
// speedup vs baseline: 2.6352x; 1.2365x over previous
#include <cuda_runtime.h>
#include <cuda_bf16.h>
#include <cstdint>

#define DM 0.9394130628134758f   /* exp(-1/16) */
#define DS 0.7788007830714049f   /* exp(-1/4)  */
#define TH 0.3f

#define N_L0 (16*64*64*64)       /* conv0 state, [cog][b][px][16c] */
#define N_L1 (16*64*64*128)      /* conv1 state, NHWC */
#define N_L2 (16*32*32*128)      /* conv2 state, NHWC */
#define N_P2 (16*32768)
#define N_L3 (16*512)
#define N_L4 (16*11)
#define N_PART (16*16*512)

#define SZ_S0B (16*4356*64)      /* s0 spikes, guarded NHWC bf16 (66x66) */
#define SZ_P1B (16*1156*128)     /* p1 pooled spikes, guarded NHWC bf16 (34x34) */
#define NW1PK4 (9*3*4*8*32)      /* conv1 packed B uint4: tap,split,kc,ntpair,lane */
#define NW2PK4 (9*3*8*8*32)

__device__ float g_vm0[N_L0], g_vs0[N_L0];
__device__ float g_vm1[N_L1], g_vs1[N_L1];
__device__ float g_vm2[N_L2], g_vs2[N_L2];
__device__ float g_p2[N_P2];
__device__ float g_vm3[N_L3], g_vs3[N_L3];
__device__ float g_vm4[N_L4], g_vs4[N_L4];
__device__ float g_part[N_PART];
__device__ float g_out[N_L4];
__device__ __nv_bfloat16 g_s0b[SZ_S0B];
__device__ __nv_bfloat16 g_p1b[SZ_P1B];
__device__ uint4 g_w1pk[NW1PK4];
__device__ uint4 g_w2pk[NW2PK4];

// SRM without stored spike: previous spike recomputed from stored vm,vs
// (bit-exact: stored vm,vs are the values the spike was computed from).
__device__ __forceinline__ float srm_ns(float I, float* vm, float* vs, size_t idx) {
    float v = vm[idx], w = vs[idx];
    float k = ((v - w) > TH) ? 0.f : 1.f;
    float a = DM * v * k + I;
    float c = DS * w * k + I;
    float sn = ((a - c) > TH) ? 1.0f : 0.0f;
    vm[idx] = a; vs[idx] = c;
    return sn;
}

__device__ __forceinline__ void srm2_ns(float I0, float I1,
                                        float* vm, float* vs, size_t idx,
                                        float& s0, float& s1) {
    float2 vmv = *(float2*)(vm + idx);
    float2 vsv = *(float2*)(vs + idx);
    float k0 = ((vmv.x - vsv.x) > TH) ? 0.f : 1.f;
    float k1 = ((vmv.y - vsv.y) > TH) ? 0.f : 1.f;
    float a0 = DM * vmv.x * k0 + I0, a1 = DM * vmv.y * k1 + I1;
    float b0 = DS * vsv.x * k0 + I0, b1 = DS * vsv.y * k1 + I1;
    s0 = ((a0 - b0) > TH) ? 1.f : 0.f;
    s1 = ((a1 - b1) > TH) ? 1.f : 0.f;
    *(float2*)(vm + idx) = make_float2(a0, a1);
    *(float2*)(vs + idx) = make_float2(b0, b1);
}

__global__ void zero_all() {
    int stride = gridDim.x * blockDim.x;
    int i0 = blockIdx.x * blockDim.x + threadIdx.x;
    for (int i = i0; i < N_L0; i += stride) { g_vm0[i] = 0.f; g_vs0[i] = 0.f; }
    for (int i = i0; i < N_L1; i += stride) { g_vm1[i] = 0.f; g_vs1[i] = 0.f; }
    for (int i = i0; i < N_L2; i += stride) { g_vm2[i] = 0.f; g_vs2[i] = 0.f; }
    for (int i = i0; i < N_L3; i += stride) { g_vm3[i] = 0.f; g_vs3[i] = 0.f; }
    for (int i = i0; i < N_L4; i += stride) { g_vm4[i] = 0.f; g_vs4[i] = 0.f; g_out[i] = 0.f; }
    unsigned* s0b = (unsigned*)g_s0b;
    for (int i = i0; i < SZ_S0B / 2; i += stride) s0b[i] = 0u;
    unsigned* p1b = (unsigned*)g_p1b;
    for (int i = i0; i < SZ_P1B / 2; i += stride) p1b[i] = 0u;
}

// ---------------------------------------------------------------------------
// Weight prepack: W[co][ci][3][3] fp32 -> mma B-fragments, bf16 3-way split,
// two n-tiles per lane (uint4).
__device__ __forceinline__ unsigned pick_split_pack(float wa, float wb, int split) {
    __nv_bfloat16 ha = __float2bfloat16(wa);
    float ra = wa - __bfloat162float(ha);
    __nv_bfloat16 ma = __float2bfloat16(ra);
    __nv_bfloat16 la = __float2bfloat16(ra - __bfloat162float(ma));
    __nv_bfloat16 hb = __float2bfloat16(wb);
    float rb = wb - __bfloat162float(hb);
    __nv_bfloat16 mb = __float2bfloat16(rb);
    __nv_bfloat16 lb = __float2bfloat16(rb - __bfloat162float(mb));
    __nv_bfloat16 va = (split == 0) ? ha : (split == 1) ? ma : la;
    __nv_bfloat16 vb = (split == 0) ? hb : (split == 1) ? mb : lb;
    unsigned ua = (unsigned)__bfloat16_as_ushort(va);
    unsigned ub = (unsigned)__bfloat16_as_ushort(vb);
    return ua | (ub << 16);
}

__global__ void pack_w(const float* __restrict__ W, uint4* __restrict__ Bpk, int CIN, int total) {
    int idx = blockIdx.x * 256 + threadIdx.x;
    if (idx >= total) return;
    int KC = CIN / 16;
    int lane = idx & 31;
    int p = (idx >> 5) & 7;            // n-tile pair
    int rest = idx >> 8;
    int kc = rest % KC; rest /= KC;
    int split = rest % 3; int tap = rest / 3;
    int ky = tap / 3, kx = tap % 3;
    int k0 = kc * 16 + (lane & 3) * 2;
    int n0 = (2 * p) * 8 + (lane >> 2);
    int n1 = n0 + 8;
    uint4 v;
    {
        float w0 = W[((size_t)(n0 * CIN + k0 + 0) * 3 + ky) * 3 + kx];
        float w1 = W[((size_t)(n0 * CIN + k0 + 1) * 3 + ky) * 3 + kx];
        float w8 = W[((size_t)(n0 * CIN + k0 + 8) * 3 + ky) * 3 + kx];
        float w9 = W[((size_t)(n0 * CIN + k0 + 9) * 3 + ky) * 3 + kx];
        v.x = pick_split_pack(w0, w1, split);
        v.y = pick_split_pack(w8, w9, split);
    }
    {
        float w0 = W[((size_t)(n1 * CIN + k0 + 0) * 3 + ky) * 3 + kx];
        float w1 = W[((size_t)(n1 * CIN + k0 + 1) * 3 + ky) * 3 + kx];
        float w8 = W[((size_t)(n1 * CIN + k0 + 8) * 3 + ky) * 3 + kx];
        float w9 = W[((size_t)(n1 * CIN + k0 + 9) * 3 + ky) * 3 + kx];
        v.z = pick_split_pack(w0, w1, split);
        v.w = pick_split_pack(w8, w9, split);
    }
    Bpk[idx] = v;
}

// ---------------------------------------------------------------------------
// conv0: 2->64 on 64x64. grid (16 tiles, 4 cog, 16 b), 1 px x 16 co per thread.
// State layout [cog][b][y][x][16c] (tile rows are globally contiguous) so the
// epilogue — after an smem acc remap — does perfectly coalesced float4 r/w.
__global__ void __launch_bounds__(256)
conv0_srm(const float* __restrict__ x, const float* __restrict__ W0, int t) {
    __shared__ float ins[2 * 360];        // [2ci][18 rows][20 cols pad]
    __shared__ float ws[16 * 2 * 12];     // [16co][2ci][12 pad]
    __shared__ float sacc[256 * 17];      // [px 16x16][17 pad]
    int tid = threadIdx.x;
    int b = blockIdx.z;
    int cog = blockIdx.y;
    int tX = blockIdx.x & 3, tY = blockIdx.x >> 2;
    int x0 = tX * 16, y0 = tY * 16;

    const float* xb = x + ((size_t)(b * 16 + t)) * 2 * 4096;
    for (int i = tid; i < 2 * 324; i += 256) {
        int ci = i / 324; int r = i - ci * 324;
        int y = r / 18;   int xq = r - y * 18;
        int gy = y0 + y - 1, gx = x0 + xq - 1;
        float v = 0.f;
        if ((unsigned)gy < 64u && (unsigned)gx < 64u) {
            v = __ldg(xb + ci * 4096 + gy * 64 + gx);
            v = fminf(fmaxf(v, 0.f), 1.f);
        }
        ins[ci * 360 + y * 20 + xq] = v;
    }
    for (int i = tid; i < 16 * 18; i += 256) {
        int col = i / 18; int r = i - col * 18;
        int ci = r / 9;   int k = r - ci * 9;
        ws[(col * 2 + ci) * 12 + k] = __ldg(W0 + ((size_t)(cog * 16 + col) * 2 + ci) * 9 + k);
    }
    __syncthreads();

    int ty = tid >> 4, tx = tid & 15;
    float acc[16];
#pragma unroll
    for (int j = 0; j < 16; j++) acc[j] = 0.f;

#pragma unroll
    for (int ci = 0; ci < 2; ci++) {
        const float* ip = ins + ci * 360 + ty * 20 + tx;
        float iv[3][3];
#pragma unroll
        for (int yy = 0; yy < 3; yy++)
#pragma unroll
            for (int xx = 0; xx < 3; xx++) iv[yy][xx] = ip[yy * 20 + xx];
#pragma unroll
        for (int j = 0; j < 16; j++) {
            const float* wb = ws + (j * 2 + ci) * 12;
            float4 wA = *reinterpret_cast<const float4*>(wb);
            float4 wB = *reinterpret_cast<const float4*>(wb + 4);
            float  w8 = wb[8];
            float s = acc[j];
            s += iv[0][0] * wA.x; s += iv[0][1] * wA.y; s += iv[0][2] * wA.z;
            s += iv[1][0] * wA.w; s += iv[1][1] * wB.x; s += iv[1][2] * wB.y;
            s += iv[2][0] * wB.z; s += iv[2][1] * wB.w; s += iv[2][2] * w8;
            acc[j] = s;
        }
    }

    // remap acc through smem (pad 17 -> conflict-free writes)
#pragma unroll
    for (int c = 0; c < 16; c++) sacc[(ty * 16 + tx) * 17 + c] = acc[c];
    __syncthreads();

    // state update: 1024 float4 groups, 4 per thread, lane-consecutive global access
#pragma unroll
    for (int q = 0; q < 4; q++) {
        int f = q * 256 + tid;            // float4 index in tile
        int yl = f >> 6;                  // row 0..15
        int fi = f & 63;                  // float4 within row
        int xl = fi >> 2, cq = fi & 3;
        size_t rowb = (((size_t)(cog * 16 + b) * 4096) + (y0 + yl) * 64 + x0) * 16;
        float4 vmv = *(float4*)(g_vm0 + rowb + fi * 4);
        float4 vsv = *(float4*)(g_vs0 + rowb + fi * 4);
        const float* sp = sacc + (yl * 16 + xl) * 17 + cq * 4;
        float I0 = sp[0], I1 = sp[1], I2 = sp[2], I3 = sp[3];
        float k0 = ((vmv.x - vsv.x) > TH) ? 0.f : 1.f;
        float k1 = ((vmv.y - vsv.y) > TH) ? 0.f : 1.f;
        float k2 = ((vmv.z - vsv.z) > TH) ? 0.f : 1.f;
        float k3 = ((vmv.w - vsv.w) > TH) ? 0.f : 1.f;
        float a0 = DM * vmv.x * k0 + I0, a1 = DM * vmv.y * k1 + I1;
        float a2 = DM * vmv.z * k2 + I2, a3 = DM * vmv.w * k3 + I3;
        float c0 = DS * vsv.x * k0 + I0, c1 = DS * vsv.y * k1 + I1;
        float c2 = DS * vsv.z * k2 + I2, c3 = DS * vsv.w * k3 + I3;
        float s0 = ((a0 - c0) > TH) ? 1.f : 0.f;
        float s1 = ((a1 - c1) > TH) ? 1.f : 0.f;
        float s2 = ((a2 - c2) > TH) ? 1.f : 0.f;
        float s3 = ((a3 - c3) > TH) ? 1.f : 0.f;
        *(float4*)(g_vm0 + rowb + fi * 4) = make_float4(a0, a1, a2, a3);
        *(float4*)(g_vs0 + rowb + fi * 4) = make_float4(c0, c1, c2, c3);
        int gy = y0 + yl, gx = x0 + xl;
        size_t qi = ((size_t)b * 4356 + (gy + 1) * 66 + (gx + 1)) * 64 + cog * 16 + cq * 4;
        *(__nv_bfloat162*)(g_s0b + qi)     = __floats2bfloat162_rn(s0, s1);
        *(__nv_bfloat162*)(g_s0b + qi + 2) = __floats2bfloat162_rn(s2, s3);
    }
}

// ---------------------------------------------------------------------------
__device__ __forceinline__ void mma16816(float* c, const unsigned* a, unsigned b0, unsigned b1) {
    asm volatile(
        "mma.sync.aligned.m16n8k16.row.col.f32.bf16.bf16.f32 "
        "{%0,%1,%2,%3}, {%4,%5,%6,%7}, {%8,%9}, {%0,%1,%2,%3};\n"
        : "+f"(c[0]), "+f"(c[1]), "+f"(c[2]), "+f"(c[3])
        : "r"(a[0]), "r"(a[1]), "r"(a[2]), "r"(a[3]), "r"(b0), "r"(b1));
}

__device__ __forceinline__ void ldsm4(unsigned& r0, unsigned& r1, unsigned& r2, unsigned& r3,
                                      uint32_t addr) {
    asm volatile("ldmatrix.sync.aligned.m8n8.x4.shared.b16 {%0,%1,%2,%3}, [%4];\n"
                 : "=r"(r0), "=r"(r1), "=r"(r2), "=r"(r3) : "r"(addr));
}

// ---------------------------------------------------------------------------
// Implicit-GEMM 3x3 conv on tensor cores + SRM + fused 2x2 maxpool.
// CTA: M=128 pixels x N=(32*JT) co. 8 warps = 2(M) x 4(N), JT j-tiles per warp.
template<int HW, int CIN, int YROWS, int SHIFT, int JT, bool IS_CONV2>
__global__ void __launch_bounds__(256, 2)
conv_mma(const __nv_bfloat16* __restrict__ Abuf,
         const uint4* __restrict__ Bpk,
         float* __restrict__ vm, float* __restrict__ vs,
         __nv_bfloat16* __restrict__ poolb,
         float* __restrict__ p2out)
{
    const int WB = HW + 2, QTOT = WB * WB, KC = CIN / 16;
    const int PITCHE = CIN + 8;              // bf16 units; pitch%32 words == 4
    const int SLABROWS = (YROWS + 2) * WB;
    const int CPR = CIN / 8;
    const int JP = JT / 2;
    extern __shared__ __align__(16) unsigned char dsm[];
    __nv_bfloat16* As = (__nv_bfloat16*)dsm;

    int tid = threadIdx.x, lane = tid & 31, wid = tid >> 5;
    int warp_m = wid >> 2, warp_n = wid & 3;
    int b = blockIdx.z;
    int cogBase = blockIdx.y * 32 * JT;
    int y0 = blockIdx.x * YROWS;
    int q0 = y0 * WB;

    for (int i = tid; i < SLABROWS * CPR; i += 256) {
        int rrow = i / CPR, cw = i - rrow * CPR;
        uint4 v = __ldg((const uint4*)(Abuf + ((size_t)b * QTOT + q0 + rrow) * CIN) + cw);
        *(uint4*)(As + rrow * PITCHE + cw * 8) = v;
    }
    __syncthreads();

    int mtg[4];
#pragma unroll
    for (int l = 0; l < 4; l++)
        mtg[l] = (YROWS == 2) ? (warp_m * 2 + (l & 1) + ((l & 2) << 1)) : (warp_m * 4 + l);

    uint32_t smem_u32 = (uint32_t)__cvta_generic_to_shared(As);
    uint32_t abase[4];
#pragma unroll
    for (int l = 0; l < 4; l++) {
        int m = mtg[l] * 16 + (lane & 15);
        int pr = (m >> SHIFT) * WB + (m & (HW - 1));
        abase[l] = smem_u32 + (uint32_t)(pr * PITCHE * 2) + ((lane >> 4) & 1) * 16;
    }

    float acc[4][JT][4];
#pragma unroll
    for (int l = 0; l < 4; l++)
#pragma unroll
        for (int j = 0; j < JT; j++)
#pragma unroll
            for (int c = 0; c < 4; c++) acc[l][j][c] = 0.f;

    int ntp = cogBase / 16 + warp_n * JP;

#pragma unroll 1
    for (int tap = 0; tap < 9; tap++) {
        int ky = tap / 3, kx = tap - ky * 3;
        uint32_t ta[4];
#pragma unroll
        for (int l = 0; l < 4; l++) ta[l] = abase[l] + (uint32_t)((ky * WB + kx) * PITCHE * 2);
#pragma unroll 1
        for (int kc = 0; kc < KC; kc++) {
            unsigned a[4][4];
#pragma unroll
            for (int l = 0; l < 4; l++)
                ldsm4(a[l][0], a[l][1], a[l][2], a[l][3], ta[l] + kc * 32);
#pragma unroll
            for (int s = 0; s < 3; s++) {
                uint4 bb[JP];
#pragma unroll
                for (int jp = 0; jp < JP; jp++)
                    bb[jp] = __ldg(Bpk + ((((size_t)(tap * 3 + s) * KC + kc) * 8) + ntp + jp) * 32 + lane);
#pragma unroll
                for (int l = 0; l < 4; l++)
#pragma unroll
                    for (int jp = 0; jp < JP; jp++) {
                        mma16816(acc[l][2 * jp + 0], a[l], bb[jp].x, bb[jp].y);
                        mma16816(acc[l][2 * jp + 1], a[l], bb[jp].z, bb[jp].w);
                    }
            }
        }
    }

    // Epilogue: SRM + 2x2 maxpool (y-pairs = mtiles l,l+2; x-pairs = lane^4).
#pragma unroll
    for (int lp = 0; lp < 2; lp++) {
#pragma unroll
        for (int o = 0; o < 2; o++) {
            int mA = mtg[lp] * 16 + (lane >> 2) + o * 8;
            int mB = mtg[lp + 2] * 16 + (lane >> 2) + o * 8;
            int yA = y0 + (mA >> SHIFT), xA = mA & (HW - 1);
            int yB = y0 + (mB >> SHIFT);
#pragma unroll
            for (int j = 0; j < JT; j++) {
                int co = cogBase + warp_n * 8 * JT + j * 8 + (lane & 3) * 2;
                size_t iA = ((size_t)(b * HW * HW) + yA * HW + xA) * 128 + co;
                size_t iB = ((size_t)(b * HW * HW) + yB * HW + xA) * 128 + co;
                float sA0, sA1, sB0, sB1;
                srm2_ns(acc[lp][j][o * 2 + 0],     acc[lp][j][o * 2 + 1],     vm, vs, iA, sA0, sA1);
                srm2_ns(acc[lp + 2][j][o * 2 + 0], acc[lp + 2][j][o * 2 + 1], vm, vs, iB, sB0, sB1);
                float xA0 = fmaxf(sA0, __shfl_xor_sync(0xffffffffu, sA0, 4));
                float xA1 = fmaxf(sA1, __shfl_xor_sync(0xffffffffu, sA1, 4));
                float xB0 = fmaxf(sB0, __shfl_xor_sync(0xffffffffu, sB0, 4));
                float xB1 = fmaxf(sB1, __shfl_xor_sync(0xffffffffu, sB1, 4));
                float p0 = fmaxf(xA0, xB0);
                float p1 = fmaxf(xA1, xB1);
                if ((lane & 4) == 0) {
                    int yp = yA >> 1, xp = xA >> 1;
                    if (IS_CONV2) {
                        p2out[(size_t)b * 32768 + co * 256 + yp * 16 + xp] = p0;
                        p2out[(size_t)b * 32768 + (co + 1) * 256 + yp * 16 + xp] = p1;
                    } else {
                        size_t qi = ((size_t)b * 1156 + (yp + 1) * 34 + (xp + 1)) * 128 + co;
                        *reinterpret_cast<__nv_bfloat162*>(poolb + qi) = __floats2bfloat162_rn(p0, p1);
                    }
                }
            }
        }
    }
}

// ---------------------------------------------------------------------------
// fc3 split-K partial GEMM: grid (16 ks, 32 jg), 2 j per warp.
__global__ void __launch_bounds__(256) fc3_partial(const float* __restrict__ W3) {
    extern __shared__ float p2s[];   // [16][2048]
    int ks = blockIdx.x, jg = blockIdx.y;
    int k0 = ks * 2048;
    int tid = threadIdx.x;
    for (int i = tid; i < 16 * 2048; i += 256) {
        int b = i >> 11, k = i & 2047;
        p2s[i] = g_p2[b * 32768 + k0 + k];
    }
    __syncthreads();
    int wj = tid >> 5, lane = tid & 31;
    const float4* ps = reinterpret_cast<const float4*>(p2s);
#pragma unroll
    for (int jj = 0; jj < 2; jj++) {
        int j = jg * 16 + wj * 2 + jj;
        const float4* wr = reinterpret_cast<const float4*>(W3 + (size_t)j * 32768 + k0);
        float acc[16];
#pragma unroll
        for (int b = 0; b < 16; b++) acc[b] = 0.f;
#pragma unroll 1
        for (int kk = lane; kk < 512; kk += 32) {
            float4 w4 = __ldg(wr + kk);
#pragma unroll
            for (int b = 0; b < 16; b++) {
                float4 p = ps[b * 512 + kk];
                acc[b] += w4.x * p.x; acc[b] += w4.y * p.y;
                acc[b] += w4.z * p.z; acc[b] += w4.w * p.w;
            }
        }
#pragma unroll
        for (int b = 0; b < 16; b++) {
            float v = acc[b];
            v += __shfl_down_sync(0xffffffffu, v, 16);
            v += __shfl_down_sync(0xffffffffu, v, 8);
            v += __shfl_down_sync(0xffffffffu, v, 4);
            v += __shfl_down_sync(0xffffffffu, v, 2);
            v += __shfl_down_sync(0xffffffffu, v, 1);
            if (lane == 0) g_part[(ks * 16 + b) * 512 + j] = v;
        }
    }
}

// fc3 SRM + fc4 + SRM + output accumulation, one block of 1024 threads.
__global__ void __launch_bounds__(1024) fc34_srm(const float* __restrict__ W4) {
    __shared__ float s3s[8192];
    int tid = threadIdx.x;
#pragma unroll
    for (int e = 0; e < 8; e++) {
        int i = e * 1024 + tid;
        float I = 0.f;
#pragma unroll
        for (int ks = 0; ks < 16; ks++) I += g_part[ks * 8192 + i];
        s3s[i] = srm_ns(I, g_vm3, g_vs3, i);
    }
    __syncthreads();
    if (tid < 176) {
        int b = tid / 11, j = tid % 11;
        const float4* wr = reinterpret_cast<const float4*>(W4 + j * 512);
        const float4* sr = reinterpret_cast<const float4*>(s3s + b * 512);
        float acc = 0.f;
#pragma unroll 4
        for (int k = 0; k < 128; k++) {
            float4 w = __ldg(wr + k), s = sr[k];
            acc += w.x * s.x; acc += w.y * s.y; acc += w.z * s.z; acc += w.w * s.w;
        }
        float sn = srm_ns(acc, g_vm4, g_vs4, tid);
        g_out[tid] += sn;
    }
}

__global__ void finalize_k(float* __restrict__ out) {
    int i = threadIdx.x;
    if (i < 176) out[i] = g_out[i] * 0.0625f;
}

extern "C" void kernel_launch(void* const* d_in, const int* in_sizes, int n_in,
                              void* d_out, int out_size) {
    (void)in_sizes; (void)n_in; (void)out_size;
    const float* x  = (const float*)d_in[0];
    const float* W0 = (const float*)d_in[1];
    const float* W1 = (const float*)d_in[2];
    const float* W2 = (const float*)d_in[3];
    const float* W3 = (const float*)d_in[4];
    const float* W4 = (const float*)d_in[5];
    float* out = (float*)d_out;

    const int SMEM1 = 264 * 144;   // 38016 B
    const int SMEM2 = 204 * 272;   // 55488 B
    cudaFuncSetAttribute((const void*)conv_mma<64, 64, 2, 6, 4, false>,
                         cudaFuncAttributeMaxDynamicSharedMemorySize, SMEM1);
    cudaFuncSetAttribute((const void*)conv_mma<32, 128, 4, 5, 2, true>,
                         cudaFuncAttributeMaxDynamicSharedMemorySize, SMEM2);
    cudaFuncSetAttribute((const void*)fc3_partial,
                         cudaFuncAttributeMaxDynamicSharedMemorySize, 131072);

    __nv_bfloat16 *s0b, *p1b;
    uint4 *w1pk, *w2pk;
    float *vm1, *vs1, *vm2, *vs2, *p2;
    cudaGetSymbolAddress((void**)&s0b, g_s0b);
    cudaGetSymbolAddress((void**)&p1b, g_p1b);
    cudaGetSymbolAddress((void**)&w1pk, g_w1pk);
    cudaGetSymbolAddress((void**)&w2pk, g_w2pk);
    cudaGetSymbolAddress((void**)&vm1, g_vm1);
    cudaGetSymbolAddress((void**)&vs1, g_vs1);
    cudaGetSymbolAddress((void**)&vm2, g_vm2);
    cudaGetSymbolAddress((void**)&vs2, g_vs2);
    cudaGetSymbolAddress((void**)&p2,  g_p2);

    zero_all<<<2048, 256>>>();
    pack_w<<<(NW1PK4 + 255) / 256, 256>>>(W1, w1pk, 64, NW1PK4);
    pack_w<<<(NW2PK4 + 255) / 256, 256>>>(W2, w2pk, 128, NW2PK4);
    for (int t = 0; t < 16; t++) {
        conv0_srm<<<dim3(16, 4, 16), 256>>>(x, W0, t);
        conv_mma<64, 64, 2, 6, 4, false><<<dim3(32, 1, 16), 256, SMEM1>>>(
            s0b, w1pk, vm1, vs1, p1b, nullptr);
        conv_mma<32, 128, 4, 5, 2, true><<<dim3(8, 2, 16), 256, SMEM2>>>(
            p1b, w2pk, vm2, vs2, nullptr, p2);
        fc3_partial<<<dim3(16, 32), 256, 131072>>>(W3);
        fc34_srm<<<1, 1024>>>(W4);
    }
    finalize_k<<<1, 256>>>(out);
}

// round 7
// speedup vs baseline: 3.2273x; 1.2247x over previous
#include <cuda_runtime.h>
#include <cuda_bf16.h>
#include <cstdint>

#define DM 0.9394130628134758f   /* exp(-1/16) */
#define DS 0.7788007830714049f   /* exp(-1/4)  */
#define TH 0.3f

#define N_L0 (16*64*64*64)       /* conv0 state, [cog][b][px][16c] */
#define N_L1 (16*64*64*128)      /* conv1 state, NHWC */
#define N_L2 (16*32*32*128)      /* conv2 state, NHWC */
#define N_P2 (16*32768)
#define N_L3 (16*512)
#define N_L4 (16*11)
#define N_PART (16*16*512)

#define SZ_S0B (16*4356*64)      /* s0 spikes, guarded NHWC bf16 (66x66) */
#define SZ_P1B (16*1156*128)     /* p1 pooled spikes, guarded NHWC bf16 (34x34) */
#define NW1PK4 (9*3*4*8*32)      /* conv1 packed B uint4: tap,split,kc,ntpair,lane */
#define NW2PK4 (9*3*8*8*32)

__device__ float g_vm0[N_L0], g_vs0[N_L0];
__device__ float g_vm1[N_L1], g_vs1[N_L1];
__device__ float g_vm2[N_L2], g_vs2[N_L2];
__device__ float g_vm3[N_L3], g_vs3[N_L3];
__device__ float g_vm4[N_L4], g_vs4[N_L4];
__device__ float g_part[N_PART];
__device__ float g_out[N_L4];
__device__ __nv_bfloat16 g_s0b[SZ_S0B];
__device__ __nv_bfloat16 g_p1b[SZ_P1B];
__device__ __nv_bfloat16 g_p2b[N_P2];    /* p2 pooled spikes, binary -> bf16 exact */
__device__ uint4 g_w1pk[NW1PK4];
__device__ uint4 g_w2pk[NW2PK4];

// SRM without stored spike: previous spike recomputed from stored vm,vs
// (bit-exact: stored vm,vs are the values the spike was computed from).
__device__ __forceinline__ float srm_ns(float I, float* vm, float* vs, size_t idx) {
    float v = vm[idx], w = vs[idx];
    float k = ((v - w) > TH) ? 0.f : 1.f;
    float a = DM * v * k + I;
    float c = DS * w * k + I;
    float sn = ((a - c) > TH) ? 1.0f : 0.0f;
    vm[idx] = a; vs[idx] = c;
    return sn;
}

__device__ __forceinline__ void srm2_ns(float I0, float I1,
                                        float* vm, float* vs, size_t idx,
                                        float& s0, float& s1) {
    float2 vmv = *(float2*)(vm + idx);
    float2 vsv = *(float2*)(vs + idx);
    float k0 = ((vmv.x - vsv.x) > TH) ? 0.f : 1.f;
    float k1 = ((vmv.y - vsv.y) > TH) ? 0.f : 1.f;
    float a0 = DM * vmv.x * k0 + I0, a1 = DM * vmv.y * k1 + I1;
    float b0 = DS * vsv.x * k0 + I0, b1 = DS * vsv.y * k1 + I1;
    s0 = ((a0 - b0) > TH) ? 1.f : 0.f;
    s1 = ((a1 - b1) > TH) ? 1.f : 0.f;
    *(float2*)(vm + idx) = make_float2(a0, a1);
    *(float2*)(vs + idx) = make_float2(b0, b1);
}

__global__ void zero_all() {
    int stride = gridDim.x * blockDim.x;
    int i0 = blockIdx.x * blockDim.x + threadIdx.x;
    for (int i = i0; i < N_L0; i += stride) { g_vm0[i] = 0.f; g_vs0[i] = 0.f; }
    for (int i = i0; i < N_L1; i += stride) { g_vm1[i] = 0.f; g_vs1[i] = 0.f; }
    for (int i = i0; i < N_L2; i += stride) { g_vm2[i] = 0.f; g_vs2[i] = 0.f; }
    for (int i = i0; i < N_L3; i += stride) { g_vm3[i] = 0.f; g_vs3[i] = 0.f; }
    for (int i = i0; i < N_L4; i += stride) { g_vm4[i] = 0.f; g_vs4[i] = 0.f; g_out[i] = 0.f; }
    unsigned* s0b = (unsigned*)g_s0b;
    for (int i = i0; i < SZ_S0B / 2; i += stride) s0b[i] = 0u;
    unsigned* p1b = (unsigned*)g_p1b;
    for (int i = i0; i < SZ_P1B / 2; i += stride) p1b[i] = 0u;
}

// ---------------------------------------------------------------------------
// Weight prepack: W[co][ci][3][3] fp32 -> mma B-fragments, bf16 3-way split,
// two n-tiles per lane (uint4).
__device__ __forceinline__ unsigned pick_split_pack(float wa, float wb, int split) {
    __nv_bfloat16 ha = __float2bfloat16(wa);
    float ra = wa - __bfloat162float(ha);
    __nv_bfloat16 ma = __float2bfloat16(ra);
    __nv_bfloat16 la = __float2bfloat16(ra - __bfloat162float(ma));
    __nv_bfloat16 hb = __float2bfloat16(wb);
    float rb = wb - __bfloat162float(hb);
    __nv_bfloat16 mb = __float2bfloat16(rb);
    __nv_bfloat16 lb = __float2bfloat16(rb - __bfloat162float(mb));
    __nv_bfloat16 va = (split == 0) ? ha : (split == 1) ? ma : la;
    __nv_bfloat16 vb = (split == 0) ? hb : (split == 1) ? mb : lb;
    unsigned ua = (unsigned)__bfloat16_as_ushort(va);
    unsigned ub = (unsigned)__bfloat16_as_ushort(vb);
    return ua | (ub << 16);
}

__global__ void pack_w(const float* __restrict__ W, uint4* __restrict__ Bpk, int CIN, int total) {
    int idx = blockIdx.x * 256 + threadIdx.x;
    if (idx >= total) return;
    int KC = CIN / 16;
    int lane = idx & 31;
    int p = (idx >> 5) & 7;            // n-tile pair
    int rest = idx >> 8;
    int kc = rest % KC; rest /= KC;
    int split = rest % 3; int tap = rest / 3;
    int ky = tap / 3, kx = tap % 3;
    int k0 = kc * 16 + (lane & 3) * 2;
    int n0 = (2 * p) * 8 + (lane >> 2);
    int n1 = n0 + 8;
    uint4 v;
    {
        float w0 = W[((size_t)(n0 * CIN + k0 + 0) * 3 + ky) * 3 + kx];
        float w1 = W[((size_t)(n0 * CIN + k0 + 1) * 3 + ky) * 3 + kx];
        float w8 = W[((size_t)(n0 * CIN + k0 + 8) * 3 + ky) * 3 + kx];
        float w9 = W[((size_t)(n0 * CIN + k0 + 9) * 3 + ky) * 3 + kx];
        v.x = pick_split_pack(w0, w1, split);
        v.y = pick_split_pack(w8, w9, split);
    }
    {
        float w0 = W[((size_t)(n1 * CIN + k0 + 0) * 3 + ky) * 3 + kx];
        float w1 = W[((size_t)(n1 * CIN + k0 + 1) * 3 + ky) * 3 + kx];
        float w8 = W[((size_t)(n1 * CIN + k0 + 8) * 3 + ky) * 3 + kx];
        float w9 = W[((size_t)(n1 * CIN + k0 + 9) * 3 + ky) * 3 + kx];
        v.z = pick_split_pack(w0, w1, split);
        v.w = pick_split_pack(w8, w9, split);
    }
    Bpk[idx] = v;
}

// ---------------------------------------------------------------------------
// conv0: 2->64 on 64x64. grid (16 tiles, 4 cog, 16 b), 1 px x 16 co per thread.
// State layout [cog][b][y][x][16c]; epilogue remaps acc via smem so all global
// state r/w are lane-consecutive float4.
__global__ void __launch_bounds__(256)
conv0_srm(const float* __restrict__ x, const float* __restrict__ W0, int t) {
    __shared__ float ins[2 * 360];
    __shared__ float ws[16 * 2 * 12];
    __shared__ float sacc[256 * 17];
    int tid = threadIdx.x;
    int b = blockIdx.z;
    int cog = blockIdx.y;
    int tX = blockIdx.x & 3, tY = blockIdx.x >> 2;
    int x0 = tX * 16, y0 = tY * 16;

    const float* xb = x + ((size_t)(b * 16 + t)) * 2 * 4096;
    for (int i = tid; i < 2 * 324; i += 256) {
        int ci = i / 324; int r = i - ci * 324;
        int y = r / 18;   int xq = r - y * 18;
        int gy = y0 + y - 1, gx = x0 + xq - 1;
        float v = 0.f;
        if ((unsigned)gy < 64u && (unsigned)gx < 64u) {
            v = __ldg(xb + ci * 4096 + gy * 64 + gx);
            v = fminf(fmaxf(v, 0.f), 1.f);
        }
        ins[ci * 360 + y * 20 + xq] = v;
    }
    for (int i = tid; i < 16 * 18; i += 256) {
        int col = i / 18; int r = i - col * 18;
        int ci = r / 9;   int k = r - ci * 9;
        ws[(col * 2 + ci) * 12 + k] = __ldg(W0 + ((size_t)(cog * 16 + col) * 2 + ci) * 9 + k);
    }
    __syncthreads();

    int ty = tid >> 4, tx = tid & 15;
    float acc[16];
#pragma unroll
    for (int j = 0; j < 16; j++) acc[j] = 0.f;

#pragma unroll
    for (int ci = 0; ci < 2; ci++) {
        const float* ip = ins + ci * 360 + ty * 20 + tx;
        float iv[3][3];
#pragma unroll
        for (int yy = 0; yy < 3; yy++)
#pragma unroll
            for (int xx = 0; xx < 3; xx++) iv[yy][xx] = ip[yy * 20 + xx];
#pragma unroll
        for (int j = 0; j < 16; j++) {
            const float* wb = ws + (j * 2 + ci) * 12;
            float4 wA = *reinterpret_cast<const float4*>(wb);
            float4 wB = *reinterpret_cast<const float4*>(wb + 4);
            float  w8 = wb[8];
            float s = acc[j];
            s += iv[0][0] * wA.x; s += iv[0][1] * wA.y; s += iv[0][2] * wA.z;
            s += iv[1][0] * wA.w; s += iv[1][1] * wB.x; s += iv[1][2] * wB.y;
            s += iv[2][0] * wB.z; s += iv[2][1] * wB.w; s += iv[2][2] * w8;
            acc[j] = s;
        }
    }

#pragma unroll
    for (int c = 0; c < 16; c++) sacc[(ty * 16 + tx) * 17 + c] = acc[c];
    __syncthreads();

#pragma unroll
    for (int q = 0; q < 4; q++) {
        int f = q * 256 + tid;
        int yl = f >> 6;
        int fi = f & 63;
        int xl = fi >> 2, cq = fi & 3;
        size_t rowb = (((size_t)(cog * 16 + b) * 4096) + (y0 + yl) * 64 + x0) * 16;
        float4 vmv = *(float4*)(g_vm0 + rowb + fi * 4);
        float4 vsv = *(float4*)(g_vs0 + rowb + fi * 4);
        const float* sp = sacc + (yl * 16 + xl) * 17 + cq * 4;
        float I0 = sp[0], I1 = sp[1], I2 = sp[2], I3 = sp[3];
        float k0 = ((vmv.x - vsv.x) > TH) ? 0.f : 1.f;
        float k1 = ((vmv.y - vsv.y) > TH) ? 0.f : 1.f;
        float k2 = ((vmv.z - vsv.z) > TH) ? 0.f : 1.f;
        float k3 = ((vmv.w - vsv.w) > TH) ? 0.f : 1.f;
        float a0 = DM * vmv.x * k0 + I0, a1 = DM * vmv.y * k1 + I1;
        float a2 = DM * vmv.z * k2 + I2, a3 = DM * vmv.w * k3 + I3;
        float c0 = DS * vsv.x * k0 + I0, c1 = DS * vsv.y * k1 + I1;
        float c2 = DS * vsv.z * k2 + I2, c3 = DS * vsv.w * k3 + I3;
        float s0 = ((a0 - c0) > TH) ? 1.f : 0.f;
        float s1 = ((a1 - c1) > TH) ? 1.f : 0.f;
        float s2 = ((a2 - c2) > TH) ? 1.f : 0.f;
        float s3 = ((a3 - c3) > TH) ? 1.f : 0.f;
        *(float4*)(g_vm0 + rowb + fi * 4) = make_float4(a0, a1, a2, a3);
        *(float4*)(g_vs0 + rowb + fi * 4) = make_float4(c0, c1, c2, c3);
        int gy = y0 + yl, gx = x0 + xl;
        size_t qi = ((size_t)b * 4356 + (gy + 1) * 66 + (gx + 1)) * 64 + cog * 16 + cq * 4;
        *(__nv_bfloat162*)(g_s0b + qi)     = __floats2bfloat162_rn(s0, s1);
        *(__nv_bfloat162*)(g_s0b + qi + 2) = __floats2bfloat162_rn(s2, s3);
    }
}

// ---------------------------------------------------------------------------
__device__ __forceinline__ void mma16816(float* c, const unsigned* a, unsigned b0, unsigned b1) {
    asm volatile(
        "mma.sync.aligned.m16n8k16.row.col.f32.bf16.bf16.f32 "
        "{%0,%1,%2,%3}, {%4,%5,%6,%7}, {%8,%9}, {%0,%1,%2,%3};\n"
        : "+f"(c[0]), "+f"(c[1]), "+f"(c[2]), "+f"(c[3])
        : "r"(a[0]), "r"(a[1]), "r"(a[2]), "r"(a[3]), "r"(b0), "r"(b1));
}

__device__ __forceinline__ void ldsm4(unsigned& r0, unsigned& r1, unsigned& r2, unsigned& r3,
                                      uint32_t addr) {
    asm volatile("ldmatrix.sync.aligned.m8n8.x4.shared.b16 {%0,%1,%2,%3}, [%4];\n"
                 : "=r"(r0), "=r"(r1), "=r"(r2), "=r"(r3) : "r"(addr));
}

// ---------------------------------------------------------------------------
// Implicit-GEMM 3x3 conv on tensor cores + SRM + fused 2x2 maxpool.
// kc loop fully unrolled; B pointer strength-reduced to static offsets.
template<int HW, int CIN, int YROWS, int SHIFT, int JT, bool IS_CONV2>
__global__ void __launch_bounds__(256, 2)
conv_mma(const __nv_bfloat16* __restrict__ Abuf,
         const uint4* __restrict__ Bpk,
         float* __restrict__ vm, float* __restrict__ vs,
         __nv_bfloat16* __restrict__ poolb,
         __nv_bfloat16* __restrict__ p2out)
{
    const int WB = HW + 2, QTOT = WB * WB, KC = CIN / 16;
    const int PITCHE = CIN + 8;
    const int SLABROWS = (YROWS + 2) * WB;
    const int CPR = CIN / 8;
    const int JP = JT / 2;
    extern __shared__ __align__(16) unsigned char dsm[];
    __nv_bfloat16* As = (__nv_bfloat16*)dsm;

    int tid = threadIdx.x, lane = tid & 31, wid = tid >> 5;
    int warp_m = wid >> 2, warp_n = wid & 3;
    int b = blockIdx.z;
    int cogBase = blockIdx.y * 32 * JT;
    int y0 = blockIdx.x * YROWS;
    int q0 = y0 * WB;

    for (int i = tid; i < SLABROWS * CPR; i += 256) {
        int rrow = i / CPR, cw = i - rrow * CPR;
        uint4 v = __ldg((const uint4*)(Abuf + ((size_t)b * QTOT + q0 + rrow) * CIN) + cw);
        *(uint4*)(As + rrow * PITCHE + cw * 8) = v;
    }
    __syncthreads();

    int mtg[4];
#pragma unroll
    for (int l = 0; l < 4; l++)
        mtg[l] = (YROWS == 2) ? (warp_m * 2 + (l & 1) + ((l & 2) << 1)) : (warp_m * 4 + l);

    uint32_t smem_u32 = (uint32_t)__cvta_generic_to_shared(As);
    uint32_t abase[4];
#pragma unroll
    for (int l = 0; l < 4; l++) {
        int m = mtg[l] * 16 + (lane & 15);
        int pr = (m >> SHIFT) * WB + (m & (HW - 1));
        abase[l] = smem_u32 + (uint32_t)(pr * PITCHE * 2) + ((lane >> 4) & 1) * 16;
    }

    float acc[4][JT][4];
#pragma unroll
    for (int l = 0; l < 4; l++)
#pragma unroll
        for (int j = 0; j < JT; j++)
#pragma unroll
            for (int c = 0; c < 4; c++) acc[l][j][c] = 0.f;

    int ntp = cogBase / 16 + warp_n * JP;
    // per-thread B base: offsets below are compile-time after unroll
    const uint4* btl = Bpk + (size_t)ntp * 32 + lane;

#pragma unroll 1
    for (int tap = 0; tap < 9; tap++) {
        int ky = tap / 3, kx = tap - ky * 3;
        uint32_t ta[4];
#pragma unroll
        for (int l = 0; l < 4; l++) ta[l] = abase[l] + (uint32_t)((ky * WB + kx) * PITCHE * 2);
        const uint4* bt = btl + (size_t)tap * (3 * KC * 256);
#pragma unroll
        for (int kc = 0; kc < KC; kc++) {
            unsigned a[4][4];
#pragma unroll
            for (int l = 0; l < 4; l++)
                ldsm4(a[l][0], a[l][1], a[l][2], a[l][3], ta[l] + kc * 32);
#pragma unroll
            for (int s = 0; s < 3; s++) {
                uint4 bb[JP];
#pragma unroll
                for (int jp = 0; jp < JP; jp++)
                    bb[jp] = __ldg(bt + (s * KC + kc) * 256 + jp * 32);
#pragma unroll
                for (int l = 0; l < 4; l++)
#pragma unroll
                    for (int jp = 0; jp < JP; jp++) {
                        mma16816(acc[l][2 * jp + 0], a[l], bb[jp].x, bb[jp].y);
                        mma16816(acc[l][2 * jp + 1], a[l], bb[jp].z, bb[jp].w);
                    }
            }
        }
    }

    // Epilogue: SRM + 2x2 maxpool (y-pairs = mtiles l,l+2; x-pairs = lane^4).
#pragma unroll
    for (int lp = 0; lp < 2; lp++) {
#pragma unroll
        for (int o = 0; o < 2; o++) {
            int mA = mtg[lp] * 16 + (lane >> 2) + o * 8;
            int mB = mtg[lp + 2] * 16 + (lane >> 2) + o * 8;
            int yA = y0 + (mA >> SHIFT), xA = mA & (HW - 1);
            int yB = y0 + (mB >> SHIFT);
#pragma unroll
            for (int j = 0; j < JT; j++) {
                int co = cogBase + warp_n * 8 * JT + j * 8 + (lane & 3) * 2;
                size_t iA = ((size_t)(b * HW * HW) + yA * HW + xA) * 128 + co;
                size_t iB = ((size_t)(b * HW * HW) + yB * HW + xA) * 128 + co;
                float sA0, sA1, sB0, sB1;
                srm2_ns(acc[lp][j][o * 2 + 0],     acc[lp][j][o * 2 + 1],     vm, vs, iA, sA0, sA1);
                srm2_ns(acc[lp + 2][j][o * 2 + 0], acc[lp + 2][j][o * 2 + 1], vm, vs, iB, sB0, sB1);
                float xA0 = fmaxf(sA0, __shfl_xor_sync(0xffffffffu, sA0, 4));
                float xA1 = fmaxf(sA1, __shfl_xor_sync(0xffffffffu, sA1, 4));
                float xB0 = fmaxf(sB0, __shfl_xor_sync(0xffffffffu, sB0, 4));
                float xB1 = fmaxf(sB1, __shfl_xor_sync(0xffffffffu, sB1, 4));
                float p0 = fmaxf(xA0, xB0);
                float p1 = fmaxf(xA1, xB1);
                if ((lane & 4) == 0) {
                    int yp = yA >> 1, xp = xA >> 1;
                    if (IS_CONV2) {
                        p2out[(size_t)b * 32768 + co * 256 + yp * 16 + xp] = __float2bfloat16(p0);
                        p2out[(size_t)b * 32768 + (co + 1) * 256 + yp * 16 + xp] = __float2bfloat16(p1);
                    } else {
                        size_t qi = ((size_t)b * 1156 + (yp + 1) * 34 + (xp + 1)) * 128 + co;
                        *reinterpret_cast<__nv_bfloat162*>(poolb + qi) = __floats2bfloat162_rn(p0, p1);
                    }
                }
            }
        }
    }
}

// ---------------------------------------------------------------------------
// fc3 split-K partial GEMM: C[16,512] = p2[16,32768] @ W3[512,32768]^T.
// grid (16 ks, 16 jg); p2 staged as bf16 (binary -> exact); 4 j per warp.
__global__ void __launch_bounds__(256) fc3_partial(const float* __restrict__ W3) {
    extern __shared__ __nv_bfloat16 p2s[];   // [16][2048] bf16 = 64KB
    int ks = blockIdx.x, jg = blockIdx.y;
    int k0 = ks * 2048;
    int tid = threadIdx.x;
    for (int i = tid; i < 4096; i += 256) {   // 4096 uint4 = 32768 bf16
        int b = i >> 8, c = i & 255;
        ((uint4*)p2s)[i] = __ldg((const uint4*)(g_p2b + (size_t)b * 32768 + k0) + c);
    }
    __syncthreads();
    int wj = tid >> 5, lane = tid & 31;
    const uint2* ps = reinterpret_cast<const uint2*>(p2s);
#pragma unroll 1
    for (int jj = 0; jj < 4; jj++) {
        int j = jg * 32 + wj * 4 + jj;
        const float4* wr = reinterpret_cast<const float4*>(W3 + (size_t)j * 32768 + k0);
        float acc[16];
#pragma unroll
        for (int b = 0; b < 16; b++) acc[b] = 0.f;
#pragma unroll 1
        for (int kk = lane; kk < 512; kk += 32) {
            float4 w4 = __ldg(wr + kk);
#pragma unroll
            for (int b = 0; b < 16; b++) {
                uint2 pv = ps[b * 512 + kk];
                float2 lo = __bfloat1622float2(*(const __nv_bfloat162*)&pv.x);
                float2 hi = __bfloat1622float2(*(const __nv_bfloat162*)&pv.y);
                acc[b] += w4.x * lo.x; acc[b] += w4.y * lo.y;
                acc[b] += w4.z * hi.x; acc[b] += w4.w * hi.y;
            }
        }
#pragma unroll
        for (int b = 0; b < 16; b++) {
            float v = acc[b];
            v += __shfl_down_sync(0xffffffffu, v, 16);
            v += __shfl_down_sync(0xffffffffu, v, 8);
            v += __shfl_down_sync(0xffffffffu, v, 4);
            v += __shfl_down_sync(0xffffffffu, v, 2);
            v += __shfl_down_sync(0xffffffffu, v, 1);
            if (lane == 0) g_part[(ks * 16 + b) * 512 + j] = v;
        }
    }
}

// fc3 SRM + fc4 + SRM + output accumulation, one block of 1024 threads.
__global__ void __launch_bounds__(1024) fc34_srm(const float* __restrict__ W4) {
    __shared__ float s3s[8192];
    int tid = threadIdx.x;
#pragma unroll
    for (int e = 0; e < 8; e++) {
        int i = e * 1024 + tid;
        float I = 0.f;
#pragma unroll
        for (int ks = 0; ks < 16; ks++) I += g_part[ks * 8192 + i];
        s3s[i] = srm_ns(I, g_vm3, g_vs3, i);
    }
    __syncthreads();
    if (tid < 176) {
        int b = tid / 11, j = tid % 11;
        const float4* wr = reinterpret_cast<const float4*>(W4 + j * 512);
        const float4* sr = reinterpret_cast<const float4*>(s3s + b * 512);
        float acc = 0.f;
#pragma unroll 4
        for (int k = 0; k < 128; k++) {
            float4 w = __ldg(wr + k), s = sr[k];
            acc += w.x * s.x; acc += w.y * s.y; acc += w.z * s.z; acc += w.w * s.w;
        }
        float sn = srm_ns(acc, g_vm4, g_vs4, tid);
        g_out[tid] += sn;
    }
}

__global__ void finalize_k(float* __restrict__ out) {
    int i = threadIdx.x;
    if (i < 176) out[i] = g_out[i] * 0.0625f;
}

extern "C" void kernel_launch(void* const* d_in, const int* in_sizes, int n_in,
                              void* d_out, int out_size) {
    (void)in_sizes; (void)n_in; (void)out_size;
    const float* x  = (const float*)d_in[0];
    const float* W0 = (const float*)d_in[1];
    const float* W1 = (const float*)d_in[2];
    const float* W2 = (const float*)d_in[3];
    const float* W3 = (const float*)d_in[4];
    const float* W4 = (const float*)d_in[5];
    float* out = (float*)d_out;

    const int SMEM1 = 264 * 144;   // 38016 B
    const int SMEM2 = 204 * 272;   // 55488 B
    cudaFuncSetAttribute((const void*)conv_mma<64, 64, 2, 6, 4, false>,
                         cudaFuncAttributeMaxDynamicSharedMemorySize, SMEM1);
    cudaFuncSetAttribute((const void*)conv_mma<32, 128, 4, 5, 2, true>,
                         cudaFuncAttributeMaxDynamicSharedMemorySize, SMEM2);
    cudaFuncSetAttribute((const void*)fc3_partial,
                         cudaFuncAttributeMaxDynamicSharedMemorySize, 65536);

    __nv_bfloat16 *s0b, *p1b, *p2b;
    uint4 *w1pk, *w2pk;
    float *vm1, *vs1, *vm2, *vs2;
    cudaGetSymbolAddress((void**)&s0b, g_s0b);
    cudaGetSymbolAddress((void**)&p1b, g_p1b);
    cudaGetSymbolAddress((void**)&p2b, g_p2b);
    cudaGetSymbolAddress((void**)&w1pk, g_w1pk);
    cudaGetSymbolAddress((void**)&w2pk, g_w2pk);
    cudaGetSymbolAddress((void**)&vm1, g_vm1);
    cudaGetSymbolAddress((void**)&vs1, g_vs1);
    cudaGetSymbolAddress((void**)&vm2, g_vm2);
    cudaGetSymbolAddress((void**)&vs2, g_vs2);

    zero_all<<<2048, 256>>>();
    pack_w<<<(NW1PK4 + 255) / 256, 256>>>(W1, w1pk, 64, NW1PK4);
    pack_w<<<(NW2PK4 + 255) / 256, 256>>>(W2, w2pk, 128, NW2PK4);
    for (int t = 0; t < 16; t++) {
        conv0_srm<<<dim3(16, 4, 16), 256>>>(x, W0, t);
        conv_mma<64, 64, 2, 6, 4, false><<<dim3(32, 1, 16), 256, SMEM1>>>(
            s0b, w1pk, vm1, vs1, p1b, nullptr);
        conv_mma<32, 128, 4, 5, 2, true><<<dim3(8, 2, 16), 256, SMEM2>>>(
            p1b, w2pk, vm2, vs2, nullptr, p2b);
        fc3_partial<<<dim3(16, 16), 256, 65536>>>(W3);
        fc34_srm<<<1, 1024>>>(W4);
    }
    finalize_k<<<1, 256>>>(out);
}

// round 8
// speedup vs baseline: 3.5934x; 1.1134x over previous
#include <cuda_runtime.h>
#include <cuda_fp16.h>
#include <cstdint>

#define DM 0.9394130628134758f   /* exp(-1/16) */
#define DS 0.7788007830714049f   /* exp(-1/4)  */
#define TH 0.3f
#define INVSC (1.0f/4096.0f)

#define N_L0 (16*64*64*64)       /* conv0 state, [cog][b][px][16c] */
#define N_L1 (16*64*64*128)      /* conv1 state, NHWC */
#define N_L2 (16*32*32*128)      /* conv2 state, NHWC */
#define N_P2 (16*32768)
#define N_L3 (16*512)
#define N_L4 (16*11)
#define N_PART (16*16*512)

#define SZ_S0B (16*4356*64)      /* s0 spikes, guarded NHWC fp16 (66x66) */
#define SZ_P1B (16*1156*128)     /* p1 pooled spikes, guarded NHWC fp16 (34x34) */
#define NW1PK4 (9*2*4*8*32)      /* conv1 packed B uint4: tap,split,kc,ntpair,lane */
#define NW2PK4 (9*2*8*8*32)

__device__ float g_vm0[N_L0], g_vs0[N_L0];
__device__ float g_vm1[N_L1], g_vs1[N_L1];
__device__ float g_vm2[N_L2], g_vs2[N_L2];
__device__ float g_vm3[N_L3], g_vs3[N_L3];
__device__ float g_vm4[N_L4], g_vs4[N_L4];
__device__ float g_part[N_PART];
__device__ float g_out[N_L4];
__device__ __half g_s0b[SZ_S0B];
__device__ __half g_p1b[SZ_P1B];
__device__ __half g_p2b[N_P2];           /* p2 pooled spikes, binary -> fp16 exact */
__device__ uint4 g_w1pk[NW1PK4];
__device__ uint4 g_w2pk[NW2PK4];

// SRM without stored spike: previous spike recomputed from stored vm,vs (bit-exact).
__device__ __forceinline__ float srm_ns(float I, float* vm, float* vs, size_t idx) {
    float v = vm[idx], w = vs[idx];
    float k = ((v - w) > TH) ? 0.f : 1.f;
    float a = DM * v * k + I;
    float c = DS * w * k + I;
    float sn = ((a - c) > TH) ? 1.0f : 0.0f;
    vm[idx] = a; vs[idx] = c;
    return sn;
}

__device__ __forceinline__ void srm2_ns(float I0, float I1,
                                        float* vm, float* vs, size_t idx,
                                        float& s0, float& s1) {
    float2 vmv = *(float2*)(vm + idx);
    float2 vsv = *(float2*)(vs + idx);
    float k0 = ((vmv.x - vsv.x) > TH) ? 0.f : 1.f;
    float k1 = ((vmv.y - vsv.y) > TH) ? 0.f : 1.f;
    float a0 = DM * vmv.x * k0 + I0, a1 = DM * vmv.y * k1 + I1;
    float b0 = DS * vsv.x * k0 + I0, b1 = DS * vsv.y * k1 + I1;
    s0 = ((a0 - b0) > TH) ? 1.f : 0.f;
    s1 = ((a1 - b1) > TH) ? 1.f : 0.f;
    *(float2*)(vm + idx) = make_float2(a0, a1);
    *(float2*)(vs + idx) = make_float2(b0, b1);
}

__global__ void zero_all() {
    int stride = gridDim.x * blockDim.x;
    int i0 = blockIdx.x * blockDim.x + threadIdx.x;
    for (int i = i0; i < N_L0; i += stride) { g_vm0[i] = 0.f; g_vs0[i] = 0.f; }
    for (int i = i0; i < N_L1; i += stride) { g_vm1[i] = 0.f; g_vs1[i] = 0.f; }
    for (int i = i0; i < N_L2; i += stride) { g_vm2[i] = 0.f; g_vs2[i] = 0.f; }
    for (int i = i0; i < N_L3; i += stride) { g_vm3[i] = 0.f; g_vs3[i] = 0.f; }
    for (int i = i0; i < N_L4; i += stride) { g_vm4[i] = 0.f; g_vs4[i] = 0.f; g_out[i] = 0.f; }
    unsigned* s0b = (unsigned*)g_s0b;
    for (int i = i0; i < SZ_S0B / 2; i += stride) s0b[i] = 0u;
    unsigned* p1b = (unsigned*)g_p1b;
    for (int i = i0; i < SZ_P1B / 2; i += stride) p1b[i] = 0u;
}

// ---------------------------------------------------------------------------
// Weight prepack: W[co][ci][3][3] fp32 -> mma B-fragments, fp16 2-way split
// (hi, mid*4096), two n-tiles per lane (uint4).
__device__ __forceinline__ unsigned pick_split_pack_h(float wa, float wb, int split) {
    __half ha = __float2half_rn(wa);
    __half hb = __float2half_rn(wb);
    __half va, vb;
    if (split == 0) { va = ha; vb = hb; }
    else {
        float ra = (wa - __half2float(ha)) * 4096.0f;
        float rb = (wb - __half2float(hb)) * 4096.0f;
        va = __float2half_rn(ra);
        vb = __float2half_rn(rb);
    }
    unsigned ua = (unsigned)__half_as_ushort(va);
    unsigned ub = (unsigned)__half_as_ushort(vb);
    return ua | (ub << 16);
}

__global__ void pack_w(const float* __restrict__ W, uint4* __restrict__ Bpk, int CIN, int total) {
    int idx = blockIdx.x * 256 + threadIdx.x;
    if (idx >= total) return;
    int KC = CIN / 16;
    int lane = idx & 31;
    int p = (idx >> 5) & 7;            // n-tile pair
    int rest = idx >> 8;
    int kc = rest % KC; rest /= KC;
    int split = rest & 1; int tap = rest >> 1;
    int ky = tap / 3, kx = tap % 3;
    int k0 = kc * 16 + (lane & 3) * 2;
    int n0 = (2 * p) * 8 + (lane >> 2);
    int n1 = n0 + 8;
    uint4 v;
    {
        float w0 = W[((size_t)(n0 * CIN + k0 + 0) * 3 + ky) * 3 + kx];
        float w1 = W[((size_t)(n0 * CIN + k0 + 1) * 3 + ky) * 3 + kx];
        float w8 = W[((size_t)(n0 * CIN + k0 + 8) * 3 + ky) * 3 + kx];
        float w9 = W[((size_t)(n0 * CIN + k0 + 9) * 3 + ky) * 3 + kx];
        v.x = pick_split_pack_h(w0, w1, split);
        v.y = pick_split_pack_h(w8, w9, split);
    }
    {
        float w0 = W[((size_t)(n1 * CIN + k0 + 0) * 3 + ky) * 3 + kx];
        float w1 = W[((size_t)(n1 * CIN + k0 + 1) * 3 + ky) * 3 + kx];
        float w8 = W[((size_t)(n1 * CIN + k0 + 8) * 3 + ky) * 3 + kx];
        float w9 = W[((size_t)(n1 * CIN + k0 + 9) * 3 + ky) * 3 + kx];
        v.z = pick_split_pack_h(w0, w1, split);
        v.w = pick_split_pack_h(w8, w9, split);
    }
    Bpk[idx] = v;
}

// ---------------------------------------------------------------------------
// conv0: 2->64 on 64x64. grid (16 tiles, 4 cog, 16 b), 1 px x 16 co per thread.
__global__ void __launch_bounds__(256)
conv0_srm(const float* __restrict__ x, const float* __restrict__ W0, int t) {
    __shared__ float ins[2 * 360];
    __shared__ float ws[16 * 2 * 12];
    __shared__ float sacc[256 * 17];
    int tid = threadIdx.x;
    int b = blockIdx.z;
    int cog = blockIdx.y;
    int tX = blockIdx.x & 3, tY = blockIdx.x >> 2;
    int x0 = tX * 16, y0 = tY * 16;

    const float* xb = x + ((size_t)(b * 16 + t)) * 2 * 4096;
    for (int i = tid; i < 2 * 324; i += 256) {
        int ci = i / 324; int r = i - ci * 324;
        int y = r / 18;   int xq = r - y * 18;
        int gy = y0 + y - 1, gx = x0 + xq - 1;
        float v = 0.f;
        if ((unsigned)gy < 64u && (unsigned)gx < 64u) {
            v = __ldg(xb + ci * 4096 + gy * 64 + gx);
            v = fminf(fmaxf(v, 0.f), 1.f);
        }
        ins[ci * 360 + y * 20 + xq] = v;
    }
    for (int i = tid; i < 16 * 18; i += 256) {
        int col = i / 18; int r = i - col * 18;
        int ci = r / 9;   int k = r - ci * 9;
        ws[(col * 2 + ci) * 12 + k] = __ldg(W0 + ((size_t)(cog * 16 + col) * 2 + ci) * 9 + k);
    }
    __syncthreads();

    int ty = tid >> 4, tx = tid & 15;
    float acc[16];
#pragma unroll
    for (int j = 0; j < 16; j++) acc[j] = 0.f;

#pragma unroll
    for (int ci = 0; ci < 2; ci++) {
        const float* ip = ins + ci * 360 + ty * 20 + tx;
        float iv[3][3];
#pragma unroll
        for (int yy = 0; yy < 3; yy++)
#pragma unroll
            for (int xx = 0; xx < 3; xx++) iv[yy][xx] = ip[yy * 20 + xx];
#pragma unroll
        for (int j = 0; j < 16; j++) {
            const float* wb = ws + (j * 2 + ci) * 12;
            float4 wA = *reinterpret_cast<const float4*>(wb);
            float4 wB = *reinterpret_cast<const float4*>(wb + 4);
            float  w8 = wb[8];
            float s = acc[j];
            s += iv[0][0] * wA.x; s += iv[0][1] * wA.y; s += iv[0][2] * wA.z;
            s += iv[1][0] * wA.w; s += iv[1][1] * wB.x; s += iv[1][2] * wB.y;
            s += iv[2][0] * wB.z; s += iv[2][1] * wB.w; s += iv[2][2] * w8;
            acc[j] = s;
        }
    }

#pragma unroll
    for (int c = 0; c < 16; c++) sacc[(ty * 16 + tx) * 17 + c] = acc[c];
    __syncthreads();

#pragma unroll
    for (int q = 0; q < 4; q++) {
        int f = q * 256 + tid;
        int yl = f >> 6;
        int fi = f & 63;
        int xl = fi >> 2, cq = fi & 3;
        size_t rowb = (((size_t)(cog * 16 + b) * 4096) + (y0 + yl) * 64 + x0) * 16;
        float4 vmv = *(float4*)(g_vm0 + rowb + fi * 4);
        float4 vsv = *(float4*)(g_vs0 + rowb + fi * 4);
        const float* sp = sacc + (yl * 16 + xl) * 17 + cq * 4;
        float I0 = sp[0], I1 = sp[1], I2 = sp[2], I3 = sp[3];
        float k0 = ((vmv.x - vsv.x) > TH) ? 0.f : 1.f;
        float k1 = ((vmv.y - vsv.y) > TH) ? 0.f : 1.f;
        float k2 = ((vmv.z - vsv.z) > TH) ? 0.f : 1.f;
        float k3 = ((vmv.w - vsv.w) > TH) ? 0.f : 1.f;
        float a0 = DM * vmv.x * k0 + I0, a1 = DM * vmv.y * k1 + I1;
        float a2 = DM * vmv.z * k2 + I2, a3 = DM * vmv.w * k3 + I3;
        float c0 = DS * vsv.x * k0 + I0, c1 = DS * vsv.y * k1 + I1;
        float c2 = DS * vsv.z * k2 + I2, c3 = DS * vsv.w * k3 + I3;
        float s0 = ((a0 - c0) > TH) ? 1.f : 0.f;
        float s1 = ((a1 - c1) > TH) ? 1.f : 0.f;
        float s2 = ((a2 - c2) > TH) ? 1.f : 0.f;
        float s3 = ((a3 - c3) > TH) ? 1.f : 0.f;
        *(float4*)(g_vm0 + rowb + fi * 4) = make_float4(a0, a1, a2, a3);
        *(float4*)(g_vs0 + rowb + fi * 4) = make_float4(c0, c1, c2, c3);
        int gy = y0 + yl, gx = x0 + xl;
        size_t qi = ((size_t)b * 4356 + (gy + 1) * 66 + (gx + 1)) * 64 + cog * 16 + cq * 4;
        *(__half2*)(g_s0b + qi)     = __floats2half2_rn(s0, s1);
        *(__half2*)(g_s0b + qi + 2) = __floats2half2_rn(s2, s3);
    }
}

// ---------------------------------------------------------------------------
__device__ __forceinline__ void mma16816h(float* c, const unsigned* a, unsigned b0, unsigned b1) {
    asm volatile(
        "mma.sync.aligned.m16n8k16.row.col.f32.f16.f16.f32 "
        "{%0,%1,%2,%3}, {%4,%5,%6,%7}, {%8,%9}, {%0,%1,%2,%3};\n"
        : "+f"(c[0]), "+f"(c[1]), "+f"(c[2]), "+f"(c[3])
        : "r"(a[0]), "r"(a[1]), "r"(a[2]), "r"(a[3]), "r"(b0), "r"(b1));
}

__device__ __forceinline__ void ldsm4(unsigned& r0, unsigned& r1, unsigned& r2, unsigned& r3,
                                      uint32_t addr) {
    asm volatile("ldmatrix.sync.aligned.m8n8.x4.shared.b16 {%0,%1,%2,%3}, [%4];\n"
                 : "=r"(r0), "=r"(r1), "=r"(r2), "=r"(r3) : "r"(addr));
}

// ---------------------------------------------------------------------------
// Implicit-GEMM 3x3 conv on tensor cores + SRM + fused 2x2 maxpool.
// fp16 2-split weights, separate fp32 accumulators, combined in epilogue.
// CTA: M=128 pixels x N=64 co (JT=2). 8 warps = 2(M) x 4(N).
template<int HW, int CIN, int YROWS, int SHIFT, bool IS_CONV2>
__global__ void __launch_bounds__(256, 2)
conv_mma(const __half* __restrict__ Abuf,
         const uint4* __restrict__ Bpk,
         float* __restrict__ vm, float* __restrict__ vs,
         __half* __restrict__ poolb,
         __half* __restrict__ p2out)
{
    const int WB = HW + 2, QTOT = WB * WB, KC = CIN / 16;
    const int PITCHE = CIN + 8;
    const int SLABROWS = (YROWS + 2) * WB;
    const int CPR = CIN / 8;
    const int JT = 2;
    extern __shared__ __align__(16) unsigned char dsm[];
    __half* As = (__half*)dsm;

    int tid = threadIdx.x, lane = tid & 31, wid = tid >> 5;
    int warp_m = wid >> 2, warp_n = wid & 3;
    int b = blockIdx.z;
    int cogBase = blockIdx.y * 32 * JT;
    int y0 = blockIdx.x * YROWS;
    int q0 = y0 * WB;

    for (int i = tid; i < SLABROWS * CPR; i += 256) {
        int rrow = i / CPR, cw = i - rrow * CPR;
        uint4 v = __ldg((const uint4*)(Abuf + ((size_t)b * QTOT + q0 + rrow) * CIN) + cw);
        *(uint4*)(As + rrow * PITCHE + cw * 8) = v;
    }
    __syncthreads();

    int mtg[4];
#pragma unroll
    for (int l = 0; l < 4; l++)
        mtg[l] = (YROWS == 2) ? (warp_m * 2 + (l & 1) + ((l & 2) << 1)) : (warp_m * 4 + l);

    uint32_t smem_u32 = (uint32_t)__cvta_generic_to_shared(As);
    uint32_t abase[4];
#pragma unroll
    for (int l = 0; l < 4; l++) {
        int m = mtg[l] * 16 + (lane & 15);
        int pr = (m >> SHIFT) * WB + (m & (HW - 1));
        abase[l] = smem_u32 + (uint32_t)(pr * PITCHE * 2) + ((lane >> 4) & 1) * 16;
    }

    float acc[2][4][JT][4];   // [split][mtile][jtile][frag]
#pragma unroll
    for (int s = 0; s < 2; s++)
#pragma unroll
        for (int l = 0; l < 4; l++)
#pragma unroll
            for (int j = 0; j < JT; j++)
#pragma unroll
                for (int c = 0; c < 4; c++) acc[s][l][j][c] = 0.f;

    int ntp = cogBase / 16 + warp_n;
    const uint4* btl = Bpk + (size_t)ntp * 32 + lane;

#pragma unroll 1
    for (int tap = 0; tap < 9; tap++) {
        int ky = tap / 3, kx = tap - ky * 3;
        uint32_t ta[4];
#pragma unroll
        for (int l = 0; l < 4; l++) ta[l] = abase[l] + (uint32_t)((ky * WB + kx) * PITCHE * 2);
        const uint4* bt = btl + (size_t)tap * (2 * KC * 256);
#pragma unroll
        for (int kc = 0; kc < KC; kc++) {
            unsigned a[4][4];
#pragma unroll
            for (int l = 0; l < 4; l++)
                ldsm4(a[l][0], a[l][1], a[l][2], a[l][3], ta[l] + kc * 32);
#pragma unroll
            for (int s = 0; s < 2; s++) {
                uint4 bb = __ldg(bt + (s * KC + kc) * 256);
#pragma unroll
                for (int l = 0; l < 4; l++) {
                    mma16816h(acc[s][l][0], a[l], bb.x, bb.y);
                    mma16816h(acc[s][l][1], a[l], bb.z, bb.w);
                }
            }
        }
    }

    // Epilogue: combine splits, SRM + 2x2 maxpool.
#pragma unroll
    for (int lp = 0; lp < 2; lp++) {
#pragma unroll
        for (int o = 0; o < 2; o++) {
            int mA = mtg[lp] * 16 + (lane >> 2) + o * 8;
            int mB = mtg[lp + 2] * 16 + (lane >> 2) + o * 8;
            int yA = y0 + (mA >> SHIFT), xA = mA & (HW - 1);
            int yB = y0 + (mB >> SHIFT);
#pragma unroll
            for (int j = 0; j < JT; j++) {
                int co = cogBase + warp_n * 8 * JT + j * 8 + (lane & 3) * 2;
                size_t iA = ((size_t)(b * HW * HW) + yA * HW + xA) * 128 + co;
                size_t iB = ((size_t)(b * HW * HW) + yB * HW + xA) * 128 + co;
                float IA0 = acc[0][lp][j][o * 2 + 0]     + acc[1][lp][j][o * 2 + 0]     * INVSC;
                float IA1 = acc[0][lp][j][o * 2 + 1]     + acc[1][lp][j][o * 2 + 1]     * INVSC;
                float IB0 = acc[0][lp + 2][j][o * 2 + 0] + acc[1][lp + 2][j][o * 2 + 0] * INVSC;
                float IB1 = acc[0][lp + 2][j][o * 2 + 1] + acc[1][lp + 2][j][o * 2 + 1] * INVSC;
                float sA0, sA1, sB0, sB1;
                srm2_ns(IA0, IA1, vm, vs, iA, sA0, sA1);
                srm2_ns(IB0, IB1, vm, vs, iB, sB0, sB1);
                float xA0 = fmaxf(sA0, __shfl_xor_sync(0xffffffffu, sA0, 4));
                float xA1 = fmaxf(sA1, __shfl_xor_sync(0xffffffffu, sA1, 4));
                float xB0 = fmaxf(sB0, __shfl_xor_sync(0xffffffffu, sB0, 4));
                float xB1 = fmaxf(sB1, __shfl_xor_sync(0xffffffffu, sB1, 4));
                float p0 = fmaxf(xA0, xB0);
                float p1 = fmaxf(xA1, xB1);
                if ((lane & 4) == 0) {
                    int yp = yA >> 1, xp = xA >> 1;
                    if (IS_CONV2) {
                        p2out[(size_t)b * 32768 + co * 256 + yp * 16 + xp] = __float2half(p0);
                        p2out[(size_t)b * 32768 + (co + 1) * 256 + yp * 16 + xp] = __float2half(p1);
                    } else {
                        size_t qi = ((size_t)b * 1156 + (yp + 1) * 34 + (xp + 1)) * 128 + co;
                        *reinterpret_cast<__half2*>(poolb + qi) = __floats2half2_rn(p0, p1);
                    }
                }
            }
        }
    }
}

// ---------------------------------------------------------------------------
// fc3 split-K partial GEMM: C[16,512] = p2[16,32768] @ W3[512,32768]^T.
// grid (16 ks, 16 jg); p2 staged as fp16 (binary -> exact); 4 j per warp.
__global__ void __launch_bounds__(256) fc3_partial(const float* __restrict__ W3) {
    extern __shared__ __half p2s[];   // [16][2048] fp16 = 64KB
    int ks = blockIdx.x, jg = blockIdx.y;
    int k0 = ks * 2048;
    int tid = threadIdx.x;
    for (int i = tid; i < 4096; i += 256) {
        int b = i >> 8, c = i & 255;
        ((uint4*)p2s)[i] = __ldg((const uint4*)(g_p2b + (size_t)b * 32768 + k0) + c);
    }
    __syncthreads();
    int wj = tid >> 5, lane = tid & 31;
    const uint2* ps = reinterpret_cast<const uint2*>(p2s);
#pragma unroll 1
    for (int jj = 0; jj < 4; jj++) {
        int j = jg * 32 + wj * 4 + jj;
        const float4* wr = reinterpret_cast<const float4*>(W3 + (size_t)j * 32768 + k0);
        float acc[16];
#pragma unroll
        for (int b = 0; b < 16; b++) acc[b] = 0.f;
#pragma unroll 1
        for (int kk = lane; kk < 512; kk += 32) {
            float4 w4 = __ldg(wr + kk);
#pragma unroll
            for (int b = 0; b < 16; b++) {
                uint2 pv = ps[b * 512 + kk];
                float2 lo = __half22float2(*(const __half2*)&pv.x);
                float2 hi = __half22float2(*(const __half2*)&pv.y);
                acc[b] += w4.x * lo.x; acc[b] += w4.y * lo.y;
                acc[b] += w4.z * hi.x; acc[b] += w4.w * hi.y;
            }
        }
#pragma unroll
        for (int b = 0; b < 16; b++) {
            float v = acc[b];
            v += __shfl_down_sync(0xffffffffu, v, 16);
            v += __shfl_down_sync(0xffffffffu, v, 8);
            v += __shfl_down_sync(0xffffffffu, v, 4);
            v += __shfl_down_sync(0xffffffffu, v, 2);
            v += __shfl_down_sync(0xffffffffu, v, 1);
            if (lane == 0) g_part[(ks * 16 + b) * 512 + j] = v;
        }
    }
}

// fc3 SRM + fc4 + SRM + output accumulation, one block of 1024 threads.
__global__ void __launch_bounds__(1024) fc34_srm(const float* __restrict__ W4) {
    __shared__ float s3s[8192];
    int tid = threadIdx.x;
#pragma unroll
    for (int e = 0; e < 8; e++) {
        int i = e * 1024 + tid;
        float I = 0.f;
#pragma unroll
        for (int ks = 0; ks < 16; ks++) I += g_part[ks * 8192 + i];
        s3s[i] = srm_ns(I, g_vm3, g_vs3, i);
    }
    __syncthreads();
    if (tid < 176) {
        int b = tid / 11, j = tid % 11;
        const float4* wr = reinterpret_cast<const float4*>(W4 + j * 512);
        const float4* sr = reinterpret_cast<const float4*>(s3s + b * 512);
        float acc = 0.f;
#pragma unroll 4
        for (int k = 0; k < 128; k++) {
            float4 w = __ldg(wr + k), s = sr[k];
            acc += w.x * s.x; acc += w.y * s.y; acc += w.z * s.z; acc += w.w * s.w;
        }
        float sn = srm_ns(acc, g_vm4, g_vs4, tid);
        g_out[tid] += sn;
    }
}

__global__ void finalize_k(float* __restrict__ out) {
    int i = threadIdx.x;
    if (i < 176) out[i] = g_out[i] * 0.0625f;
}

extern "C" void kernel_launch(void* const* d_in, const int* in_sizes, int n_in,
                              void* d_out, int out_size) {
    (void)in_sizes; (void)n_in; (void)out_size;
    const float* x  = (const float*)d_in[0];
    const float* W0 = (const float*)d_in[1];
    const float* W1 = (const float*)d_in[2];
    const float* W2 = (const float*)d_in[3];
    const float* W3 = (const float*)d_in[4];
    const float* W4 = (const float*)d_in[5];
    float* out = (float*)d_out;

    const int SMEM1 = 264 * 144;   // 38016 B
    const int SMEM2 = 204 * 272;   // 55488 B
    cudaFuncSetAttribute((const void*)conv_mma<64, 64, 2, 6, false>,
                         cudaFuncAttributeMaxDynamicSharedMemorySize, SMEM1);
    cudaFuncSetAttribute((const void*)conv_mma<32, 128, 4, 5, true>,
                         cudaFuncAttributeMaxDynamicSharedMemorySize, SMEM2);
    cudaFuncSetAttribute((const void*)fc3_partial,
                         cudaFuncAttributeMaxDynamicSharedMemorySize, 65536);

    __half *s0b, *p1b, *p2b;
    uint4 *w1pk, *w2pk;
    float *vm1, *vs1, *vm2, *vs2;
    cudaGetSymbolAddress((void**)&s0b, g_s0b);
    cudaGetSymbolAddress((void**)&p1b, g_p1b);
    cudaGetSymbolAddress((void**)&p2b, g_p2b);
    cudaGetSymbolAddress((void**)&w1pk, g_w1pk);
    cudaGetSymbolAddress((void**)&w2pk, g_w2pk);
    cudaGetSymbolAddress((void**)&vm1, g_vm1);
    cudaGetSymbolAddress((void**)&vs1, g_vs1);
    cudaGetSymbolAddress((void**)&vm2, g_vm2);
    cudaGetSymbolAddress((void**)&vs2, g_vs2);

    zero_all<<<2048, 256>>>();
    pack_w<<<(NW1PK4 + 255) / 256, 256>>>(W1, w1pk, 64, NW1PK4);
    pack_w<<<(NW2PK4 + 255) / 256, 256>>>(W2, w2pk, 128, NW2PK4);
    for (int t = 0; t < 16; t++) {
        conv0_srm<<<dim3(16, 4, 16), 256>>>(x, W0, t);
        conv_mma<64, 64, 2, 6, false><<<dim3(32, 2, 16), 256, SMEM1>>>(
            s0b, w1pk, vm1, vs1, p1b, nullptr);
        conv_mma<32, 128, 4, 5, true><<<dim3(8, 2, 16), 256, SMEM2>>>(
            p1b, w2pk, vm2, vs2, nullptr, p2b);
        fc3_partial<<<dim3(16, 16), 256, 65536>>>(W3);
        fc34_srm<<<1, 1024>>>(W4);
    }
    finalize_k<<<1, 256>>>(out);
}

// round 9
// speedup vs baseline: 3.6464x; 1.0148x over previous
#include <cuda_runtime.h>
#include <cuda_fp16.h>
#include <cstdint>

#define DM 0.9394130628134758f   /* exp(-1/16) */
#define DS 0.7788007830714049f   /* exp(-1/4)  */
#define TH 0.3f
#define INVSC (1.0f/4096.0f)

#define N_L0 (16*64*64*64)       /* conv0 state, [cog][b][px][16c] */
#define N_L1 (16*64*64*128)      /* conv1 state, NHWC */
#define N_L2 (16*32*32*128)      /* conv2 state, NHWC */
#define N_P2 (16*32768)
#define N_L3 (16*512)
#define N_L4 (16*11)
#define N_PART (16*16*512)

#define SZ_S0B (16*4356*64)      /* s0 spikes, guarded NHWC fp16 (66x66) */
#define SZ_P1B (16*1156*128)     /* p1 pooled spikes, guarded NHWC fp16 (34x34) */
#define NW1PK4 (9*2*4*8*32)      /* conv1 packed B uint4: tap,split,kc,ntpair,lane */
#define NW2PK4 (9*2*8*8*32)

__device__ float g_vm0[N_L0], g_vs0[N_L0];
__device__ float g_vm1[N_L1], g_vs1[N_L1];
__device__ float g_vm2[N_L2], g_vs2[N_L2];
__device__ float g_vm3[N_L3], g_vs3[N_L3];
__device__ float g_vm4[N_L4], g_vs4[N_L4];
__device__ float g_part[N_PART];
__device__ float g_out[N_L4];
__device__ __half g_s0b[SZ_S0B];
__device__ __half g_p1b[SZ_P1B];
__device__ __half g_p2b[N_P2];           /* p2 pooled spikes, binary -> fp16 exact */
__device__ uint4 g_w1pk[NW1PK4];
__device__ uint4 g_w2pk[NW2PK4];

// SRM without stored spike: previous spike recomputed from stored vm,vs (bit-exact).
__device__ __forceinline__ float srm_ns(float I, float* vm, float* vs, size_t idx) {
    float v = vm[idx], w = vs[idx];
    float k = ((v - w) > TH) ? 0.f : 1.f;
    float a = DM * v * k + I;
    float c = DS * w * k + I;
    float sn = ((a - c) > TH) ? 1.0f : 0.0f;
    vm[idx] = a; vs[idx] = c;
    return sn;
}

__device__ __forceinline__ void srm2_ns(float I0, float I1,
                                        float* vm, float* vs, size_t idx,
                                        float& s0, float& s1) {
    float2 vmv = *(float2*)(vm + idx);
    float2 vsv = *(float2*)(vs + idx);
    float k0 = ((vmv.x - vsv.x) > TH) ? 0.f : 1.f;
    float k1 = ((vmv.y - vsv.y) > TH) ? 0.f : 1.f;
    float a0 = DM * vmv.x * k0 + I0, a1 = DM * vmv.y * k1 + I1;
    float b0 = DS * vsv.x * k0 + I0, b1 = DS * vsv.y * k1 + I1;
    s0 = ((a0 - b0) > TH) ? 1.f : 0.f;
    s1 = ((a1 - b1) > TH) ? 1.f : 0.f;
    *(float2*)(vm + idx) = make_float2(a0, a1);
    *(float2*)(vs + idx) = make_float2(b0, b1);
}

__global__ void zero_all() {
    int stride = gridDim.x * blockDim.x;
    int i0 = blockIdx.x * blockDim.x + threadIdx.x;
    for (int i = i0; i < N_L0; i += stride) { g_vm0[i] = 0.f; g_vs0[i] = 0.f; }
    for (int i = i0; i < N_L1; i += stride) { g_vm1[i] = 0.f; g_vs1[i] = 0.f; }
    for (int i = i0; i < N_L2; i += stride) { g_vm2[i] = 0.f; g_vs2[i] = 0.f; }
    for (int i = i0; i < N_L3; i += stride) { g_vm3[i] = 0.f; g_vs3[i] = 0.f; }
    for (int i = i0; i < N_L4; i += stride) { g_vm4[i] = 0.f; g_vs4[i] = 0.f; g_out[i] = 0.f; }
    unsigned* s0b = (unsigned*)g_s0b;
    for (int i = i0; i < SZ_S0B / 2; i += stride) s0b[i] = 0u;
    unsigned* p1b = (unsigned*)g_p1b;
    for (int i = i0; i < SZ_P1B / 2; i += stride) p1b[i] = 0u;
}

// ---------------------------------------------------------------------------
// Weight prepack: W[co][ci][3][3] fp32 -> mma B-fragments, fp16 2-way split
// (hi, mid*4096), two n-tiles per lane (uint4).
__device__ __forceinline__ unsigned pick_split_pack_h(float wa, float wb, int split) {
    __half ha = __float2half_rn(wa);
    __half hb = __float2half_rn(wb);
    __half va, vb;
    if (split == 0) { va = ha; vb = hb; }
    else {
        float ra = (wa - __half2float(ha)) * 4096.0f;
        float rb = (wb - __half2float(hb)) * 4096.0f;
        va = __float2half_rn(ra);
        vb = __float2half_rn(rb);
    }
    unsigned ua = (unsigned)__half_as_ushort(va);
    unsigned ub = (unsigned)__half_as_ushort(vb);
    return ua | (ub << 16);
}

__global__ void pack_w(const float* __restrict__ W, uint4* __restrict__ Bpk, int CIN, int total) {
    int idx = blockIdx.x * 256 + threadIdx.x;
    if (idx >= total) return;
    int KC = CIN / 16;
    int lane = idx & 31;
    int p = (idx >> 5) & 7;            // n-tile pair
    int rest = idx >> 8;
    int kc = rest % KC; rest /= KC;
    int split = rest & 1; int tap = rest >> 1;
    int ky = tap / 3, kx = tap % 3;
    int k0 = kc * 16 + (lane & 3) * 2;
    int n0 = (2 * p) * 8 + (lane >> 2);
    int n1 = n0 + 8;
    uint4 v;
    {
        float w0 = W[((size_t)(n0 * CIN + k0 + 0) * 3 + ky) * 3 + kx];
        float w1 = W[((size_t)(n0 * CIN + k0 + 1) * 3 + ky) * 3 + kx];
        float w8 = W[((size_t)(n0 * CIN + k0 + 8) * 3 + ky) * 3 + kx];
        float w9 = W[((size_t)(n0 * CIN + k0 + 9) * 3 + ky) * 3 + kx];
        v.x = pick_split_pack_h(w0, w1, split);
        v.y = pick_split_pack_h(w8, w9, split);
    }
    {
        float w0 = W[((size_t)(n1 * CIN + k0 + 0) * 3 + ky) * 3 + kx];
        float w1 = W[((size_t)(n1 * CIN + k0 + 1) * 3 + ky) * 3 + kx];
        float w8 = W[((size_t)(n1 * CIN + k0 + 8) * 3 + ky) * 3 + kx];
        float w9 = W[((size_t)(n1 * CIN + k0 + 9) * 3 + ky) * 3 + kx];
        v.z = pick_split_pack_h(w0, w1, split);
        v.w = pick_split_pack_h(w8, w9, split);
    }
    Bpk[idx] = v;
}

// ---------------------------------------------------------------------------
// conv0: 2->64 on 64x64. grid (16 tiles, 4 cog, 16 b), 1 px x 16 co per thread.
__global__ void __launch_bounds__(256)
conv0_srm(const float* __restrict__ x, const float* __restrict__ W0, int t) {
    __shared__ float ins[2 * 360];
    __shared__ float ws[16 * 2 * 12];
    __shared__ float sacc[256 * 17];
    int tid = threadIdx.x;
    int b = blockIdx.z;
    int cog = blockIdx.y;
    int tX = blockIdx.x & 3, tY = blockIdx.x >> 2;
    int x0 = tX * 16, y0 = tY * 16;

    const float* xb = x + ((size_t)(b * 16 + t)) * 2 * 4096;
    for (int i = tid; i < 2 * 324; i += 256) {
        int ci = i / 324; int r = i - ci * 324;
        int y = r / 18;   int xq = r - y * 18;
        int gy = y0 + y - 1, gx = x0 + xq - 1;
        float v = 0.f;
        if ((unsigned)gy < 64u && (unsigned)gx < 64u) {
            v = __ldg(xb + ci * 4096 + gy * 64 + gx);
            v = fminf(fmaxf(v, 0.f), 1.f);
        }
        ins[ci * 360 + y * 20 + xq] = v;
    }
    for (int i = tid; i < 16 * 18; i += 256) {
        int col = i / 18; int r = i - col * 18;
        int ci = r / 9;   int k = r - ci * 9;
        ws[(col * 2 + ci) * 12 + k] = __ldg(W0 + ((size_t)(cog * 16 + col) * 2 + ci) * 9 + k);
    }
    __syncthreads();

    int ty = tid >> 4, tx = tid & 15;
    float acc[16];
#pragma unroll
    for (int j = 0; j < 16; j++) acc[j] = 0.f;

#pragma unroll
    for (int ci = 0; ci < 2; ci++) {
        const float* ip = ins + ci * 360 + ty * 20 + tx;
        float iv[3][3];
#pragma unroll
        for (int yy = 0; yy < 3; yy++)
#pragma unroll
            for (int xx = 0; xx < 3; xx++) iv[yy][xx] = ip[yy * 20 + xx];
#pragma unroll
        for (int j = 0; j < 16; j++) {
            const float* wb = ws + (j * 2 + ci) * 12;
            float4 wA = *reinterpret_cast<const float4*>(wb);
            float4 wB = *reinterpret_cast<const float4*>(wb + 4);
            float  w8 = wb[8];
            float s = acc[j];
            s += iv[0][0] * wA.x; s += iv[0][1] * wA.y; s += iv[0][2] * wA.z;
            s += iv[1][0] * wA.w; s += iv[1][1] * wB.x; s += iv[1][2] * wB.y;
            s += iv[2][0] * wB.z; s += iv[2][1] * wB.w; s += iv[2][2] * w8;
            acc[j] = s;
        }
    }

#pragma unroll
    for (int c = 0; c < 16; c++) sacc[(ty * 16 + tx) * 17 + c] = acc[c];
    __syncthreads();

#pragma unroll
    for (int q = 0; q < 4; q++) {
        int f = q * 256 + tid;
        int yl = f >> 6;
        int fi = f & 63;
        int xl = fi >> 2, cq = fi & 3;
        size_t rowb = (((size_t)(cog * 16 + b) * 4096) + (y0 + yl) * 64 + x0) * 16;
        float4 vmv = *(float4*)(g_vm0 + rowb + fi * 4);
        float4 vsv = *(float4*)(g_vs0 + rowb + fi * 4);
        const float* sp = sacc + (yl * 16 + xl) * 17 + cq * 4;
        float I0 = sp[0], I1 = sp[1], I2 = sp[2], I3 = sp[3];
        float k0 = ((vmv.x - vsv.x) > TH) ? 0.f : 1.f;
        float k1 = ((vmv.y - vsv.y) > TH) ? 0.f : 1.f;
        float k2 = ((vmv.z - vsv.z) > TH) ? 0.f : 1.f;
        float k3 = ((vmv.w - vsv.w) > TH) ? 0.f : 1.f;
        float a0 = DM * vmv.x * k0 + I0, a1 = DM * vmv.y * k1 + I1;
        float a2 = DM * vmv.z * k2 + I2, a3 = DM * vmv.w * k3 + I3;
        float c0 = DS * vsv.x * k0 + I0, c1 = DS * vsv.y * k1 + I1;
        float c2 = DS * vsv.z * k2 + I2, c3 = DS * vsv.w * k3 + I3;
        float s0 = ((a0 - c0) > TH) ? 1.f : 0.f;
        float s1 = ((a1 - c1) > TH) ? 1.f : 0.f;
        float s2 = ((a2 - c2) > TH) ? 1.f : 0.f;
        float s3 = ((a3 - c3) > TH) ? 1.f : 0.f;
        *(float4*)(g_vm0 + rowb + fi * 4) = make_float4(a0, a1, a2, a3);
        *(float4*)(g_vs0 + rowb + fi * 4) = make_float4(c0, c1, c2, c3);
        int gy = y0 + yl, gx = x0 + xl;
        size_t qi = ((size_t)b * 4356 + (gy + 1) * 66 + (gx + 1)) * 64 + cog * 16 + cq * 4;
        *(__half2*)(g_s0b + qi)     = __floats2half2_rn(s0, s1);
        *(__half2*)(g_s0b + qi + 2) = __floats2half2_rn(s2, s3);
    }
}

// ---------------------------------------------------------------------------
__device__ __forceinline__ void mma16816h(float* c, const unsigned* a, unsigned b0, unsigned b1) {
    asm volatile(
        "mma.sync.aligned.m16n8k16.row.col.f32.f16.f16.f32 "
        "{%0,%1,%2,%3}, {%4,%5,%6,%7}, {%8,%9}, {%0,%1,%2,%3};\n"
        : "+f"(c[0]), "+f"(c[1]), "+f"(c[2]), "+f"(c[3])
        : "r"(a[0]), "r"(a[1]), "r"(a[2]), "r"(a[3]), "r"(b0), "r"(b1));
}

__device__ __forceinline__ void ldsm4(unsigned& r0, unsigned& r1, unsigned& r2, unsigned& r3,
                                      uint32_t addr) {
    asm volatile("ldmatrix.sync.aligned.m8n8.x4.shared.b16 {%0,%1,%2,%3}, [%4];\n"
                 : "=r"(r0), "=r"(r1), "=r"(r2), "=r"(r3) : "r"(addr));
}

// ---------------------------------------------------------------------------
// Implicit-GEMM 3x3 conv on tensor cores + SRM + fused 2x2 maxpool.
// fp16 2-split weights, separate fp32 accumulators, combined in epilogue.
// CTA: M=128 pixels x N=64 co (JT=2). 8 warps = 2(M) x 4(N).
template<int HW, int CIN, int YROWS, int SHIFT, bool IS_CONV2>
__global__ void __launch_bounds__(256, 2)
conv_mma(const __half* __restrict__ Abuf,
         const uint4* __restrict__ Bpk,
         float* __restrict__ vm, float* __restrict__ vs,
         __half* __restrict__ poolb,
         __half* __restrict__ p2out)
{
    const int WB = HW + 2, QTOT = WB * WB, KC = CIN / 16;
    const int PITCHE = CIN + 8;
    const int SLABROWS = (YROWS + 2) * WB;
    const int CPR = CIN / 8;
    const int JT = 2;
    extern __shared__ __align__(16) unsigned char dsm[];
    __half* As = (__half*)dsm;

    int tid = threadIdx.x, lane = tid & 31, wid = tid >> 5;
    int warp_m = wid >> 2, warp_n = wid & 3;
    int b = blockIdx.z;
    int cogBase = blockIdx.y * 32 * JT;
    int y0 = blockIdx.x * YROWS;
    int q0 = y0 * WB;

    for (int i = tid; i < SLABROWS * CPR; i += 256) {
        int rrow = i / CPR, cw = i - rrow * CPR;
        uint4 v = __ldg((const uint4*)(Abuf + ((size_t)b * QTOT + q0 + rrow) * CIN) + cw);
        *(uint4*)(As + rrow * PITCHE + cw * 8) = v;
    }
    __syncthreads();

    int mtg[4];
#pragma unroll
    for (int l = 0; l < 4; l++)
        mtg[l] = (YROWS == 2) ? (warp_m * 2 + (l & 1) + ((l & 2) << 1)) : (warp_m * 4 + l);

    uint32_t smem_u32 = (uint32_t)__cvta_generic_to_shared(As);
    uint32_t abase[4];
#pragma unroll
    for (int l = 0; l < 4; l++) {
        int m = mtg[l] * 16 + (lane & 15);
        int pr = (m >> SHIFT) * WB + (m & (HW - 1));
        abase[l] = smem_u32 + (uint32_t)(pr * PITCHE * 2) + ((lane >> 4) & 1) * 16;
    }

    float acc[2][4][JT][4];   // [split][mtile][jtile][frag]
#pragma unroll
    for (int s = 0; s < 2; s++)
#pragma unroll
        for (int l = 0; l < 4; l++)
#pragma unroll
            for (int j = 0; j < JT; j++)
#pragma unroll
                for (int c = 0; c < 4; c++) acc[s][l][j][c] = 0.f;

    int ntp = cogBase / 16 + warp_n;
    const uint4* btl = Bpk + (size_t)ntp * 32 + lane;

#pragma unroll 1
    for (int tap = 0; tap < 9; tap++) {
        int ky = tap / 3, kx = tap - ky * 3;
        uint32_t ta[4];
#pragma unroll
        for (int l = 0; l < 4; l++) ta[l] = abase[l] + (uint32_t)((ky * WB + kx) * PITCHE * 2);
        const uint4* bt = btl + (size_t)tap * (2 * KC * 256);
#pragma unroll
        for (int kc = 0; kc < KC; kc++) {
            unsigned a[4][4];
#pragma unroll
            for (int l = 0; l < 4; l++)
                ldsm4(a[l][0], a[l][1], a[l][2], a[l][3], ta[l] + kc * 32);
#pragma unroll
            for (int s = 0; s < 2; s++) {
                uint4 bb = __ldg(bt + (s * KC + kc) * 256);
#pragma unroll
                for (int l = 0; l < 4; l++) {
                    mma16816h(acc[s][l][0], a[l], bb.x, bb.y);
                    mma16816h(acc[s][l][1], a[l], bb.z, bb.w);
                }
            }
        }
    }

    // Epilogue: combine splits, SRM + 2x2 maxpool.
#pragma unroll
    for (int lp = 0; lp < 2; lp++) {
#pragma unroll
        for (int o = 0; o < 2; o++) {
            int mA = mtg[lp] * 16 + (lane >> 2) + o * 8;
            int mB = mtg[lp + 2] * 16 + (lane >> 2) + o * 8;
            int yA = y0 + (mA >> SHIFT), xA = mA & (HW - 1);
            int yB = y0 + (mB >> SHIFT);
#pragma unroll
            for (int j = 0; j < JT; j++) {
                int co = cogBase + warp_n * 8 * JT + j * 8 + (lane & 3) * 2;
                size_t iA = ((size_t)(b * HW * HW) + yA * HW + xA) * 128 + co;
                size_t iB = ((size_t)(b * HW * HW) + yB * HW + xA) * 128 + co;
                float IA0 = acc[0][lp][j][o * 2 + 0]     + acc[1][lp][j][o * 2 + 0]     * INVSC;
                float IA1 = acc[0][lp][j][o * 2 + 1]     + acc[1][lp][j][o * 2 + 1]     * INVSC;
                float IB0 = acc[0][lp + 2][j][o * 2 + 0] + acc[1][lp + 2][j][o * 2 + 0] * INVSC;
                float IB1 = acc[0][lp + 2][j][o * 2 + 1] + acc[1][lp + 2][j][o * 2 + 1] * INVSC;
                float sA0, sA1, sB0, sB1;
                srm2_ns(IA0, IA1, vm, vs, iA, sA0, sA1);
                srm2_ns(IB0, IB1, vm, vs, iB, sB0, sB1);
                float xA0 = fmaxf(sA0, __shfl_xor_sync(0xffffffffu, sA0, 4));
                float xA1 = fmaxf(sA1, __shfl_xor_sync(0xffffffffu, sA1, 4));
                float xB0 = fmaxf(sB0, __shfl_xor_sync(0xffffffffu, sB0, 4));
                float xB1 = fmaxf(sB1, __shfl_xor_sync(0xffffffffu, sB1, 4));
                float p0 = fmaxf(xA0, xB0);
                float p1 = fmaxf(xA1, xB1);
                if ((lane & 4) == 0) {
                    int yp = yA >> 1, xp = xA >> 1;
                    if (IS_CONV2) {
                        p2out[(size_t)b * 32768 + co * 256 + yp * 16 + xp] = __float2half(p0);
                        p2out[(size_t)b * 32768 + (co + 1) * 256 + yp * 16 + xp] = __float2half(p1);
                    } else {
                        size_t qi = ((size_t)b * 1156 + (yp + 1) * 34 + (xp + 1)) * 128 + co;
                        *reinterpret_cast<__half2*>(poolb + qi) = __floats2half2_rn(p0, p1);
                    }
                }
            }
        }
    }
}

// ---------------------------------------------------------------------------
// fc3 split-K partial GEMM: C[16,512] = p2[16,32768] @ W3[512,32768]^T.
// grid (16 ks, 16 jg); p2 staged as fp16 (binary -> exact); 4 j per warp.
__global__ void __launch_bounds__(256) fc3_partial(const float* __restrict__ W3) {
    extern __shared__ __half p2s[];   // [16][2048] fp16 = 64KB
    int ks = blockIdx.x, jg = blockIdx.y;
    int k0 = ks * 2048;
    int tid = threadIdx.x;
    for (int i = tid; i < 4096; i += 256) {
        int b = i >> 8, c = i & 255;
        ((uint4*)p2s)[i] = __ldg((const uint4*)(g_p2b + (size_t)b * 32768 + k0) + c);
    }
    __syncthreads();
    int wj = tid >> 5, lane = tid & 31;
    const uint2* ps = reinterpret_cast<const uint2*>(p2s);
#pragma unroll 1
    for (int jj = 0; jj < 4; jj++) {
        int j = jg * 32 + wj * 4 + jj;
        const float4* wr = reinterpret_cast<const float4*>(W3 + (size_t)j * 32768 + k0);
        float acc[16];
#pragma unroll
        for (int b = 0; b < 16; b++) acc[b] = 0.f;
#pragma unroll 1
        for (int kk = lane; kk < 512; kk += 32) {
            float4 w4 = __ldg(wr + kk);
#pragma unroll
            for (int b = 0; b < 16; b++) {
                uint2 pv = ps[b * 512 + kk];
                float2 lo = __half22float2(*(const __half2*)&pv.x);
                float2 hi = __half22float2(*(const __half2*)&pv.y);
                acc[b] += w4.x * lo.x; acc[b] += w4.y * lo.y;
                acc[b] += w4.z * hi.x; acc[b] += w4.w * hi.y;
            }
        }
#pragma unroll
        for (int b = 0; b < 16; b++) {
            float v = acc[b];
            v += __shfl_down_sync(0xffffffffu, v, 16);
            v += __shfl_down_sync(0xffffffffu, v, 8);
            v += __shfl_down_sync(0xffffffffu, v, 4);
            v += __shfl_down_sync(0xffffffffu, v, 2);
            v += __shfl_down_sync(0xffffffffu, v, 1);
            if (lane == 0) g_part[(ks * 16 + b) * 512 + j] = v;
        }
    }
}

// fc3 SRM + fc4 + SRM + output accumulation, one block of 1024 threads.
__global__ void __launch_bounds__(1024) fc34_srm(const float* __restrict__ W4) {
    __shared__ float s3s[8192];
    int tid = threadIdx.x;
#pragma unroll
    for (int e = 0; e < 8; e++) {
        int i = e * 1024 + tid;
        float I = 0.f;
#pragma unroll
        for (int ks = 0; ks < 16; ks++) I += g_part[ks * 8192 + i];
        s3s[i] = srm_ns(I, g_vm3, g_vs3, i);
    }
    __syncthreads();
    if (tid < 176) {
        int b = tid / 11, j = tid % 11;
        const float4* wr = reinterpret_cast<const float4*>(W4 + j * 512);
        const float4* sr = reinterpret_cast<const float4*>(s3s + b * 512);
        float acc = 0.f;
#pragma unroll 4
        for (int k = 0; k < 128; k++) {
            float4 w = __ldg(wr + k), s = sr[k];
            acc += w.x * s.x; acc += w.y * s.y; acc += w.z * s.z; acc += w.w * s.w;
        }
        float sn = srm_ns(acc, g_vm4, g_vs4, tid);
        g_out[tid] += sn;
    }
}

__global__ void finalize_k(float* __restrict__ out) {
    int i = threadIdx.x;
    if (i < 176) out[i] = g_out[i] * 0.0625f;
}

extern "C" void kernel_launch(void* const* d_in, const int* in_sizes, int n_in,
                              void* d_out, int out_size) {
    (void)in_sizes; (void)n_in; (void)out_size;
    const float* x  = (const float*)d_in[0];
    const float* W0 = (const float*)d_in[1];
    const float* W1 = (const float*)d_in[2];
    const float* W2 = (const float*)d_in[3];
    const float* W3 = (const float*)d_in[4];
    const float* W4 = (const float*)d_in[5];
    float* out = (float*)d_out;

    const int SMEM1 = 264 * 144;   // 38016 B
    const int SMEM2 = 204 * 272;   // 55488 B
    cudaFuncSetAttribute((const void*)conv_mma<64, 64, 2, 6, false>,
                         cudaFuncAttributeMaxDynamicSharedMemorySize, SMEM1);
    cudaFuncSetAttribute((const void*)conv_mma<32, 128, 4, 5, true>,
                         cudaFuncAttributeMaxDynamicSharedMemorySize, SMEM2);
    cudaFuncSetAttribute((const void*)fc3_partial,
                         cudaFuncAttributeMaxDynamicSharedMemorySize, 65536);

    __half *s0b, *p1b, *p2b;
    uint4 *w1pk, *w2pk;
    float *vm1, *vs1, *vm2, *vs2;
    cudaGetSymbolAddress((void**)&s0b, g_s0b);
    cudaGetSymbolAddress((void**)&p1b, g_p1b);
    cudaGetSymbolAddress((void**)&p2b, g_p2b);
    cudaGetSymbolAddress((void**)&w1pk, g_w1pk);
    cudaGetSymbolAddress((void**)&w2pk, g_w2pk);
    cudaGetSymbolAddress((void**)&vm1, g_vm1);
    cudaGetSymbolAddress((void**)&vs1, g_vs1);
    cudaGetSymbolAddress((void**)&vm2, g_vm2);
    cudaGetSymbolAddress((void**)&vs2, g_vs2);

    zero_all<<<2048, 256>>>();
    pack_w<<<(NW1PK4 + 255) / 256, 256>>>(W1, w1pk, 64, NW1PK4);
    pack_w<<<(NW2PK4 + 255) / 256, 256>>>(W2, w2pk, 128, NW2PK4);
    for (int t = 0; t < 16; t++) {
        conv0_srm<<<dim3(16, 4, 16), 256>>>(x, W0, t);
        conv_mma<64, 64, 2, 6, false><<<dim3(32, 2, 16), 256, SMEM1>>>(
            s0b, w1pk, vm1, vs1, p1b, nullptr);
        conv_mma<32, 128, 4, 5, true><<<dim3(8, 2, 16), 256, SMEM2>>>(
            p1b, w2pk, vm2, vs2, nullptr, p2b);
        fc3_partial<<<dim3(16, 16), 256, 65536>>>(W3);
        fc34_srm<<<1, 1024>>>(W4);
    }
    finalize_k<<<1, 256>>>(out);
}

// round 11
// speedup vs baseline: 5.1546x; 1.4136x over previous
#include <cuda_runtime.h>
#include <cuda_fp16.h>
#include <cstdint>

#define DM 0.9394130628134758f
#define DS 0.7788007830714049f
#define TH 0.3f
#define INVSC (1.0f/4096.0f)

#define N_L0 (16*64*64*64)
#define N_L1 (16*64*64*128)
#define N_L2 (16*32*32*128)
#define N_P2 (16*32768)
#define N_L3 (16*512)
#define N_L4 (16*11)
#define N_PART (16*16*512)
#define SZ_S0B (16*4356*64)
#define SZ_P1B (16*1156*128)
#define NW1PK4 (9*2*4*8*32)
#define NW2PK4 (9*2*8*8*32)

__device__ float g_vm0[N_L0], g_vs0[N_L0];
__device__ float g_vm1[N_L1], g_vs1[N_L1];
__device__ float g_vm2[N_L2], g_vs2[N_L2];
__device__ float g_vm3[N_L3], g_vs3[N_L3];
__device__ float g_vm4[N_L4], g_vs4[N_L4];
__device__ float g_part[N_PART];
__device__ float g_out[N_L4];
__device__ __half g_s0b[2 * SZ_S0B];     /* double-buffered (pipeline) */
__device__ __half g_p1b[SZ_P1B];
__device__ __half g_p2b[2 * N_P2];       /* double-buffered (pipeline) */
__device__ uint4 g_w1pk[NW1PK4];
__device__ uint4 g_w2pk[NW2PK4];

__device__ __forceinline__ float srm_ns(float I, float* vm, float* vs, size_t idx) {
    float v = vm[idx], w = vs[idx];
    float k = ((v - w) > TH) ? 0.f : 1.f;
    float a = DM * v * k + I;
    float c = DS * w * k + I;
    float sn = ((a - c) > TH) ? 1.0f : 0.0f;
    vm[idx] = a; vs[idx] = c;
    return sn;
}

__device__ __forceinline__ void srm2_ns(float I0, float I1, float* vm, float* vs,
                                        size_t idx, float& s0, float& s1) {
    float2 vmv = *(float2*)(vm + idx);
    float2 vsv = *(float2*)(vs + idx);
    float k0 = ((vmv.x - vsv.x) > TH) ? 0.f : 1.f;
    float k1 = ((vmv.y - vsv.y) > TH) ? 0.f : 1.f;
    float a0 = DM * vmv.x * k0 + I0, a1 = DM * vmv.y * k1 + I1;
    float b0 = DS * vsv.x * k0 + I0, b1 = DS * vsv.y * k1 + I1;
    s0 = ((a0 - b0) > TH) ? 1.f : 0.f;
    s1 = ((a1 - b1) > TH) ? 1.f : 0.f;
    *(float2*)(vm + idx) = make_float2(a0, a1);
    *(float2*)(vs + idx) = make_float2(b0, b1);
}

__global__ void zero_all() {
    int stride = gridDim.x * blockDim.x;
    int i0 = blockIdx.x * blockDim.x + threadIdx.x;
    for (int i = i0; i < N_L0; i += stride) { g_vm0[i] = 0.f; g_vs0[i] = 0.f; }
    for (int i = i0; i < N_L1; i += stride) { g_vm1[i] = 0.f; g_vs1[i] = 0.f; }
    for (int i = i0; i < N_L2; i += stride) { g_vm2[i] = 0.f; g_vs2[i] = 0.f; }
    for (int i = i0; i < N_L3; i += stride) { g_vm3[i] = 0.f; g_vs3[i] = 0.f; }
    for (int i = i0; i < N_L4; i += stride) { g_vm4[i] = 0.f; g_vs4[i] = 0.f; g_out[i] = 0.f; }
    unsigned* a = (unsigned*)g_s0b;
    for (int i = i0; i < SZ_S0B; i += stride) a[i] = 0u;   /* both buffers */
    unsigned* c = (unsigned*)g_p1b;
    for (int i = i0; i < SZ_P1B / 2; i += stride) c[i] = 0u;
}

__device__ __forceinline__ unsigned pick_split_pack_h(float wa, float wb, int split) {
    __half ha = __float2half_rn(wa);
    __half hb = __float2half_rn(wb);
    __half va, vb;
    if (split == 0) { va = ha; vb = hb; }
    else {
        va = __float2half_rn((wa - __half2float(ha)) * 4096.0f);
        vb = __float2half_rn((wb - __half2float(hb)) * 4096.0f);
    }
    return (unsigned)__half_as_ushort(va) | ((unsigned)__half_as_ushort(vb) << 16);
}

__global__ void pack_w(const float* __restrict__ W, uint4* __restrict__ Bpk, int CIN, int total) {
    int idx = blockIdx.x * 256 + threadIdx.x;
    if (idx >= total) return;
    int KC = CIN / 16;
    int lane = idx & 31;
    int p = (idx >> 5) & 7;
    int rest = idx >> 8;
    int kc = rest % KC; rest /= KC;
    int split = rest & 1; int tap = rest >> 1;
    int ky = tap / 3, kx = tap % 3;
    int k0 = kc * 16 + (lane & 3) * 2;
    int n0 = (2 * p) * 8 + (lane >> 2);
    int n1 = n0 + 8;
    uint4 v;
    {
        float w0 = W[((size_t)(n0 * CIN + k0 + 0) * 3 + ky) * 3 + kx];
        float w1 = W[((size_t)(n0 * CIN + k0 + 1) * 3 + ky) * 3 + kx];
        float w8 = W[((size_t)(n0 * CIN + k0 + 8) * 3 + ky) * 3 + kx];
        float w9 = W[((size_t)(n0 * CIN + k0 + 9) * 3 + ky) * 3 + kx];
        v.x = pick_split_pack_h(w0, w1, split);
        v.y = pick_split_pack_h(w8, w9, split);
    }
    {
        float w0 = W[((size_t)(n1 * CIN + k0 + 0) * 3 + ky) * 3 + kx];
        float w1 = W[((size_t)(n1 * CIN + k0 + 1) * 3 + ky) * 3 + kx];
        float w8 = W[((size_t)(n1 * CIN + k0 + 8) * 3 + ky) * 3 + kx];
        float w9 = W[((size_t)(n1 * CIN + k0 + 9) * 3 + ky) * 3 + kx];
        v.z = pick_split_pack_h(w0, w1, split);
        v.w = pick_split_pack_h(w8, w9, split);
    }
    Bpk[idx] = v;
}

__global__ void __launch_bounds__(256)
conv0_srm(const float* __restrict__ x, const float* __restrict__ W0, int t,
          __half* __restrict__ s0out) {
    __shared__ float ins[2 * 360];
    __shared__ float ws[16 * 2 * 12];
    __shared__ float sacc[256 * 17];
    int tid = threadIdx.x;
    int b = blockIdx.z, cog = blockIdx.y;
    int tX = blockIdx.x & 3, tY = blockIdx.x >> 2;
    int x0 = tX * 16, y0 = tY * 16;
    const float* xb = x + ((size_t)(b * 16 + t)) * 2 * 4096;
    for (int i = tid; i < 2 * 324; i += 256) {
        int ci = i / 324; int r = i - ci * 324;
        int y = r / 18;   int xq = r - y * 18;
        int gy = y0 + y - 1, gx = x0 + xq - 1;
        float v = 0.f;
        if ((unsigned)gy < 64u && (unsigned)gx < 64u) {
            v = __ldg(xb + ci * 4096 + gy * 64 + gx);
            v = fminf(fmaxf(v, 0.f), 1.f);
        }
        ins[ci * 360 + y * 20 + xq] = v;
    }
    for (int i = tid; i < 16 * 18; i += 256) {
        int col = i / 18; int r = i - col * 18;
        int ci = r / 9;   int k = r - ci * 9;
        ws[(col * 2 + ci) * 12 + k] = __ldg(W0 + ((size_t)(cog * 16 + col) * 2 + ci) * 9 + k);
    }
    __syncthreads();
    int ty = tid >> 4, tx = tid & 15;
    float acc[16];
#pragma unroll
    for (int j = 0; j < 16; j++) acc[j] = 0.f;
#pragma unroll
    for (int ci = 0; ci < 2; ci++) {
        const float* ip = ins + ci * 360 + ty * 20 + tx;
        float iv[3][3];
#pragma unroll
        for (int yy = 0; yy < 3; yy++)
#pragma unroll
            for (int xx = 0; xx < 3; xx++) iv[yy][xx] = ip[yy * 20 + xx];
#pragma unroll
        for (int j = 0; j < 16; j++) {
            const float* wb = ws + (j * 2 + ci) * 12;
            float4 wA = *(const float4*)wb;
            float4 wB = *(const float4*)(wb + 4);
            float w8 = wb[8];
            float s = acc[j];
            s += iv[0][0] * wA.x; s += iv[0][1] * wA.y; s += iv[0][2] * wA.z;
            s += iv[1][0] * wA.w; s += iv[1][1] * wB.x; s += iv[1][2] * wB.y;
            s += iv[2][0] * wB.z; s += iv[2][1] * wB.w; s += iv[2][2] * w8;
            acc[j] = s;
        }
    }
#pragma unroll
    for (int c = 0; c < 16; c++) sacc[(ty * 16 + tx) * 17 + c] = acc[c];
    __syncthreads();
#pragma unroll
    for (int q = 0; q < 4; q++) {
        int f = q * 256 + tid;
        int yl = f >> 6, fi = f & 63;
        int xl = fi >> 2, cq = fi & 3;
        size_t rowb = (((size_t)(cog * 16 + b) * 4096) + (y0 + yl) * 64 + x0) * 16;
        float4 vmv = *(float4*)(g_vm0 + rowb + fi * 4);
        float4 vsv = *(float4*)(g_vs0 + rowb + fi * 4);
        const float* sp = sacc + (yl * 16 + xl) * 17 + cq * 4;
        float I0 = sp[0], I1 = sp[1], I2 = sp[2], I3 = sp[3];
        float k0 = ((vmv.x - vsv.x) > TH) ? 0.f : 1.f;
        float k1 = ((vmv.y - vsv.y) > TH) ? 0.f : 1.f;
        float k2 = ((vmv.z - vsv.z) > TH) ? 0.f : 1.f;
        float k3 = ((vmv.w - vsv.w) > TH) ? 0.f : 1.f;
        float a0 = DM * vmv.x * k0 + I0, a1 = DM * vmv.y * k1 + I1;
        float a2 = DM * vmv.z * k2 + I2, a3 = DM * vmv.w * k3 + I3;
        float c0 = DS * vsv.x * k0 + I0, c1 = DS * vsv.y * k1 + I1;
        float c2 = DS * vsv.z * k2 + I2, c3 = DS * vsv.w * k3 + I3;
        float s0 = ((a0 - c0) > TH) ? 1.f : 0.f;
        float s1 = ((a1 - c1) > TH) ? 1.f : 0.f;
        float s2 = ((a2 - c2) > TH) ? 1.f : 0.f;
        float s3 = ((a3 - c3) > TH) ? 1.f : 0.f;
        *(float4*)(g_vm0 + rowb + fi * 4) = make_float4(a0, a1, a2, a3);
        *(float4*)(g_vs0 + rowb + fi * 4) = make_float4(c0, c1, c2, c3);
        int gy = y0 + yl, gx = x0 + xl;
        size_t qi = ((size_t)b * 4356 + (gy + 1) * 66 + (gx + 1)) * 64 + cog * 16 + cq * 4;
        *(__half2*)(s0out + qi)     = __floats2half2_rn(s0, s1);
        *(__half2*)(s0out + qi + 2) = __floats2half2_rn(s2, s3);
    }
}

__device__ __forceinline__ void mma16816h(float* c, const unsigned* a, unsigned b0, unsigned b1) {
    asm volatile(
        "mma.sync.aligned.m16n8k16.row.col.f32.f16.f16.f32 "
        "{%0,%1,%2,%3}, {%4,%5,%6,%7}, {%8,%9}, {%0,%1,%2,%3};\n"
        : "+f"(c[0]), "+f"(c[1]), "+f"(c[2]), "+f"(c[3])
        : "r"(a[0]), "r"(a[1]), "r"(a[2]), "r"(a[3]), "r"(b0), "r"(b1));
}

__device__ __forceinline__ void ldsm4(unsigned& r0, unsigned& r1, unsigned& r2, unsigned& r3,
                                      uint32_t addr) {
    asm volatile("ldmatrix.sync.aligned.m8n8.x4.shared.b16 {%0,%1,%2,%3}, [%4];\n"
                 : "=r"(r0), "=r"(r1), "=r"(r2), "=r"(r3) : "r"(addr));
}

template<int HW, int CIN, int YROWS, int SHIFT, bool IS_CONV2>
__global__ void __launch_bounds__(256, 2)
conv_mma(const __half* __restrict__ Abuf, const uint4* __restrict__ Bpk,
         float* __restrict__ vm, float* __restrict__ vs,
         __half* __restrict__ poolb, __half* __restrict__ p2out)
{
    const int WB = HW + 2, QTOT = WB * WB, KC = CIN / 16;
    const int PITCHE = CIN + 8;
    const int SLABROWS = (YROWS + 2) * WB;
    const int CPR = CIN / 8;
    const int JT = 2;
    extern __shared__ __align__(16) unsigned char dsm[];
    __half* As = (__half*)dsm;

    int tid = threadIdx.x, lane = tid & 31, wid = tid >> 5;
    int warp_m = wid >> 2, warp_n = wid & 3;
    int b = blockIdx.z;
    int cogBase = blockIdx.y * 32 * JT;
    int y0 = blockIdx.x * YROWS;
    int q0 = y0 * WB;

    for (int i = tid; i < SLABROWS * CPR; i += 256) {
        int rrow = i / CPR, cw = i - rrow * CPR;
        uint4 v = __ldg((const uint4*)(Abuf + ((size_t)b * QTOT + q0 + rrow) * CIN) + cw);
        *(uint4*)(As + rrow * PITCHE + cw * 8) = v;
    }
    __syncthreads();

    int mtg[4];
#pragma unroll
    for (int l = 0; l < 4; l++)
        mtg[l] = (YROWS == 2) ? (warp_m * 2 + (l & 1) + ((l & 2) << 1)) : (warp_m * 4 + l);

    uint32_t sm32 = (uint32_t)__cvta_generic_to_shared(As);
    uint32_t abase[4];
#pragma unroll
    for (int l = 0; l < 4; l++) {
        int m = mtg[l] * 16 + (lane & 15);
        int pr = (m >> SHIFT) * WB + (m & (HW - 1));
        abase[l] = sm32 + (uint32_t)(pr * PITCHE * 2) + ((lane >> 4) & 1) * 16;
    }

    float acc[2][4][JT][4];
#pragma unroll
    for (int s = 0; s < 2; s++)
#pragma unroll
        for (int l = 0; l < 4; l++)
#pragma unroll
            for (int j = 0; j < JT; j++)
#pragma unroll
                for (int c = 0; c < 4; c++) acc[s][l][j][c] = 0.f;

    int ntp = cogBase / 16 + warp_n;
    const uint4* btl = Bpk + (size_t)ntp * 32 + lane;

#pragma unroll 1
    for (int tap = 0; tap < 9; tap++) {
        int ky = tap / 3, kx = tap - ky * 3;
        uint32_t ta[4];
#pragma unroll
        for (int l = 0; l < 4; l++) ta[l] = abase[l] + (uint32_t)((ky * WB + kx) * PITCHE * 2);
        const uint4* bt = btl + (size_t)tap * (2 * KC * 256);
#pragma unroll
        for (int kc = 0; kc < KC; kc++) {
            unsigned a[4][4];
#pragma unroll
            for (int l = 0; l < 4; l++)
                ldsm4(a[l][0], a[l][1], a[l][2], a[l][3], ta[l] + kc * 32);
#pragma unroll
            for (int s = 0; s < 2; s++) {
                uint4 bb = __ldg(bt + (s * KC + kc) * 256);
#pragma unroll
                for (int l = 0; l < 4; l++) {
                    mma16816h(acc[s][l][0], a[l], bb.x, bb.y);
                    mma16816h(acc[s][l][1], a[l], bb.z, bb.w);
                }
            }
        }
    }

#pragma unroll
    for (int lp = 0; lp < 2; lp++) {
#pragma unroll
        for (int o = 0; o < 2; o++) {
            int mA = mtg[lp] * 16 + (lane >> 2) + o * 8;
            int mB = mtg[lp + 2] * 16 + (lane >> 2) + o * 8;
            int yA = y0 + (mA >> SHIFT), xA = mA & (HW - 1);
            int yB = y0 + (mB >> SHIFT);
#pragma unroll
            for (int j = 0; j < JT; j++) {
                int co = cogBase + warp_n * 8 * JT + j * 8 + (lane & 3) * 2;
                size_t iA = ((size_t)(b * HW * HW) + yA * HW + xA) * 128 + co;
                size_t iB = ((size_t)(b * HW * HW) + yB * HW + xA) * 128 + co;
                float IA0 = acc[0][lp][j][o * 2 + 0]     + acc[1][lp][j][o * 2 + 0]     * INVSC;
                float IA1 = acc[0][lp][j][o * 2 + 1]     + acc[1][lp][j][o * 2 + 1]     * INVSC;
                float IB0 = acc[0][lp + 2][j][o * 2 + 0] + acc[1][lp + 2][j][o * 2 + 0] * INVSC;
                float IB1 = acc[0][lp + 2][j][o * 2 + 1] + acc[1][lp + 2][j][o * 2 + 1] * INVSC;
                float sA0, sA1, sB0, sB1;
                srm2_ns(IA0, IA1, vm, vs, iA, sA0, sA1);
                srm2_ns(IB0, IB1, vm, vs, iB, sB0, sB1);
                float xA0 = fmaxf(sA0, __shfl_xor_sync(0xffffffffu, sA0, 4));
                float xA1 = fmaxf(sA1, __shfl_xor_sync(0xffffffffu, sA1, 4));
                float xB0 = fmaxf(sB0, __shfl_xor_sync(0xffffffffu, sB0, 4));
                float xB1 = fmaxf(sB1, __shfl_xor_sync(0xffffffffu, sB1, 4));
                float p0 = fmaxf(xA0, xB0);
                float p1 = fmaxf(xA1, xB1);
                if ((lane & 4) == 0) {
                    int yp = yA >> 1, xp = xA >> 1;
                    if (IS_CONV2) {
                        p2out[(size_t)b * 32768 + co * 256 + yp * 16 + xp] = __float2half(p0);
                        p2out[(size_t)b * 32768 + (co + 1) * 256 + yp * 16 + xp] = __float2half(p1);
                    } else {
                        size_t qi = ((size_t)b * 1156 + (yp + 1) * 34 + (xp + 1)) * 128 + co;
                        *reinterpret_cast<__half2*>(poolb + qi) = __floats2half2_rn(p0, p1);
                    }
                }
            }
        }
    }
}

__global__ void __launch_bounds__(256)
fc3_partial(const float* __restrict__ W3, const __half* __restrict__ p2) {
    extern __shared__ __half p2s[];
    int ks = blockIdx.x, jg = blockIdx.y;
    int k0 = ks * 2048;
    int tid = threadIdx.x;
    for (int i = tid; i < 4096; i += 256) {
        int b = i >> 8, c = i & 255;
        ((uint4*)p2s)[i] = __ldg((const uint4*)(p2 + (size_t)b * 32768 + k0) + c);
    }
    __syncthreads();
    int wj = tid >> 5, lane = tid & 31;
    const uint2* ps = (const uint2*)p2s;
#pragma unroll 1
    for (int jj = 0; jj < 4; jj++) {
        int j = jg * 32 + wj * 4 + jj;
        const float4* wr = (const float4*)(W3 + (size_t)j * 32768 + k0);
        float acc[16];
#pragma unroll
        for (int b = 0; b < 16; b++) acc[b] = 0.f;
#pragma unroll 1
        for (int kk = lane; kk < 512; kk += 32) {
            float4 w4 = __ldg(wr + kk);
#pragma unroll
            for (int b = 0; b < 16; b++) {
                uint2 pv = ps[b * 512 + kk];
                float2 lo = __half22float2(*(const __half2*)&pv.x);
                float2 hi = __half22float2(*(const __half2*)&pv.y);
                acc[b] += w4.x * lo.x; acc[b] += w4.y * lo.y;
                acc[b] += w4.z * hi.x; acc[b] += w4.w * hi.y;
            }
        }
#pragma unroll
        for (int b = 0; b < 16; b++) {
            float v = acc[b];
            v += __shfl_down_sync(0xffffffffu, v, 16);
            v += __shfl_down_sync(0xffffffffu, v, 8);
            v += __shfl_down_sync(0xffffffffu, v, 4);
            v += __shfl_down_sync(0xffffffffu, v, 2);
            v += __shfl_down_sync(0xffffffffu, v, 1);
            if (lane == 0) g_part[(ks * 16 + b) * 512 + j] = v;
        }
    }
}

__global__ void __launch_bounds__(1024) fc34_srm(const float* __restrict__ W4) {
    __shared__ float s3s[8192];
    int tid = threadIdx.x;
#pragma unroll
    for (int e = 0; e < 8; e++) {
        int i = e * 1024 + tid;
        float I = 0.f;
#pragma unroll
        for (int ks = 0; ks < 16; ks++) I += g_part[ks * 8192 + i];
        s3s[i] = srm_ns(I, g_vm3, g_vs3, i);
    }
    __syncthreads();
    if (tid < 176) {
        int b = tid / 11, j = tid % 11;
        const float4* wr = (const float4*)(W4 + j * 512);
        const float4* sr = (const float4*)(s3s + b * 512);
        float acc = 0.f;
#pragma unroll 4
        for (int k = 0; k < 128; k++) {
            float4 w = __ldg(wr + k), s = sr[k];
            acc += w.x * s.x; acc += w.y * s.y; acc += w.z * s.z; acc += w.w * s.w;
        }
        float sn = srm_ns(acc, g_vm4, g_vs4, tid);
        g_out[tid] += sn;
    }
}

__global__ void finalize_k(float* __restrict__ out) {
    int i = threadIdx.x;
    if (i < 176) out[i] = g_out[i] * 0.0625f;
}

// ---------------------------------------------------------------------------
// Pipeline resources: created once at static init (before harness baseline).
struct PipeCtx {
    cudaStream_t sA, sC;
    cudaEvent_t evInit, evJoinA, evJoinC;
    cudaEvent_t evA[16], evB1[16], evB2[16], evC3[16];
    PipeCtx() {
        cudaStreamCreateWithFlags(&sA, cudaStreamNonBlocking);
        cudaStreamCreateWithFlags(&sC, cudaStreamNonBlocking);
        cudaEventCreateWithFlags(&evInit, cudaEventDisableTiming);
        cudaEventCreateWithFlags(&evJoinA, cudaEventDisableTiming);
        cudaEventCreateWithFlags(&evJoinC, cudaEventDisableTiming);
        for (int i = 0; i < 16; i++) {
            cudaEventCreateWithFlags(&evA[i], cudaEventDisableTiming);
            cudaEventCreateWithFlags(&evB1[i], cudaEventDisableTiming);
            cudaEventCreateWithFlags(&evB2[i], cudaEventDisableTiming);
            cudaEventCreateWithFlags(&evC3[i], cudaEventDisableTiming);
        }
    }
};
static PipeCtx g_pipe;

extern "C" void kernel_launch(void* const* d_in, const int* in_sizes, int n_in,
                              void* d_out, int out_size) {
    (void)in_sizes; (void)n_in; (void)out_size;
    const float* x  = (const float*)d_in[0];
    const float* W0 = (const float*)d_in[1];
    const float* W1 = (const float*)d_in[2];
    const float* W2 = (const float*)d_in[3];
    const float* W3 = (const float*)d_in[4];
    const float* W4 = (const float*)d_in[5];
    float* out = (float*)d_out;

    const int SMEM1 = 264 * 144;
    const int SMEM2 = 204 * 272;
    cudaFuncSetAttribute((const void*)conv_mma<64, 64, 2, 6, false>,
                         cudaFuncAttributeMaxDynamicSharedMemorySize, SMEM1);
    cudaFuncSetAttribute((const void*)conv_mma<32, 128, 4, 5, true>,
                         cudaFuncAttributeMaxDynamicSharedMemorySize, SMEM2);
    cudaFuncSetAttribute((const void*)fc3_partial,
                         cudaFuncAttributeMaxDynamicSharedMemorySize, 65536);

    __half *s0b, *p1b, *p2b;
    uint4 *w1pk, *w2pk;
    float *vm1, *vs1, *vm2, *vs2;
    cudaGetSymbolAddress((void**)&s0b, g_s0b);
    cudaGetSymbolAddress((void**)&p1b, g_p1b);
    cudaGetSymbolAddress((void**)&p2b, g_p2b);
    cudaGetSymbolAddress((void**)&w1pk, g_w1pk);
    cudaGetSymbolAddress((void**)&w2pk, g_w2pk);
    cudaGetSymbolAddress((void**)&vm1, g_vm1);
    cudaGetSymbolAddress((void**)&vs1, g_vs1);
    cudaGetSymbolAddress((void**)&vm2, g_vm2);
    cudaGetSymbolAddress((void**)&vs2, g_vs2);

    zero_all<<<2048, 256>>>();
    pack_w<<<(NW1PK4 + 255) / 256, 256>>>(W1, w1pk, 64, NW1PK4);
    pack_w<<<(NW2PK4 + 255) / 256, 256>>>(W2, w2pk, 128, NW2PK4);
    cudaEventRecord(g_pipe.evInit, 0);
    cudaStreamWaitEvent(g_pipe.sA, g_pipe.evInit, 0);

    for (int t = 0; t < 16; t++) {
        __half* s0t = s0b + (size_t)(t & 1) * SZ_S0B;
        __half* p2t = p2b + (size_t)(t & 1) * N_P2;

        // Stream A: conv0(t). Waits conv1(t-2) (s0b buffer reuse).
        if (t >= 2) cudaStreamWaitEvent(g_pipe.sA, g_pipe.evB1[t - 2], 0);
        conv0_srm<<<dim3(16, 4, 16), 256, 0, g_pipe.sA>>>(x, W0, t, s0t);
        cudaEventRecord(g_pipe.evA[t], g_pipe.sA);

        // Default stream B: conv1(t) (waits conv0(t)), conv2(t).
        cudaStreamWaitEvent(0, g_pipe.evA[t], 0);
        conv_mma<64, 64, 2, 6, false><<<dim3(32, 2, 16), 256, SMEM1>>>(
            s0t, w1pk, vm1, vs1, p1b, nullptr);
        cudaEventRecord(g_pipe.evB1[t], 0);
        if (t >= 2) cudaStreamWaitEvent(0, g_pipe.evC3[t - 2], 0);   // p2b reuse
        conv_mma<32, 128, 4, 5, true><<<dim3(8, 2, 16), 256, SMEM2>>>(
            p1b, w2pk, vm2, vs2, nullptr, p2t);
        cudaEventRecord(g_pipe.evB2[t], 0);

        // Stream C: fc3(t) (waits conv2(t)), fc34(t).
        cudaStreamWaitEvent(g_pipe.sC, g_pipe.evB2[t], 0);
        fc3_partial<<<dim3(16, 16), 256, 65536, g_pipe.sC>>>(W3, p2t);
        cudaEventRecord(g_pipe.evC3[t], g_pipe.sC);
        fc34_srm<<<1, 1024, 0, g_pipe.sC>>>(W4);
    }

    // Join all forked work back to the origin stream.
    cudaEventRecord(g_pipe.evJoinA, g_pipe.sA);
    cudaEventRecord(g_pipe.evJoinC, g_pipe.sC);
    cudaStreamWaitEvent(0, g_pipe.evJoinA, 0);
    cudaStreamWaitEvent(0, g_pipe.evJoinC, 0);
    finalize_k<<<1, 256>>>(out);
}